// round 2
// baseline (speedup 1.0000x reference)
#include <cuda_runtime.h>
#include <math.h>

// ---------------------------------------------------------------------------
// Problem constants
// ---------------------------------------------------------------------------
#define Bv   16
#define Dd   768
#define NLAY 12
#define NHh  12
#define DHh  64
#define DFFd 3072
#define Pn   10
#define Sn   5
#define LPn  5
#define NCn  100
#define NP   196
#define N1   197
#define N2   222          // 1 + S*LP + 196
#define LOG2PI_F 1.8378770664093454f

// ---------------------------------------------------------------------------
// Device scratch (static __device__ arrays; no runtime allocation)
// ---------------------------------------------------------------------------
__device__ float g_col [(size_t)Bv * NP * Dd];          // im2col
__device__ float g_img [(size_t)Bv * NP * Dd];          // patch embed out
__device__ float g_x0  [(size_t)Bv * N1 * Dd];          // initial tokens pass1
__device__ float g_x   [(size_t)Bv * N2 * Dd];          // residual stream
__device__ float g_h   [(size_t)Bv * N2 * Dd];          // LN output
__device__ float g_qkv [(size_t)Bv * N2 * 3 * Dd];
__device__ float g_att [(size_t)Bv * NHh * N2 * N2];
__device__ float g_o   [(size_t)Bv * N2 * Dd];
__device__ float g_mlp [(size_t)Bv * N2 * DFFd];
__device__ float g_q   [(size_t)Bv * Dd];
__device__ float g_L   [(size_t)Pn * Dd * Dd];
__device__ float g_LT  [(size_t)Pn * Dd * Dd];
__device__ float g_logdet[Pn];
__device__ float g_logp[Bv * Pn];
__device__ int   g_topk[Bv * Sn];
__device__ float g_pool[Bv * Dd];

// ---------------------------------------------------------------------------
// Helpers
// ---------------------------------------------------------------------------
__device__ __forceinline__ float warp_sum(float v) {
#pragma unroll
    for (int o = 16; o > 0; o >>= 1) v += __shfl_xor_sync(0xffffffffu, v, o);
    return v;
}
__device__ __forceinline__ float warp_max(float v) {
#pragma unroll
    for (int o = 16; o > 0; o >>= 1) v = fmaxf(v, __shfl_xor_sync(0xffffffffu, v, o));
    return v;
}
__device__ __forceinline__ float gelu_f(float x) {
    float x3 = x * x * x;
    return 0.5f * x * (1.f + tanhf(0.7978845608028654f * (x + 0.044715f * x3)));
}

// ---------------------------------------------------------------------------
// Generic batched tiled GEMM: C = act(alpha * A*op(B) + bias) + resid
//   64x64 tile, 256 threads, 4x4 per thread, K-tile 16.
//   Batch index z decomposes as zo = z/inner, zi = z%inner with separate
//   strides, so strided QKV heads batch cleanly.
// ---------------------------------------------------------------------------
template <int TRANSB>
__global__ void gemm_k(const float* __restrict__ A, const float* __restrict__ Bm,
                       const float* __restrict__ bias, const float* __restrict__ resid,
                       float* __restrict__ C,
                       int M, int N, int K, int lda, int ldb, int ldc,
                       int inner,
                       long long sAo, long long sAi, long long sBo, long long sBi,
                       long long sCo, long long sCi,
                       float alpha, int act, int lowerOnly) {
    if (lowerOnly && blockIdx.x > blockIdx.y) return;   // uniform early exit

    int z = blockIdx.z;
    int zo = z / inner, zi = z % inner;
    A += zo * sAo + zi * sAi;
    Bm += zo * sBo + zi * sBi;
    long long co = zo * sCo + zi * sCi;
    C += co;
    if (resid) resid += co;

    __shared__ float As[16][64];
    __shared__ float Bs[16][64];

    int tid = threadIdx.x;
    int tx = tid & 15, ty = tid >> 4;
    int m0 = blockIdx.y * 64, n0 = blockIdx.x * 64;

    float acc[4][4];
#pragma unroll
    for (int i = 0; i < 4; i++)
#pragma unroll
        for (int j = 0; j < 4; j++) acc[i][j] = 0.f;

    for (int k0 = 0; k0 < K; k0 += 16) {
#pragma unroll
        for (int i = 0; i < 4; i++) {
            int l = tid + i * 256;
            int mm = l >> 4, kk = l & 15;
            int gm = m0 + mm, gk = k0 + kk;
            As[kk][mm] = (gm < M && gk < K) ? A[(long long)gm * lda + gk] : 0.f;
        }
        if (TRANSB) {
#pragma unroll
            for (int i = 0; i < 4; i++) {
                int l = tid + i * 256;
                int nn = l >> 4, kk = l & 15;
                int gn = n0 + nn, gk = k0 + kk;
                Bs[kk][nn] = (gn < N && gk < K) ? Bm[(long long)gn * ldb + gk] : 0.f;
            }
        } else {
#pragma unroll
            for (int i = 0; i < 4; i++) {
                int l = tid + i * 256;
                int kk = l >> 6, nn = l & 63;
                int gk = k0 + kk, gn = n0 + nn;
                Bs[kk][nn] = (gk < K && gn < N) ? Bm[(long long)gk * ldb + gn] : 0.f;
            }
        }
        __syncthreads();
#pragma unroll
        for (int kk = 0; kk < 16; kk++) {
            float a[4], b[4];
#pragma unroll
            for (int i = 0; i < 4; i++) a[i] = As[kk][ty * 4 + i];
#pragma unroll
            for (int j = 0; j < 4; j++) b[j] = Bs[kk][tx * 4 + j];
#pragma unroll
            for (int i = 0; i < 4; i++)
#pragma unroll
                for (int j = 0; j < 4; j++) acc[i][j] += a[i] * b[j];
        }
        __syncthreads();
    }

#pragma unroll
    for (int i = 0; i < 4; i++) {
        int gm = m0 + ty * 4 + i;
        if (gm >= M) continue;
#pragma unroll
        for (int j = 0; j < 4; j++) {
            int gn = n0 + tx * 4 + j;
            if (gn >= N) continue;
            float v = alpha * acc[i][j];
            if (bias) v += bias[gn];
            if (act == 1) v = gelu_f(v);
            if (resid) v += resid[(long long)gm * ldc + gn];
            C[(long long)gm * ldc + gn] = v;
        }
    }
}

// ---------------------------------------------------------------------------
// LayerNorm (one 256-thread block per 768-wide row)
// ---------------------------------------------------------------------------
__global__ void ln_k(const float* __restrict__ x, const float* __restrict__ g,
                     const float* __restrict__ b, float* __restrict__ out, int rows) {
    int row = blockIdx.x;
    if (row >= rows) return;
    const float* xr = x + (size_t)row * Dd;
    float* yr = out + (size_t)row * Dd;
    int tid = threadIdx.x;
    float v0 = xr[tid], v1 = xr[tid + 256], v2 = xr[tid + 512];
    __shared__ float red[8];
    __shared__ float stat[2];
    float s = warp_sum(v0 + v1 + v2);
    if ((tid & 31) == 0) red[tid >> 5] = s;
    __syncthreads();
    if (tid == 0) {
        float t = 0.f;
#pragma unroll
        for (int i = 0; i < 8; i++) t += red[i];
        stat[0] = t * (1.f / Dd);
    }
    __syncthreads();
    float m = stat[0];
    float d0 = v0 - m, d1 = v1 - m, d2 = v2 - m;
    s = warp_sum(d0 * d0 + d1 * d1 + d2 * d2);
    if ((tid & 31) == 0) red[tid >> 5] = s;
    __syncthreads();
    if (tid == 0) {
        float t = 0.f;
#pragma unroll
        for (int i = 0; i < 8; i++) t += red[i];
        stat[1] = rsqrtf(t * (1.f / Dd) + 1e-6f);
    }
    __syncthreads();
    float inv = stat[1];
    yr[tid]       = d0 * inv * g[tid]       + b[tid];
    yr[tid + 256] = d1 * inv * g[tid + 256] + b[tid + 256];
    yr[tid + 512] = d2 * inv * g[tid + 512] + b[tid + 512];
}

// ---------------------------------------------------------------------------
// Softmax over rows (warp per row)
// ---------------------------------------------------------------------------
__global__ void softmax_k(float* __restrict__ att, int n, int rows) {
    int row = blockIdx.x * (blockDim.x >> 5) + (threadIdx.x >> 5);
    if (row >= rows) return;
    int lane = threadIdx.x & 31;
    float* r = att + (long long)row * n;
    float m = -3e38f;
    for (int i = lane; i < n; i += 32) m = fmaxf(m, r[i]);
    m = warp_max(m);
    float s = 0.f;
    for (int i = lane; i < n; i += 32) {
        float e = expf(r[i] - m);
        r[i] = e;
        s += e;
    }
    s = warp_sum(s);
    float inv = 1.f / s;
    for (int i = lane; i < n; i += 32) r[i] *= inv;
}

// ---------------------------------------------------------------------------
// Patch embed im2col + token assembly
// ---------------------------------------------------------------------------
__global__ void im2col_k(const float* __restrict__ in, float* __restrict__ col) {
    long long idx = (long long)blockIdx.x * 256 + threadIdx.x;
    if (idx >= (long long)Bv * NP * Dd) return;
    int k = (int)(idx % Dd);
    long long bp = idx / Dd;
    int b = (int)(bp / NP), p = (int)(bp % NP);
    int c = k >> 8, rr = k & 255, i = rr >> 4, j = rr & 15;
    int py = p / 14, px = p % 14;
    col[idx] = in[((long long)(b * 3 + c) * 224 + py * 16 + i) * 224 + px * 16 + j];
}

__global__ void build_x0_k(const float* __restrict__ img, const float* __restrict__ cls,
                           const float* __restrict__ pos, float* __restrict__ x0,
                           float* __restrict__ x) {
    long long idx = (long long)blockIdx.x * 256 + threadIdx.x;
    if (idx >= (long long)Bv * N1 * Dd) return;
    int d = (int)(idx % Dd);
    long long bn = idx / Dd;
    int n = (int)(bn % N1), b = (int)(bn / N1);
    float t = (n == 0) ? cls[d] : img[((long long)b * NP + (n - 1)) * Dd + d];
    float v = t + pos[n * Dd + d];
    x0[idx] = v;
    x[idx] = v;
}

__global__ void extract_q_k(const float* __restrict__ h, float* __restrict__ q) {
    int idx = blockIdx.x * 256 + threadIdx.x;
    if (idx >= Bv * Dd) return;
    int b = idx / Dd, d = idx % Dd;
    q[idx] = h[(long long)b * N1 * Dd + d];
}

__global__ void build_x2_k(const float* __restrict__ x0, const float* __restrict__ prompt,
                           const float* __restrict__ pos, const float* __restrict__ img,
                           const int* __restrict__ topk, float* __restrict__ x) {
    long long idx = (long long)blockIdx.x * 256 + threadIdx.x;
    if (idx >= (long long)Bv * N2 * Dd) return;
    int d = (int)(idx % Dd);
    long long bn = idx / Dd;
    int n = (int)(bn % N2), b = (int)(bn / N2);
    float v;
    if (n == 0) {
        v = x0[(long long)b * N1 * Dd + d];
    } else if (n < 1 + Sn * LPn) {
        int t = n - 1;
        int s = t / LPn, l = t % LPn;
        int pi = topk[b * Sn + s];
        v = prompt[((long long)pi * LPn + l) * Dd + d] + pos[d];
    } else {
        v = img[((long long)b * NP + (n - (1 + Sn * LPn))) * Dd + d];
    }
    x[idx] = v;
}

__global__ void pool_k(const float* __restrict__ h, float* __restrict__ pool) {
    int idx = blockIdx.x * 256 + threadIdx.x;
    if (idx >= Bv * Dd) return;
    int b = idx / Dd, d = idx % Dd;
    float s = 0.f;
#pragma unroll
    for (int t = 1; t <= Sn * LPn; t++) s += h[((long long)b * N2 + t) * Dd + d];
    pool[idx] = s * (1.f / (Sn * LPn));
}

// ---------------------------------------------------------------------------
// Cholesky (blocked NB=64, host-unrolled): prep, diag potrf, panel trsm;
// trailing SYRK uses gemm_k<1> with alpha=-1 and resid=C, lower tiles only.
// ---------------------------------------------------------------------------
__global__ void chol_prep_k(const float* __restrict__ var, float* __restrict__ L,
                            float* __restrict__ logdet) {
    long long idx = (long long)blockIdx.x * 256 + threadIdx.x;
    if (idx >= (long long)Pn * Dd * Dd) return;
    int j = (int)(idx % Dd);
    long long pi = idx / Dd;
    int i = (int)(pi % Dd);
    int p = (int)(pi / Dd);
    L[idx] = fabsf(var[idx]) + (i == j ? 1.f : 0.f);
    if (i == 0 && j == 0) logdet[p] = 0.f;
}

__global__ void potrf_k(float* __restrict__ L, float* __restrict__ logdet, int kb) {
    int p = blockIdx.x;
    float* A = L + (long long)p * Dd * Dd + (long long)kb * 64 * Dd + kb * 64;
    __shared__ float s[64][65];
    int tid = threadIdx.x;
    for (int l = tid; l < 4096; l += 256) s[l >> 6][l & 63] = A[(l >> 6) * Dd + (l & 63)];
    __syncthreads();
    for (int k = 0; k < 64; k++) {
        if (tid == 0) s[k][k] = sqrtf(s[k][k]);
        __syncthreads();
        for (int i = k + 1 + tid; i < 64; i += 256) s[i][k] /= s[k][k];
        __syncthreads();
        for (int l = tid; l < 4096; l += 256) {
            int i = l >> 6, j = l & 63;
            if (i > k && j > k && j <= i) s[i][j] -= s[i][k] * s[j][k];
        }
        __syncthreads();
    }
    for (int l = tid; l < 4096; l += 256) A[(l >> 6) * Dd + (l & 63)] = s[l >> 6][l & 63];
    if (tid < 64) atomicAdd(&logdet[p], 2.f * logf(s[tid][tid]));
}

__global__ void trsm_k(float* __restrict__ L, int kb) {
    int p = blockIdx.x;
    int off = (kb + 1) * 64;
    __shared__ float s[64][65];
    int tid = threadIdx.x;
    float* Ldiag = L + (long long)p * Dd * Dd + (long long)kb * 64 * Dd + kb * 64;
    for (int l = tid; l < 4096; l += 256) s[l >> 6][l & 63] = Ldiag[(l >> 6) * Dd + (l & 63)];
    __syncthreads();
    int wid = tid >> 5, lane = tid & 31;
    int row = off + blockIdx.y * 8 + wid;
    if (row >= Dd) return;
    float* a = L + (long long)p * Dd * Dd + (long long)row * Dd + kb * 64;
    float a0 = a[lane], a1 = a[lane + 32];
#pragma unroll
    for (int j = 0; j < 64; j++) {
        float aj = (j < 32) ? __shfl_sync(0xffffffffu, a0, j)
                            : __shfl_sync(0xffffffffu, a1, j - 32);
        float y = aj / s[j][j];
        if (lane == (j & 31)) {
            if (j < 32) a0 = y; else a1 = y;
        }
        if (lane > j) a0 -= s[lane][j] * y;
        if (lane + 32 > j) a1 -= s[lane + 32][j] * y;
    }
    a[lane] = a0;
    a[lane + 32] = a1;
}

__global__ void transpose_k(const float* __restrict__ L, float* __restrict__ LT) {
    __shared__ float t[32][33];
    int p = blockIdx.z;
    int i0 = blockIdx.y * 32, j0 = blockIdx.x * 32;
    int x = threadIdx.x, y = threadIdx.y;    // 32 x 8
#pragma unroll
    for (int r = 0; r < 32; r += 8)
        t[y + r][x] = L[(long long)p * Dd * Dd + (long long)(i0 + y + r) * Dd + j0 + x];
    __syncthreads();
#pragma unroll
    for (int r = 0; r < 32; r += 8)
        LT[(long long)p * Dd * Dd + (long long)(j0 + y + r) * Dd + i0 + x] = t[x][y + r];
}

// warp per (b,p): forward substitution with residual in smem, coalesced LT rows
__global__ void solve_k(const float* __restrict__ LT, const float* __restrict__ q,
                        const float* __restrict__ mean, const float* __restrict__ logdet,
                        float* __restrict__ logp) {
    int p = blockIdx.x;
    int wid = threadIdx.x >> 5, lane = threadIdx.x & 31;
    int b = blockIdx.y * 8 + wid;
    __shared__ float rs[8][Dd];
    float* r = rs[wid];
    for (int i = lane; i < Dd; i += 32) r[i] = q[b * Dd + i] - mean[p * Dd + i];
    const float* lt = LT + (long long)p * Dd * Dd;
    float quad = 0.f;
    for (int j = 0; j < Dd; j++) {
        __syncwarp();
        float y = r[j] / lt[(long long)j * Dd + j];
        if (lane == 0) quad += y * y;
        for (int i = j + 1 + lane; i < Dd; i += 32) r[i] -= lt[(long long)j * Dd + i] * y;
    }
    if (lane == 0)
        logp[b * Pn + p] = -0.5f * ((float)Dd * LOG2PI_F + logdet[p] + quad);
}

__global__ void topk_k(const float* __restrict__ logp, int* __restrict__ topk) {
    int b = threadIdx.x;
    if (b >= Bv) return;
    float v[Pn];
#pragma unroll
    for (int p = 0; p < Pn; p++) v[p] = logp[b * Pn + p];
#pragma unroll
    for (int s = 0; s < Sn; s++) {
        float best = -3e38f;
        int bi = 0;
#pragma unroll
        for (int p = 0; p < Pn; p++) {
            if (v[p] > best) { best = v[p]; bi = p; }
        }
        topk[b * Sn + s] = bi;
        v[bi] = -3e38f;
    }
}

// ---------------------------------------------------------------------------
// Host side
// ---------------------------------------------------------------------------
static void* getsym(const void* symbol) {
    void* p = nullptr;
    cudaGetSymbolAddress(&p, symbol);
    return p;
}

static void gemm(bool transB, const float* A, const float* Bm, const float* bias,
                 const float* resid, float* C, int M, int N, int K,
                 int lda, int ldb, int ldc, int batch, int inner,
                 long long sAo, long long sAi, long long sBo, long long sBi,
                 long long sCo, long long sCi, float alpha, int act, int lowerOnly) {
    dim3 grid((N + 63) / 64, (M + 63) / 64, batch);
    if (transB)
        gemm_k<1><<<grid, 256>>>(A, Bm, bias, resid, C, M, N, K, lda, ldb, ldc, inner,
                                 sAo, sAi, sBo, sBi, sCo, sCi, alpha, act, lowerOnly);
    else
        gemm_k<0><<<grid, 256>>>(A, Bm, bias, resid, C, M, N, K, lda, ldb, ldc, inner,
                                 sAo, sAi, sBo, sBi, sCo, sCi, alpha, act, lowerOnly);
}

struct Weights {
    const float *ln1_g, *ln1_b, *qkv_w, *qkv_b, *proj_w, *proj_b;
    const float *ln2_g, *ln2_b, *fc1_w, *fc1_b, *fc2_w, *fc2_b;
};

static void run_blocks(float* x, int N, const Weights& w,
                       float* h, float* qkv, float* att, float* o, float* mlp) {
    int M = Bv * N;
    int rows = Bv * NHh * N;
    for (int l = 0; l < NLAY; l++) {
        // LN1
        ln_k<<<M, 256>>>(x, w.ln1_g + l * Dd, w.ln1_b + l * Dd, h, M);
        // QKV: [M,768] x [768,2304] + bias
        gemm(false, h, w.qkv_w + (long long)l * Dd * 3 * Dd, w.qkv_b + l * 3 * Dd,
             nullptr, qkv, M, 3 * Dd, Dd, Dd, 3 * Dd, 3 * Dd,
             1, 1, 0, 0, 0, 0, 0, 0, 1.f, 0, 0);
        // att = Q K^T / 8 : batched over (b,h)
        gemm(true, qkv, qkv + Dd, nullptr, nullptr, att,
             N, N, DHh, 3 * Dd, 3 * Dd, N, Bv * NHh, NHh,
             (long long)N * 3 * Dd, DHh, (long long)N * 3 * Dd, DHh,
             (long long)NHh * N * N, (long long)N * N, 0.125f, 0, 0);
        softmax_k<<<(rows + 3) / 4, 128>>>(att, N, rows);
        // o = att V
        gemm(false, att, qkv + 2 * Dd, nullptr, nullptr, o,
             N, DHh, N, N, 3 * Dd, Dd, Bv * NHh, NHh,
             (long long)NHh * N * N, (long long)N * N, (long long)N * 3 * Dd, DHh,
             (long long)N * Dd, DHh, 1.f, 0, 0);
        // x = x + o @ proj_w + proj_b
        gemm(false, o, w.proj_w + (long long)l * Dd * Dd, w.proj_b + l * Dd,
             x, x, M, Dd, Dd, Dd, Dd, Dd, 1, 1, 0, 0, 0, 0, 0, 0, 1.f, 0, 0);
        // LN2
        ln_k<<<M, 256>>>(x, w.ln2_g + l * Dd, w.ln2_b + l * Dd, h, M);
        // mlp = gelu(h @ fc1 + b1)
        gemm(false, h, w.fc1_w + (long long)l * Dd * DFFd, w.fc1_b + l * DFFd,
             nullptr, mlp, M, DFFd, Dd, Dd, DFFd, DFFd,
             1, 1, 0, 0, 0, 0, 0, 0, 1.f, 1, 0);
        // x = x + mlp @ fc2 + b2
        gemm(false, mlp, w.fc2_w + (long long)l * DFFd * Dd, w.fc2_b + l * Dd,
             x, x, M, Dd, DFFd, DFFd, Dd, Dd, 1, 1, 0, 0, 0, 0, 0, 0, 1.f, 0, 0);
    }
}

extern "C" void kernel_launch(void* const* d_in, const int* in_sizes, int n_in,
                              void* d_out, int out_size) {
    (void)in_sizes; (void)n_in; (void)out_size;
    const float* inputs   = (const float*)d_in[0];
    const float* patch_w  = (const float*)d_in[1];
    const float* patch_b  = (const float*)d_in[2];
    const float* cls_tok  = (const float*)d_in[3];
    const float* pos_emb  = (const float*)d_in[4];
    Weights w;
    w.ln1_g  = (const float*)d_in[5];
    w.ln1_b  = (const float*)d_in[6];
    w.qkv_w  = (const float*)d_in[7];
    w.qkv_b  = (const float*)d_in[8];
    w.proj_w = (const float*)d_in[9];
    w.proj_b = (const float*)d_in[10];
    w.ln2_g  = (const float*)d_in[11];
    w.ln2_b  = (const float*)d_in[12];
    w.fc1_w  = (const float*)d_in[13];
    w.fc1_b  = (const float*)d_in[14];
    w.fc2_w  = (const float*)d_in[15];
    w.fc2_b  = (const float*)d_in[16];
    const float* norm_g   = (const float*)d_in[17];
    const float* norm_b   = (const float*)d_in[18];
    const float* head_w   = (const float*)d_in[19];
    const float* head_b   = (const float*)d_in[20];
    const float* prompt   = (const float*)d_in[21];
    const float* mean     = (const float*)d_in[22];
    const float* variance = (const float*)d_in[23];
    float* out = (float*)d_out;

    float* col  = (float*)getsym(g_col);
    float* img  = (float*)getsym(g_img);
    float* x0   = (float*)getsym(g_x0);
    float* x    = (float*)getsym(g_x);
    float* h    = (float*)getsym(g_h);
    float* qkv  = (float*)getsym(g_qkv);
    float* att  = (float*)getsym(g_att);
    float* o    = (float*)getsym(g_o);
    float* mlp  = (float*)getsym(g_mlp);
    float* qv   = (float*)getsym(g_q);
    float* L    = (float*)getsym(g_L);
    float* LT   = (float*)getsym(g_LT);
    float* logd = (float*)getsym(g_logdet);
    float* logp = (float*)getsym(g_logp);
    int*   topk = (int*)getsym(g_topk);
    float* pool = (float*)getsym(g_pool);

    // ---- patch embed ----
    {
        long long tot = (long long)Bv * NP * Dd;
        im2col_k<<<(unsigned)((tot + 255) / 256), 256>>>(inputs, col);
        // img = col @ patch_w^T + patch_b   (patch_w is [768,768] row-major)
        gemm(true, col, patch_w, patch_b, nullptr, img,
             Bv * NP, Dd, Dd, Dd, Dd, Dd, 1, 1, 0, 0, 0, 0, 0, 0, 1.f, 0, 0);
        long long tot0 = (long long)Bv * N1 * Dd;
        build_x0_k<<<(unsigned)((tot0 + 255) / 256), 256>>>(img, cls_tok, pos_emb, x0, x);
    }

    // ---- Cholesky of cov = |variance| + I  (blocked NB=64) ----
    {
        long long tot = (long long)Pn * Dd * Dd;
        chol_prep_k<<<(unsigned)((tot + 255) / 256), 256>>>(variance, L, logd);
        for (int kb = 0; kb < Dd / 64; kb++) {
            potrf_k<<<Pn, 256>>>(L, logd, kb);
            int T = Dd - (kb + 1) * 64;
            if (T > 0) {
                trsm_k<<<dim3(Pn, (T + 7) / 8), 256>>>(L, kb);
                long long off = (long long)(kb + 1) * 64;
                const float* pan = L + off * Dd + kb * 64;
                float* trail = L + off * Dd + off;
                gemm(true, pan, pan, nullptr, trail, trail,
                     T, T, 64, Dd, Dd, Dd, Pn, 1,
                     (long long)Dd * Dd, 0, (long long)Dd * Dd, 0,
                     (long long)Dd * Dd, 0, -1.f, 0, 1);
            }
        }
        transpose_k<<<dim3(Dd / 32, Dd / 32, Pn), dim3(32, 8)>>>(L, LT);
    }

    // ---- pass 1 (query) ----
    run_blocks(x, N1, w, h, qkv, att, o, mlp);
    ln_k<<<Bv * N1, 256>>>(x, norm_g, norm_b, h, Bv * N1);
    extract_q_k<<<(Bv * Dd + 255) / 256, 256>>>(h, qv);

    // ---- MVN logprob + top-k ----
    solve_k<<<dim3(Pn, Bv / 8), 256>>>(LT, qv, mean, logd, logp);
    topk_k<<<1, 16>>>(logp, topk);

    // ---- pass 2 (prompted) ----
    {
        long long tot = (long long)Bv * N2 * Dd;
        build_x2_k<<<(unsigned)((tot + 255) / 256), 256>>>(x0, prompt, pos_emb, img, topk, x);
    }
    run_blocks(x, N2, w, h, qkv, att, o, mlp);
    ln_k<<<Bv * N2, 256>>>(x, norm_g, norm_b, h, Bv * N2);
    pool_k<<<(Bv * Dd + 255) / 256, 256>>>(h, pool);

    // ---- head ----
    gemm(false, pool, head_w, head_b, nullptr, out,
         Bv, NCn, Dd, Dd, NCn, NCn, 1, 1, 0, 0, 0, 0, 0, 0, 1.f, 0, 0);
}

// round 3
// speedup vs baseline: 1.4336x; 1.4336x over previous
#include <cuda_runtime.h>
#include <math.h>

// ---------------------------------------------------------------------------
// Problem constants
// ---------------------------------------------------------------------------
#define Bv   16
#define Dd   768
#define NLAY 12
#define NHh  12
#define DHh  64
#define DFFd 3072
#define Pn   10
#define Sn   5
#define LPn  5
#define NCn  100
#define NP   196
#define N1   197
#define N2   222          // 1 + S*LP + 196
#define LOG2PI_F 1.8378770664093454f

// ---------------------------------------------------------------------------
// Device scratch (static __device__ arrays; no runtime allocation)
// ---------------------------------------------------------------------------
__device__ float g_col [(size_t)Bv * NP * Dd];          // im2col
__device__ float g_img [(size_t)Bv * NP * Dd];          // patch embed out
__device__ float g_x0  [(size_t)Bv * N1 * Dd];          // initial tokens pass1
__device__ float g_x   [(size_t)Bv * N2 * Dd];          // residual stream
__device__ float g_h   [(size_t)Bv * N2 * Dd];          // LN output
__device__ float g_qkv [(size_t)Bv * N2 * 3 * Dd];
__device__ float g_att [(size_t)Bv * NHh * N2 * N2];
__device__ float g_o   [(size_t)Bv * N2 * Dd];
__device__ float g_mlp [(size_t)Bv * N2 * DFFd];
__device__ float g_q   [(size_t)Bv * Dd];
__device__ float g_L   [(size_t)Pn * Dd * Dd];
__device__ float g_LT  [(size_t)Pn * Dd * Dd];
__device__ float g_logdet[Pn];
__device__ float g_logp[Bv * Pn];
__device__ int   g_topk[Bv * Sn];
__device__ float g_pool[Bv * Dd];

// ---------------------------------------------------------------------------
// Helpers
// ---------------------------------------------------------------------------
__device__ __forceinline__ float warp_sum(float v) {
#pragma unroll
    for (int o = 16; o > 0; o >>= 1) v += __shfl_xor_sync(0xffffffffu, v, o);
    return v;
}
__device__ __forceinline__ float warp_max(float v) {
#pragma unroll
    for (int o = 16; o > 0; o >>= 1) v = fmaxf(v, __shfl_xor_sync(0xffffffffu, v, o));
    return v;
}
__device__ __forceinline__ float gelu_f(float x) {
    float x3 = x * x * x;
    return 0.5f * x * (1.f + tanhf(0.7978845608028654f * (x + 0.044715f * x3)));
}
__device__ __forceinline__ float to_tf32(float x) {
    float r;
    asm("cvt.rna.tf32.f32 %0, %1;" : "=f"(r) : "f"(x));
    return r;
}
__device__ __forceinline__ void mma8(float c[4], const unsigned a[4], const unsigned b[2]) {
    asm volatile(
        "mma.sync.aligned.m16n8k8.row.col.f32.tf32.tf32.f32 "
        "{%0,%1,%2,%3}, {%4,%5,%6,%7}, {%8,%9}, {%0,%1,%2,%3};\n"
        : "+f"(c[0]), "+f"(c[1]), "+f"(c[2]), "+f"(c[3])
        : "r"(a[0]), "r"(a[1]), "r"(a[2]), "r"(a[3]), "r"(b[0]), "r"(b[1]));
}

// ---------------------------------------------------------------------------
// Tensor-core (tf32 mma.sync) batched GEMM: C = act(alpha*A*op(B)+bias)+resid
//   CTA tile 64x64, BK=32, 128 threads (4 warps, warp tile 32x32).
//   Smem layouts chosen conflict-free for both STS and fragment LDS:
//     A:  [m][k] stride 36   (bank = 4*gid + ctg on frag loads)
//     B^T:[n][k] stride 36
//     B:  [k][n] stride 72   (bank = 8*ctg + gid on frag loads)
// ---------------------------------------------------------------------------
template <int TRANSB>
__global__ void gemmT_k(const float* __restrict__ A, const float* __restrict__ Bm,
                        const float* __restrict__ bias, const float* __restrict__ resid,
                        float* __restrict__ C,
                        int M, int N, int K, int lda, int ldb, int ldc,
                        int inner,
                        long long sAo, long long sAi, long long sBo, long long sBi,
                        long long sCo, long long sCi,
                        float alpha, int act, int lowerOnly) {
    if (lowerOnly && blockIdx.x > blockIdx.y) return;   // uniform early exit

    int z = blockIdx.z;
    int zo = z / inner, zi = z % inner;
    A  += zo * sAo + zi * sAi;
    Bm += zo * sBo + zi * sBi;
    long long co = zo * sCo + zi * sCi;
    C += co;
    if (resid) resid += co;

    __shared__ float As[64 * 36];
    __shared__ float Bs[2304];   // 32*72 (no-trans) or 64*36 (trans)

    int tid = threadIdx.x;
    int m0 = blockIdx.y * 64, n0 = blockIdx.x * 64;
    int warp = tid >> 5, lane = tid & 31;
    int gid = lane >> 2, ctg = lane & 3;
    int wm = (warp >> 1) * 32, wn = (warp & 1) * 32;

    float acc[2][4][4];
#pragma unroll
    for (int mi = 0; mi < 2; mi++)
#pragma unroll
        for (int ni = 0; ni < 4; ni++)
#pragma unroll
            for (int e = 0; e < 4; e++) acc[mi][ni][e] = 0.f;

    for (int k0 = 0; k0 < K; k0 += 32) {
        // A tile: [m][k], stride 36
#pragma unroll
        for (int i = 0; i < 16; i++) {
            int l = tid + i * 128;
            int mm = l >> 5, kk = l & 31;
            int gm = m0 + mm, gk = k0 + kk;
            As[mm * 36 + kk] = (gm < M && gk < K) ? to_tf32(A[(long long)gm * lda + gk]) : 0.f;
        }
        if (TRANSB) {   // B row-major [n][k] -> Bs[n][k] stride 36
#pragma unroll
            for (int i = 0; i < 16; i++) {
                int l = tid + i * 128;
                int nn = l >> 5, kk = l & 31;
                int gn = n0 + nn, gk = k0 + kk;
                Bs[nn * 36 + kk] = (gn < N && gk < K) ? to_tf32(Bm[(long long)gn * ldb + gk]) : 0.f;
            }
        } else {        // B row-major [k][n] -> Bs[k][n] stride 72
#pragma unroll
            for (int i = 0; i < 16; i++) {
                int l = tid + i * 128;
                int kk = l >> 6, nn = l & 63;
                int gk = k0 + kk, gn = n0 + nn;
                Bs[kk * 72 + nn] = (gk < K && gn < N) ? to_tf32(Bm[(long long)gk * ldb + gn]) : 0.f;
            }
        }
        __syncthreads();
#pragma unroll
        for (int ks = 0; ks < 4; ks++) {
            int kr0 = ks * 8 + ctg, kr1 = kr0 + 4;
            unsigned a[2][4], b[4][2];
#pragma unroll
            for (int mi = 0; mi < 2; mi++) {
                int mb = wm + mi * 16 + gid;
                a[mi][0] = __float_as_uint(As[mb * 36 + kr0]);
                a[mi][1] = __float_as_uint(As[(mb + 8) * 36 + kr0]);
                a[mi][2] = __float_as_uint(As[mb * 36 + kr1]);
                a[mi][3] = __float_as_uint(As[(mb + 8) * 36 + kr1]);
            }
#pragma unroll
            for (int ni = 0; ni < 4; ni++) {
                int nb = wn + ni * 8 + gid;
                if (TRANSB) {
                    b[ni][0] = __float_as_uint(Bs[nb * 36 + kr0]);
                    b[ni][1] = __float_as_uint(Bs[nb * 36 + kr1]);
                } else {
                    b[ni][0] = __float_as_uint(Bs[kr0 * 72 + nb]);
                    b[ni][1] = __float_as_uint(Bs[kr1 * 72 + nb]);
                }
            }
#pragma unroll
            for (int mi = 0; mi < 2; mi++)
#pragma unroll
                for (int ni = 0; ni < 4; ni++)
                    mma8(acc[mi][ni], a[mi], b[ni]);
        }
        __syncthreads();
    }

#pragma unroll
    for (int mi = 0; mi < 2; mi++) {
#pragma unroll
        for (int ni = 0; ni < 4; ni++) {
            int col = n0 + wn + ni * 8 + ctg * 2;
#pragma unroll
            for (int e = 0; e < 4; e++) {
                int r = m0 + wm + mi * 16 + gid + ((e >> 1) << 3);
                int cc = col + (e & 1);
                if (r < M && cc < N) {
                    float v = alpha * acc[mi][ni][e];
                    if (bias) v += bias[cc];
                    if (act == 1) v = gelu_f(v);
                    if (resid) v += resid[(long long)r * ldc + cc];
                    C[(long long)r * ldc + cc] = v;
                }
            }
        }
    }
}

// ---------------------------------------------------------------------------
// LayerNorm (one 256-thread block per 768-wide row)
// ---------------------------------------------------------------------------
__global__ void ln_k(const float* __restrict__ x, const float* __restrict__ g,
                     const float* __restrict__ b, float* __restrict__ out, int rows) {
    int row = blockIdx.x;
    if (row >= rows) return;
    const float* xr = x + (size_t)row * Dd;
    float* yr = out + (size_t)row * Dd;
    int tid = threadIdx.x;
    float v0 = xr[tid], v1 = xr[tid + 256], v2 = xr[tid + 512];
    __shared__ float red[8];
    __shared__ float stat[2];
    float s = warp_sum(v0 + v1 + v2);
    if ((tid & 31) == 0) red[tid >> 5] = s;
    __syncthreads();
    if (tid == 0) {
        float t = 0.f;
#pragma unroll
        for (int i = 0; i < 8; i++) t += red[i];
        stat[0] = t * (1.f / Dd);
    }
    __syncthreads();
    float m = stat[0];
    float d0 = v0 - m, d1 = v1 - m, d2 = v2 - m;
    s = warp_sum(d0 * d0 + d1 * d1 + d2 * d2);
    if ((tid & 31) == 0) red[tid >> 5] = s;
    __syncthreads();
    if (tid == 0) {
        float t = 0.f;
#pragma unroll
        for (int i = 0; i < 8; i++) t += red[i];
        stat[1] = rsqrtf(t * (1.f / Dd) + 1e-6f);
    }
    __syncthreads();
    float inv = stat[1];
    yr[tid]       = d0 * inv * g[tid]       + b[tid];
    yr[tid + 256] = d1 * inv * g[tid + 256] + b[tid + 256];
    yr[tid + 512] = d2 * inv * g[tid + 512] + b[tid + 512];
}

// ---------------------------------------------------------------------------
// Softmax over rows (warp per row)
// ---------------------------------------------------------------------------
__global__ void softmax_k(float* __restrict__ att, int n, int rows) {
    int row = blockIdx.x * (blockDim.x >> 5) + (threadIdx.x >> 5);
    if (row >= rows) return;
    int lane = threadIdx.x & 31;
    float* r = att + (long long)row * n;
    float m = -3e38f;
    for (int i = lane; i < n; i += 32) m = fmaxf(m, r[i]);
    m = warp_max(m);
    float s = 0.f;
    for (int i = lane; i < n; i += 32) {
        float e = expf(r[i] - m);
        r[i] = e;
        s += e;
    }
    s = warp_sum(s);
    float inv = 1.f / s;
    for (int i = lane; i < n; i += 32) r[i] *= inv;
}

// ---------------------------------------------------------------------------
// Patch embed im2col + token assembly
// ---------------------------------------------------------------------------
__global__ void im2col_k(const float* __restrict__ in, float* __restrict__ col) {
    long long idx = (long long)blockIdx.x * 256 + threadIdx.x;
    if (idx >= (long long)Bv * NP * Dd) return;
    int k = (int)(idx % Dd);
    long long bp = idx / Dd;
    int b = (int)(bp / NP), p = (int)(bp % NP);
    int c = k >> 8, rr = k & 255, i = rr >> 4, j = rr & 15;
    int py = p / 14, px = p % 14;
    col[idx] = in[((long long)(b * 3 + c) * 224 + py * 16 + i) * 224 + px * 16 + j];
}

__global__ void build_x0_k(const float* __restrict__ img, const float* __restrict__ cls,
                           const float* __restrict__ pos, float* __restrict__ x0,
                           float* __restrict__ x) {
    long long idx = (long long)blockIdx.x * 256 + threadIdx.x;
    if (idx >= (long long)Bv * N1 * Dd) return;
    int d = (int)(idx % Dd);
    long long bn = idx / Dd;
    int n = (int)(bn % N1), b = (int)(bn / N1);
    float t = (n == 0) ? cls[d] : img[((long long)b * NP + (n - 1)) * Dd + d];
    float v = t + pos[n * Dd + d];
    x0[idx] = v;
    x[idx] = v;
}

__global__ void extract_q_k(const float* __restrict__ h, float* __restrict__ q) {
    int idx = blockIdx.x * 256 + threadIdx.x;
    if (idx >= Bv * Dd) return;
    int b = idx / Dd, d = idx % Dd;
    q[idx] = h[(long long)b * N1 * Dd + d];
}

__global__ void build_x2_k(const float* __restrict__ x0, const float* __restrict__ prompt,
                           const float* __restrict__ pos, const float* __restrict__ img,
                           const int* __restrict__ topk, float* __restrict__ x) {
    long long idx = (long long)blockIdx.x * 256 + threadIdx.x;
    if (idx >= (long long)Bv * N2 * Dd) return;
    int d = (int)(idx % Dd);
    long long bn = idx / Dd;
    int n = (int)(bn % N2), b = (int)(bn / N2);
    float v;
    if (n == 0) {
        v = x0[(long long)b * N1 * Dd + d];
    } else if (n < 1 + Sn * LPn) {
        int t = n - 1;
        int s = t / LPn, l = t % LPn;
        int pi = topk[b * Sn + s];
        v = prompt[((long long)pi * LPn + l) * Dd + d] + pos[d];
    } else {
        v = img[((long long)b * NP + (n - (1 + Sn * LPn))) * Dd + d];
    }
    x[idx] = v;
}

__global__ void pool_k(const float* __restrict__ h, float* __restrict__ pool) {
    int idx = blockIdx.x * 256 + threadIdx.x;
    if (idx >= Bv * Dd) return;
    int b = idx / Dd, d = idx % Dd;
    float s = 0.f;
#pragma unroll
    for (int t = 1; t <= Sn * LPn; t++) s += h[((long long)b * N2 + t) * Dd + d];
    pool[idx] = s * (1.f / (Sn * LPn));
}

// ---------------------------------------------------------------------------
// Cholesky (blocked NB=64): prep, diag potrf (fp32), panel trsm (fp32);
// trailing SYRK uses gemmT_k<1> with alpha=-1, resid=C, lower tiles only.
// ---------------------------------------------------------------------------
__global__ void chol_prep_k(const float* __restrict__ var, float* __restrict__ L,
                            float* __restrict__ logdet) {
    long long idx = (long long)blockIdx.x * 256 + threadIdx.x;
    if (idx >= (long long)Pn * Dd * Dd) return;
    int j = (int)(idx % Dd);
    long long pi = idx / Dd;
    int i = (int)(pi % Dd);
    int p = (int)(pi / Dd);
    L[idx] = fabsf(var[idx]) + (i == j ? 1.f : 0.f);
    if (i == 0 && j == 0) logdet[p] = 0.f;
}

__global__ void potrf_k(float* __restrict__ L, float* __restrict__ logdet, int kb) {
    int p = blockIdx.x;
    float* A = L + (long long)p * Dd * Dd + (long long)kb * 64 * Dd + kb * 64;
    __shared__ float s[64][65];
    int tid = threadIdx.x;
    for (int l = tid; l < 4096; l += 256) s[l >> 6][l & 63] = A[(l >> 6) * Dd + (l & 63)];
    __syncthreads();
    for (int k = 0; k < 64; k++) {
        if (tid == 0) s[k][k] = sqrtf(s[k][k]);
        __syncthreads();
        for (int i = k + 1 + tid; i < 64; i += 256) s[i][k] /= s[k][k];
        __syncthreads();
        for (int l = tid; l < 4096; l += 256) {
            int i = l >> 6, j = l & 63;
            if (i > k && j > k && j <= i) s[i][j] -= s[i][k] * s[j][k];
        }
        __syncthreads();
    }
    for (int l = tid; l < 4096; l += 256) A[(l >> 6) * Dd + (l & 63)] = s[l >> 6][l & 63];
    if (tid < 64) atomicAdd(&logdet[p], 2.f * logf(s[tid][tid]));
}

__global__ void trsm_k(float* __restrict__ L, int kb) {
    int p = blockIdx.x;
    int off = (kb + 1) * 64;
    __shared__ float s[64][65];
    int tid = threadIdx.x;
    float* Ldiag = L + (long long)p * Dd * Dd + (long long)kb * 64 * Dd + kb * 64;
    for (int l = tid; l < 4096; l += 256) s[l >> 6][l & 63] = Ldiag[(l >> 6) * Dd + (l & 63)];
    __syncthreads();
    int wid = tid >> 5, lane = tid & 31;
    int row = off + blockIdx.y * 8 + wid;
    if (row >= Dd) return;
    float* a = L + (long long)p * Dd * Dd + (long long)row * Dd + kb * 64;
    float a0 = a[lane], a1 = a[lane + 32];
#pragma unroll
    for (int j = 0; j < 64; j++) {
        float aj = (j < 32) ? __shfl_sync(0xffffffffu, a0, j)
                            : __shfl_sync(0xffffffffu, a1, j - 32);
        float y = aj / s[j][j];
        if (lane == (j & 31)) {
            if (j < 32) a0 = y; else a1 = y;
        }
        if (lane > j) a0 -= s[lane][j] * y;
        if (lane + 32 > j) a1 -= s[lane + 32][j] * y;
    }
    a[lane] = a0;
    a[lane + 32] = a1;
}

__global__ void transpose_k(const float* __restrict__ L, float* __restrict__ LT) {
    __shared__ float t[32][33];
    int p = blockIdx.z;
    int i0 = blockIdx.y * 32, j0 = blockIdx.x * 32;
    int x = threadIdx.x, y = threadIdx.y;    // 32 x 8
#pragma unroll
    for (int r = 0; r < 32; r += 8)
        t[y + r][x] = L[(long long)p * Dd * Dd + (long long)(i0 + y + r) * Dd + j0 + x];
    __syncthreads();
#pragma unroll
    for (int r = 0; r < 32; r += 8)
        LT[(long long)p * Dd * Dd + (long long)(j0 + y + r) * Dd + i0 + x] = t[x][y + r];
}

// warp per (b,p): forward substitution with residual in smem, coalesced LT rows
__global__ void solve_k(const float* __restrict__ LT, const float* __restrict__ q,
                        const float* __restrict__ mean, const float* __restrict__ logdet,
                        float* __restrict__ logp) {
    int p = blockIdx.x;
    int wid = threadIdx.x >> 5, lane = threadIdx.x & 31;
    int b = blockIdx.y * 8 + wid;
    __shared__ float rs[8][Dd];
    float* r = rs[wid];
    for (int i = lane; i < Dd; i += 32) r[i] = q[b * Dd + i] - mean[p * Dd + i];
    const float* lt = LT + (long long)p * Dd * Dd;
    float quad = 0.f;
    for (int j = 0; j < Dd; j++) {
        __syncwarp();
        float y = r[j] / lt[(long long)j * Dd + j];
        if (lane == 0) quad += y * y;
        for (int i = j + 1 + lane; i < Dd; i += 32) r[i] -= lt[(long long)j * Dd + i] * y;
    }
    if (lane == 0)
        logp[b * Pn + p] = -0.5f * ((float)Dd * LOG2PI_F + logdet[p] + quad);
}

__global__ void topk_k(const float* __restrict__ logp, int* __restrict__ topk) {
    int b = threadIdx.x;
    if (b >= Bv) return;
    float v[Pn];
#pragma unroll
    for (int p = 0; p < Pn; p++) v[p] = logp[b * Pn + p];
#pragma unroll
    for (int s = 0; s < Sn; s++) {
        float best = -3e38f;
        int bi = 0;
#pragma unroll
        for (int p = 0; p < Pn; p++) {
            if (v[p] > best) { best = v[p]; bi = p; }
        }
        topk[b * Sn + s] = bi;
        v[bi] = -3e38f;
    }
}

// ---------------------------------------------------------------------------
// Host side
// ---------------------------------------------------------------------------
static void* getsym(const void* symbol) {
    void* p = nullptr;
    cudaGetSymbolAddress(&p, symbol);
    return p;
}

static void gemm(bool transB, const float* A, const float* Bm, const float* bias,
                 const float* resid, float* C, int M, int N, int K,
                 int lda, int ldb, int ldc, int batch, int inner,
                 long long sAo, long long sAi, long long sBo, long long sBi,
                 long long sCo, long long sCi, float alpha, int act, int lowerOnly) {
    dim3 grid((N + 63) / 64, (M + 63) / 64, batch);
    if (transB)
        gemmT_k<1><<<grid, 128>>>(A, Bm, bias, resid, C, M, N, K, lda, ldb, ldc, inner,
                                  sAo, sAi, sBo, sBi, sCo, sCi, alpha, act, lowerOnly);
    else
        gemmT_k<0><<<grid, 128>>>(A, Bm, bias, resid, C, M, N, K, lda, ldb, ldc, inner,
                                  sAo, sAi, sBo, sBi, sCo, sCi, alpha, act, lowerOnly);
}

struct Weights {
    const float *ln1_g, *ln1_b, *qkv_w, *qkv_b, *proj_w, *proj_b;
    const float *ln2_g, *ln2_b, *fc1_w, *fc1_b, *fc2_w, *fc2_b;
};

static void run_blocks(float* x, int N, const Weights& w,
                       float* h, float* qkv, float* att, float* o, float* mlp) {
    int M = Bv * N;
    int rows = Bv * NHh * N;
    for (int l = 0; l < NLAY; l++) {
        // LN1
        ln_k<<<M, 256>>>(x, w.ln1_g + l * Dd, w.ln1_b + l * Dd, h, M);
        // QKV: [M,768] x [768,2304] + bias
        gemm(false, h, w.qkv_w + (long long)l * Dd * 3 * Dd, w.qkv_b + l * 3 * Dd,
             nullptr, qkv, M, 3 * Dd, Dd, Dd, 3 * Dd, 3 * Dd,
             1, 1, 0, 0, 0, 0, 0, 0, 1.f, 0, 0);
        // att = Q K^T / 8 : batched over (b,h)
        gemm(true, qkv, qkv + Dd, nullptr, nullptr, att,
             N, N, DHh, 3 * Dd, 3 * Dd, N, Bv * NHh, NHh,
             (long long)N * 3 * Dd, DHh, (long long)N * 3 * Dd, DHh,
             (long long)NHh * N * N, (long long)N * N, 0.125f, 0, 0);
        softmax_k<<<(rows + 3) / 4, 128>>>(att, N, rows);
        // o = att V
        gemm(false, att, qkv + 2 * Dd, nullptr, nullptr, o,
             N, DHh, N, N, 3 * Dd, Dd, Bv * NHh, NHh,
             (long long)NHh * N * N, (long long)N * N, (long long)N * 3 * Dd, DHh,
             (long long)N * Dd, DHh, 1.f, 0, 0);
        // x = x + o @ proj_w + proj_b
        gemm(false, o, w.proj_w + (long long)l * Dd * Dd, w.proj_b + l * Dd,
             x, x, M, Dd, Dd, Dd, Dd, Dd, 1, 1, 0, 0, 0, 0, 0, 0, 1.f, 0, 0);
        // LN2
        ln_k<<<M, 256>>>(x, w.ln2_g + l * Dd, w.ln2_b + l * Dd, h, M);
        // mlp = gelu(h @ fc1 + b1)
        gemm(false, h, w.fc1_w + (long long)l * Dd * DFFd, w.fc1_b + l * DFFd,
             nullptr, mlp, M, DFFd, Dd, Dd, DFFd, DFFd,
             1, 1, 0, 0, 0, 0, 0, 0, 1.f, 1, 0);
        // x = x + mlp @ fc2 + b2
        gemm(false, mlp, w.fc2_w + (long long)l * DFFd * Dd, w.fc2_b + l * Dd,
             x, x, M, Dd, DFFd, DFFd, Dd, Dd, 1, 1, 0, 0, 0, 0, 0, 0, 1.f, 0, 0);
    }
}

extern "C" void kernel_launch(void* const* d_in, const int* in_sizes, int n_in,
                              void* d_out, int out_size) {
    (void)in_sizes; (void)n_in; (void)out_size;
    const float* inputs   = (const float*)d_in[0];
    const float* patch_w  = (const float*)d_in[1];
    const float* patch_b  = (const float*)d_in[2];
    const float* cls_tok  = (const float*)d_in[3];
    const float* pos_emb  = (const float*)d_in[4];
    Weights w;
    w.ln1_g  = (const float*)d_in[5];
    w.ln1_b  = (const float*)d_in[6];
    w.qkv_w  = (const float*)d_in[7];
    w.qkv_b  = (const float*)d_in[8];
    w.proj_w = (const float*)d_in[9];
    w.proj_b = (const float*)d_in[10];
    w.ln2_g  = (const float*)d_in[11];
    w.ln2_b  = (const float*)d_in[12];
    w.fc1_w  = (const float*)d_in[13];
    w.fc1_b  = (const float*)d_in[14];
    w.fc2_w  = (const float*)d_in[15];
    w.fc2_b  = (const float*)d_in[16];
    const float* norm_g   = (const float*)d_in[17];
    const float* norm_b   = (const float*)d_in[18];
    const float* head_w   = (const float*)d_in[19];
    const float* head_b   = (const float*)d_in[20];
    const float* prompt   = (const float*)d_in[21];
    const float* mean     = (const float*)d_in[22];
    const float* variance = (const float*)d_in[23];
    float* out = (float*)d_out;

    float* col  = (float*)getsym(g_col);
    float* img  = (float*)getsym(g_img);
    float* x0   = (float*)getsym(g_x0);
    float* x    = (float*)getsym(g_x);
    float* h    = (float*)getsym(g_h);
    float* qkv  = (float*)getsym(g_qkv);
    float* att  = (float*)getsym(g_att);
    float* o    = (float*)getsym(g_o);
    float* mlp  = (float*)getsym(g_mlp);
    float* qv   = (float*)getsym(g_q);
    float* L    = (float*)getsym(g_L);
    float* LT   = (float*)getsym(g_LT);
    float* logd = (float*)getsym(g_logdet);
    float* logp = (float*)getsym(g_logp);
    int*   topk = (int*)getsym(g_topk);
    float* pool = (float*)getsym(g_pool);

    // ---- patch embed ----
    {
        long long tot = (long long)Bv * NP * Dd;
        im2col_k<<<(unsigned)((tot + 255) / 256), 256>>>(inputs, col);
        // img = col @ patch_w^T + patch_b   (patch_w is [768,768] row-major)
        gemm(true, col, patch_w, patch_b, nullptr, img,
             Bv * NP, Dd, Dd, Dd, Dd, Dd, 1, 1, 0, 0, 0, 0, 0, 0, 1.f, 0, 0);
        long long tot0 = (long long)Bv * N1 * Dd;
        build_x0_k<<<(unsigned)((tot0 + 255) / 256), 256>>>(img, cls_tok, pos_emb, x0, x);
    }

    // ---- Cholesky of cov = |variance| + I  (blocked NB=64) ----
    {
        long long tot = (long long)Pn * Dd * Dd;
        chol_prep_k<<<(unsigned)((tot + 255) / 256), 256>>>(variance, L, logd);
        for (int kb = 0; kb < Dd / 64; kb++) {
            potrf_k<<<Pn, 256>>>(L, logd, kb);
            int T = Dd - (kb + 1) * 64;
            if (T > 0) {
                trsm_k<<<dim3(Pn, (T + 7) / 8), 256>>>(L, kb);
                long long off = (long long)(kb + 1) * 64;
                const float* pan = L + off * Dd + kb * 64;
                float* trail = L + off * Dd + off;
                gemm(true, pan, pan, nullptr, trail, trail,
                     T, T, 64, Dd, Dd, Dd, Pn, 1,
                     (long long)Dd * Dd, 0, (long long)Dd * Dd, 0,
                     (long long)Dd * Dd, 0, -1.f, 0, 1);
            }
        }
        transpose_k<<<dim3(Dd / 32, Dd / 32, Pn), dim3(32, 8)>>>(L, LT);
    }

    // ---- pass 1 (query) ----
    run_blocks(x, N1, w, h, qkv, att, o, mlp);
    ln_k<<<Bv * N1, 256>>>(x, norm_g, norm_b, h, Bv * N1);
    extract_q_k<<<(Bv * Dd + 255) / 256, 256>>>(h, qv);

    // ---- MVN logprob + top-k ----
    solve_k<<<dim3(Pn, Bv / 8), 256>>>(LT, qv, mean, logd, logp);
    topk_k<<<1, 16>>>(logp, topk);

    // ---- pass 2 (prompted) ----
    {
        long long tot = (long long)Bv * N2 * Dd;
        build_x2_k<<<(unsigned)((tot + 255) / 256), 256>>>(x0, prompt, pos_emb, img, topk, x);
    }
    run_blocks(x, N2, w, h, qkv, att, o, mlp);
    ln_k<<<Bv * N2, 256>>>(x, norm_g, norm_b, h, Bv * N2);
    pool_k<<<(Bv * Dd + 255) / 256, 256>>>(h, pool);

    // ---- head ----
    gemm(false, pool, head_w, head_b, nullptr, out,
         Bv, NCn, Dd, Dd, NCn, NCn, 1, 1, 0, 0, 0, 0, 0, 0, 1.f, 0, 0);
}

// round 4
// speedup vs baseline: 3.5545x; 2.4795x over previous
#include <cuda_runtime.h>
#include <math.h>

// ---------------------------------------------------------------------------
// Problem constants
// ---------------------------------------------------------------------------
#define Bv   16
#define Dd   768
#define NLAY 12
#define NHh  12
#define DHh  64
#define DFFd 3072
#define Pn   10
#define Sn   5
#define LPn  5
#define NCn  100
#define NP   196
#define N1   197
#define N2   222          // 1 + S*LP + 196
#define LOG2PI_F 1.8378770664093454f

// ---------------------------------------------------------------------------
// Device scratch (static __device__ arrays; no runtime allocation)
// ---------------------------------------------------------------------------
__device__ __align__(16) float g_col [(size_t)Bv * NP * Dd];
__device__ __align__(16) float g_img [(size_t)Bv * NP * Dd];
__device__ __align__(16) float g_x0  [(size_t)Bv * N1 * Dd];
__device__ __align__(16) float g_x   [(size_t)Bv * N2 * Dd];
__device__ __align__(16) float g_h   [(size_t)Bv * N2 * Dd];
__device__ __align__(16) float g_qkv [(size_t)Bv * N2 * 3 * Dd];
__device__ __align__(16) float g_att [(size_t)Bv * NHh * N2 * N2];
__device__ __align__(16) float g_o   [(size_t)Bv * N2 * Dd];
__device__ __align__(16) float g_mlp [(size_t)Bv * N2 * DFFd];
__device__ __align__(16) float g_q   [(size_t)Bv * Dd];
__device__ __align__(16) float g_L   [(size_t)Pn * Dd * Dd];
__device__ __align__(16) float g_LT  [(size_t)Pn * Dd * Dd];
__device__ float g_logdet[Pn];
__device__ float g_logp[Bv * Pn];
__device__ int   g_topk[Bv * Sn];
__device__ __align__(16) float g_pool[Bv * Dd];

// pre-converted (tf32-rounded) weights
#define WC_QKV   0LL
#define WC_PROJ  (WC_QKV  + 12LL * 768 * 2304)
#define WC_FC1   (WC_PROJ + 12LL * 768 * 768)
#define WC_FC2   (WC_FC1  + 12LL * 768 * 3072)
#define WC_PATCH (WC_FC2  + 12LL * 3072 * 768)
#define WC_TOTAL (WC_PATCH + 768LL * 768)
__device__ __align__(16) float g_wc[WC_TOTAL];

// ---------------------------------------------------------------------------
// Helpers
// ---------------------------------------------------------------------------
__device__ __forceinline__ float warp_sum(float v) {
#pragma unroll
    for (int o = 16; o > 0; o >>= 1) v += __shfl_xor_sync(0xffffffffu, v, o);
    return v;
}
__device__ __forceinline__ float warp_max(float v) {
#pragma unroll
    for (int o = 16; o > 0; o >>= 1) v = fmaxf(v, __shfl_xor_sync(0xffffffffu, v, o));
    return v;
}
__device__ __forceinline__ float gelu_f(float x) {
    float x3 = x * x * x;
    return 0.5f * x * (1.f + tanhf(0.7978845608028654f * (x + 0.044715f * x3)));
}
__device__ __forceinline__ float to_tf32(float x) {
    float r;
    asm("cvt.rna.tf32.f32 %0, %1;" : "=f"(r) : "f"(x));
    return r;
}
__device__ __forceinline__ void mma8(float c[4], const unsigned a[4], const unsigned b[2]) {
    asm volatile(
        "mma.sync.aligned.m16n8k8.row.col.f32.tf32.tf32.f32 "
        "{%0,%1,%2,%3}, {%4,%5,%6,%7}, {%8,%9}, {%0,%1,%2,%3};\n"
        : "+f"(c[0]), "+f"(c[1]), "+f"(c[2]), "+f"(c[3])
        : "r"(a[0]), "r"(a[1]), "r"(a[2]), "r"(a[3]), "r"(b[0]), "r"(b[1]));
}
__device__ __forceinline__ void cpa16(void* dst_smem, const void* src, int srcsize) {
    unsigned d = (unsigned)__cvta_generic_to_shared(dst_smem);
    asm volatile("cp.async.ca.shared.global [%0], [%1], 16, %2;\n"
                 :: "r"(d), "l"(src), "r"(srcsize));
}

// elementwise tf32 rounding (weight pre-conversion)
__global__ void cvt_k(const float* __restrict__ s, float* __restrict__ d, long long n) {
    long long i = (long long)blockIdx.x * 256 + threadIdx.x;
    if (i < n) d[i] = to_tf32(s[i]);
}

// ---------------------------------------------------------------------------
// Big dense GEMM: 128x128 CTA tile, BK=32, 256 threads (8 warps, warp 64x32),
// cp.async 2-stage double buffer. Inputs assumed pre-rounded to tf32.
// Requires: K % 32 == 0, N % 128 == 0; only M has a tail.
//   C = act(alpha*A*op(B) + bias) + resid ; optional output tf32 rounding.
// Smem: A [m][k] stride 36 (conflict-free frag loads: 4*gid+ctg),
//       B no-trans [k][n] stride 136 (8*ctg+gid), B^T [n][k] stride 36.
// ---------------------------------------------------------------------------
#define GB_STAGE 9216   // floats per stage: 128*36 + max(32*136, 128*36)

template <int TRANSB>
__global__ void __launch_bounds__(256)
gemmB_k(const float* __restrict__ A, const float* __restrict__ Bm,
        const float* __restrict__ bias, const float* __restrict__ resid,
        float* __restrict__ C, int M, int N, int K,
        int lda, int ldb, int ldc, float alpha, int act, int rndOut) {
    extern __shared__ float sm[];
    int tid = threadIdx.x;
    int m0 = blockIdx.y * 128, n0 = blockIdx.x * 128;
    int warp = tid >> 5, lane = tid & 31;
    int gid = lane >> 2, ctg = lane & 3;
    int wm = (warp & 1) * 64, wn = (warp >> 1) * 32;

    float acc[4][4][4];
#pragma unroll
    for (int mi = 0; mi < 4; mi++)
#pragma unroll
        for (int ni = 0; ni < 4; ni++)
#pragma unroll
            for (int e = 0; e < 4; e++) acc[mi][ni][e] = 0.f;

    auto loadStage = [&](int kt, int st) {
        float* As = sm + st * GB_STAGE;
        float* Bs = As + 4608;
        int k0 = kt * 32;
#pragma unroll
        for (int i = 0; i < 4; i++) {
            int ch = tid + i * 256;
            int row = ch >> 3, kc = ch & 7;
            int gm = m0 + row;
            const float* src = A + (long long)gm * lda + k0 + kc * 4;
            cpa16(As + row * 36 + kc * 4, src, (gm < M) ? 16 : 0);
        }
        if (TRANSB) {
#pragma unroll
            for (int i = 0; i < 4; i++) {
                int ch = tid + i * 256;
                int nn = ch >> 3, kc = ch & 7;
                const float* src = Bm + (long long)(n0 + nn) * ldb + k0 + kc * 4;
                cpa16(Bs + nn * 36 + kc * 4, src, 16);
            }
        } else {
#pragma unroll
            for (int i = 0; i < 4; i++) {
                int ch = tid + i * 256;
                int kk = ch >> 5, nc = ch & 31;
                const float* src = Bm + (long long)(k0 + kk) * ldb + n0 + nc * 4;
                cpa16(Bs + kk * 136 + nc * 4, src, 16);
            }
        }
    };

    int KT = K >> 5;
    loadStage(0, 0);
    asm volatile("cp.async.commit_group;\n");
    for (int kt = 0; kt < KT; kt++) {
        if (kt + 1 < KT) loadStage(kt + 1, (kt + 1) & 1);
        asm volatile("cp.async.commit_group;\n");
        asm volatile("cp.async.wait_group 1;\n");
        __syncthreads();
        const float* As = sm + (kt & 1) * GB_STAGE;
        const float* Bs = As + 4608;
#pragma unroll
        for (int ks = 0; ks < 4; ks++) {
            int kr0 = ks * 8 + ctg, kr1 = kr0 + 4;
            unsigned a[4][4], b[4][2];
#pragma unroll
            for (int mi = 0; mi < 4; mi++) {
                int mb = wm + mi * 16 + gid;
                a[mi][0] = __float_as_uint(As[mb * 36 + kr0]);
                a[mi][1] = __float_as_uint(As[(mb + 8) * 36 + kr0]);
                a[mi][2] = __float_as_uint(As[mb * 36 + kr1]);
                a[mi][3] = __float_as_uint(As[(mb + 8) * 36 + kr1]);
            }
#pragma unroll
            for (int ni = 0; ni < 4; ni++) {
                int nb = wn + ni * 8 + gid;
                if (TRANSB) {
                    b[ni][0] = __float_as_uint(Bs[nb * 36 + kr0]);
                    b[ni][1] = __float_as_uint(Bs[nb * 36 + kr1]);
                } else {
                    b[ni][0] = __float_as_uint(Bs[kr0 * 136 + nb]);
                    b[ni][1] = __float_as_uint(Bs[kr1 * 136 + nb]);
                }
            }
#pragma unroll
            for (int mi = 0; mi < 4; mi++)
#pragma unroll
                for (int ni = 0; ni < 4; ni++)
                    mma8(acc[mi][ni], a[mi], b[ni]);
        }
        __syncthreads();
    }

#pragma unroll
    for (int mi = 0; mi < 4; mi++) {
#pragma unroll
        for (int ni = 0; ni < 4; ni++) {
            int col = n0 + wn + ni * 8 + ctg * 2;
#pragma unroll
            for (int e = 0; e < 4; e++) {
                int r = m0 + wm + mi * 16 + gid + ((e >> 1) << 3);
                int cc = col + (e & 1);
                if (r < M) {
                    float v = alpha * acc[mi][ni][e];
                    if (bias) v += bias[cc];
                    if (act == 1) v = gelu_f(v);
                    if (resid) v += resid[(long long)r * ldc + cc];
                    if (rndOut) v = to_tf32(v);
                    C[(long long)r * ldc + cc] = v;
                }
            }
        }
    }
}

// ---------------------------------------------------------------------------
// Small/batched tensor-core GEMM (64x64 tile, 128 threads) — attention, SYRK,
// head. Keeps cvt-on-fill (inputs may be raw fp32).
// ---------------------------------------------------------------------------
template <int TRANSB>
__global__ void gemmT_k(const float* __restrict__ A, const float* __restrict__ Bm,
                        const float* __restrict__ bias, const float* __restrict__ resid,
                        float* __restrict__ C,
                        int M, int N, int K, int lda, int ldb, int ldc,
                        int inner,
                        long long sAo, long long sAi, long long sBo, long long sBi,
                        long long sCo, long long sCi,
                        float alpha, int act, int lowerOnly, int rndOut) {
    if (lowerOnly && blockIdx.x > blockIdx.y) return;

    int z = blockIdx.z;
    int zo = z / inner, zi = z % inner;
    A  += zo * sAo + zi * sAi;
    Bm += zo * sBo + zi * sBi;
    long long co = zo * sCo + zi * sCi;
    C += co;
    if (resid) resid += co;

    __shared__ float As[64 * 36];
    __shared__ float Bs[2304];

    int tid = threadIdx.x;
    int m0 = blockIdx.y * 64, n0 = blockIdx.x * 64;
    int warp = tid >> 5, lane = tid & 31;
    int gid = lane >> 2, ctg = lane & 3;
    int wm = (warp >> 1) * 32, wn = (warp & 1) * 32;

    float acc[2][4][4];
#pragma unroll
    for (int mi = 0; mi < 2; mi++)
#pragma unroll
        for (int ni = 0; ni < 4; ni++)
#pragma unroll
            for (int e = 0; e < 4; e++) acc[mi][ni][e] = 0.f;

    for (int k0 = 0; k0 < K; k0 += 32) {
#pragma unroll
        for (int i = 0; i < 16; i++) {
            int l = tid + i * 128;
            int mm = l >> 5, kk = l & 31;
            int gm = m0 + mm, gk = k0 + kk;
            As[mm * 36 + kk] = (gm < M && gk < K) ? to_tf32(A[(long long)gm * lda + gk]) : 0.f;
        }
        if (TRANSB) {
#pragma unroll
            for (int i = 0; i < 16; i++) {
                int l = tid + i * 128;
                int nn = l >> 5, kk = l & 31;
                int gn = n0 + nn, gk = k0 + kk;
                Bs[nn * 36 + kk] = (gn < N && gk < K) ? to_tf32(Bm[(long long)gn * ldb + gk]) : 0.f;
            }
        } else {
#pragma unroll
            for (int i = 0; i < 16; i++) {
                int l = tid + i * 128;
                int kk = l >> 6, nn = l & 63;
                int gk = k0 + kk, gn = n0 + nn;
                Bs[kk * 72 + nn] = (gk < K && gn < N) ? to_tf32(Bm[(long long)gk * ldb + gn]) : 0.f;
            }
        }
        __syncthreads();
#pragma unroll
        for (int ks = 0; ks < 4; ks++) {
            int kr0 = ks * 8 + ctg, kr1 = kr0 + 4;
            unsigned a[2][4], b[4][2];
#pragma unroll
            for (int mi = 0; mi < 2; mi++) {
                int mb = wm + mi * 16 + gid;
                a[mi][0] = __float_as_uint(As[mb * 36 + kr0]);
                a[mi][1] = __float_as_uint(As[(mb + 8) * 36 + kr0]);
                a[mi][2] = __float_as_uint(As[mb * 36 + kr1]);
                a[mi][3] = __float_as_uint(As[(mb + 8) * 36 + kr1]);
            }
#pragma unroll
            for (int ni = 0; ni < 4; ni++) {
                int nb = wn + ni * 8 + gid;
                if (TRANSB) {
                    b[ni][0] = __float_as_uint(Bs[nb * 36 + kr0]);
                    b[ni][1] = __float_as_uint(Bs[nb * 36 + kr1]);
                } else {
                    b[ni][0] = __float_as_uint(Bs[kr0 * 72 + nb]);
                    b[ni][1] = __float_as_uint(Bs[kr1 * 72 + nb]);
                }
            }
#pragma unroll
            for (int mi = 0; mi < 2; mi++)
#pragma unroll
                for (int ni = 0; ni < 4; ni++)
                    mma8(acc[mi][ni], a[mi], b[ni]);
        }
        __syncthreads();
    }

#pragma unroll
    for (int mi = 0; mi < 2; mi++) {
#pragma unroll
        for (int ni = 0; ni < 4; ni++) {
            int col = n0 + wn + ni * 8 + ctg * 2;
#pragma unroll
            for (int e = 0; e < 4; e++) {
                int r = m0 + wm + mi * 16 + gid + ((e >> 1) << 3);
                int cc = col + (e & 1);
                if (r < M && cc < N) {
                    float v = alpha * acc[mi][ni][e];
                    if (bias) v += bias[cc];
                    if (act == 1) v = gelu_f(v);
                    if (resid) v += resid[(long long)r * ldc + cc];
                    if (rndOut) v = to_tf32(v);
                    C[(long long)r * ldc + cc] = v;
                }
            }
        }
    }
}

// ---------------------------------------------------------------------------
// LayerNorm (one 256-thread block per 768-wide row) — output tf32-rounded
// ---------------------------------------------------------------------------
__global__ void ln_k(const float* __restrict__ x, const float* __restrict__ g,
                     const float* __restrict__ b, float* __restrict__ out, int rows) {
    int row = blockIdx.x;
    if (row >= rows) return;
    const float* xr = x + (size_t)row * Dd;
    float* yr = out + (size_t)row * Dd;
    int tid = threadIdx.x;
    float v0 = xr[tid], v1 = xr[tid + 256], v2 = xr[tid + 512];
    __shared__ float red[8];
    __shared__ float stat[2];
    float s = warp_sum(v0 + v1 + v2);
    if ((tid & 31) == 0) red[tid >> 5] = s;
    __syncthreads();
    if (tid == 0) {
        float t = 0.f;
#pragma unroll
        for (int i = 0; i < 8; i++) t += red[i];
        stat[0] = t * (1.f / Dd);
    }
    __syncthreads();
    float m = stat[0];
    float d0 = v0 - m, d1 = v1 - m, d2 = v2 - m;
    s = warp_sum(d0 * d0 + d1 * d1 + d2 * d2);
    if ((tid & 31) == 0) red[tid >> 5] = s;
    __syncthreads();
    if (tid == 0) {
        float t = 0.f;
#pragma unroll
        for (int i = 0; i < 8; i++) t += red[i];
        stat[1] = rsqrtf(t * (1.f / Dd) + 1e-6f);
    }
    __syncthreads();
    float inv = stat[1];
    yr[tid]       = to_tf32(d0 * inv * g[tid]       + b[tid]);
    yr[tid + 256] = to_tf32(d1 * inv * g[tid + 256] + b[tid + 256]);
    yr[tid + 512] = to_tf32(d2 * inv * g[tid + 512] + b[tid + 512]);
}

// ---------------------------------------------------------------------------
// Softmax over rows (warp per row) — output tf32-rounded
// ---------------------------------------------------------------------------
__global__ void softmax_k(float* __restrict__ att, int n, int rows) {
    int row = blockIdx.x * (blockDim.x >> 5) + (threadIdx.x >> 5);
    if (row >= rows) return;
    int lane = threadIdx.x & 31;
    float* r = att + (long long)row * n;
    float m = -3e38f;
    for (int i = lane; i < n; i += 32) m = fmaxf(m, r[i]);
    m = warp_max(m);
    float s = 0.f;
    for (int i = lane; i < n; i += 32) {
        float e = expf(r[i] - m);
        r[i] = e;
        s += e;
    }
    s = warp_sum(s);
    float inv = 1.f / s;
    for (int i = lane; i < n; i += 32) r[i] = to_tf32(r[i] * inv);
}

// ---------------------------------------------------------------------------
// Patch embed im2col (tf32-rounded) + token assembly
// ---------------------------------------------------------------------------
__global__ void im2col_k(const float* __restrict__ in, float* __restrict__ col) {
    long long idx = (long long)blockIdx.x * 256 + threadIdx.x;
    if (idx >= (long long)Bv * NP * Dd) return;
    int k = (int)(idx % Dd);
    long long bp = idx / Dd;
    int b = (int)(bp / NP), p = (int)(bp % NP);
    int c = k >> 8, rr = k & 255, i = rr >> 4, j = rr & 15;
    int py = p / 14, px = p % 14;
    col[idx] = to_tf32(in[((long long)(b * 3 + c) * 224 + py * 16 + i) * 224 + px * 16 + j]);
}

__global__ void build_x0_k(const float* __restrict__ img, const float* __restrict__ cls,
                           const float* __restrict__ pos, float* __restrict__ x0,
                           float* __restrict__ x) {
    long long idx = (long long)blockIdx.x * 256 + threadIdx.x;
    if (idx >= (long long)Bv * N1 * Dd) return;
    int d = (int)(idx % Dd);
    long long bn = idx / Dd;
    int n = (int)(bn % N1), b = (int)(bn / N1);
    float t = (n == 0) ? cls[d] : img[((long long)b * NP + (n - 1)) * Dd + d];
    float v = t + pos[n * Dd + d];
    x0[idx] = v;
    x[idx] = v;
}

__global__ void extract_q_k(const float* __restrict__ h, float* __restrict__ q) {
    int idx = blockIdx.x * 256 + threadIdx.x;
    if (idx >= Bv * Dd) return;
    int b = idx / Dd, d = idx % Dd;
    q[idx] = h[(long long)b * N1 * Dd + d];
}

__global__ void build_x2_k(const float* __restrict__ x0, const float* __restrict__ prompt,
                           const float* __restrict__ pos, const float* __restrict__ img,
                           const int* __restrict__ topk, float* __restrict__ x) {
    long long idx = (long long)blockIdx.x * 256 + threadIdx.x;
    if (idx >= (long long)Bv * N2 * Dd) return;
    int d = (int)(idx % Dd);
    long long bn = idx / Dd;
    int n = (int)(bn % N2), b = (int)(bn / N2);
    float v;
    if (n == 0) {
        v = x0[(long long)b * N1 * Dd + d];
    } else if (n < 1 + Sn * LPn) {
        int t = n - 1;
        int s = t / LPn, l = t % LPn;
        int pi = topk[b * Sn + s];
        v = prompt[((long long)pi * LPn + l) * Dd + d] + pos[d];
    } else {
        v = img[((long long)b * NP + (n - (1 + Sn * LPn))) * Dd + d];
    }
    x[idx] = v;
}

__global__ void pool_k(const float* __restrict__ h, float* __restrict__ pool) {
    int idx = blockIdx.x * 256 + threadIdx.x;
    if (idx >= Bv * Dd) return;
    int b = idx / Dd, d = idx % Dd;
    float s = 0.f;
#pragma unroll
    for (int t = 1; t <= Sn * LPn; t++) s += h[((long long)b * N2 + t) * Dd + d];
    pool[idx] = s * (1.f / (Sn * LPn));
}

// ---------------------------------------------------------------------------
// Cholesky (blocked NB=64)
// ---------------------------------------------------------------------------
__global__ void chol_prep_k(const float* __restrict__ var, float* __restrict__ L,
                            float* __restrict__ logdet) {
    long long idx = (long long)blockIdx.x * 256 + threadIdx.x;
    if (idx >= (long long)Pn * Dd * Dd) return;
    int j = (int)(idx % Dd);
    long long pi = idx / Dd;
    int i = (int)(pi % Dd);
    int p = (int)(pi / Dd);
    L[idx] = fabsf(var[idx]) + (i == j ? 1.f : 0.f);
    if (i == 0 && j == 0) logdet[p] = 0.f;
}

__global__ void potrf_k(float* __restrict__ L, float* __restrict__ logdet, int kb) {
    int p = blockIdx.x;
    float* A = L + (long long)p * Dd * Dd + (long long)kb * 64 * Dd + kb * 64;
    __shared__ float s[64][65];
    int tid = threadIdx.x;
    for (int l = tid; l < 4096; l += 256) s[l >> 6][l & 63] = A[(l >> 6) * Dd + (l & 63)];
    __syncthreads();
    for (int k = 0; k < 64; k++) {
        if (tid == 0) s[k][k] = sqrtf(s[k][k]);
        __syncthreads();
        for (int i = k + 1 + tid; i < 64; i += 256) s[i][k] /= s[k][k];
        __syncthreads();
        for (int l = tid; l < 4096; l += 256) {
            int i = l >> 6, j = l & 63;
            if (i > k && j > k && j <= i) s[i][j] -= s[i][k] * s[j][k];
        }
        __syncthreads();
    }
    for (int l = tid; l < 4096; l += 256) A[(l >> 6) * Dd + (l & 63)] = s[l >> 6][l & 63];
    if (tid < 64) atomicAdd(&logdet[p], 2.f * logf(s[tid][tid]));
}

__global__ void trsm_k(float* __restrict__ L, int kb) {
    int p = blockIdx.x;
    int off = (kb + 1) * 64;
    __shared__ float s[64][65];
    int tid = threadIdx.x;
    float* Ldiag = L + (long long)p * Dd * Dd + (long long)kb * 64 * Dd + kb * 64;
    for (int l = tid; l < 4096; l += 256) s[l >> 6][l & 63] = Ldiag[(l >> 6) * Dd + (l & 63)];
    __syncthreads();
    int wid = tid >> 5, lane = tid & 31;
    int row = off + blockIdx.y * 8 + wid;
    if (row >= Dd) return;
    float* a = L + (long long)p * Dd * Dd + (long long)row * Dd + kb * 64;
    float a0 = a[lane], a1 = a[lane + 32];
#pragma unroll
    for (int j = 0; j < 64; j++) {
        float aj = (j < 32) ? __shfl_sync(0xffffffffu, a0, j)
                            : __shfl_sync(0xffffffffu, a1, j - 32);
        float y = aj / s[j][j];
        if (lane == (j & 31)) {
            if (j < 32) a0 = y; else a1 = y;
        }
        if (lane > j) a0 -= s[lane][j] * y;
        if (lane + 32 > j) a1 -= s[lane + 32][j] * y;
    }
    a[lane] = a0;
    a[lane + 32] = a1;
}

__global__ void transpose_k(const float* __restrict__ L, float* __restrict__ LT) {
    __shared__ float t[32][33];
    int p = blockIdx.z;
    int i0 = blockIdx.y * 32, j0 = blockIdx.x * 32;
    int x = threadIdx.x, y = threadIdx.y;    // 32 x 8
#pragma unroll
    for (int r = 0; r < 32; r += 8)
        t[y + r][x] = L[(long long)p * Dd * Dd + (long long)(i0 + y + r) * Dd + j0 + x];
    __syncthreads();
#pragma unroll
    for (int r = 0; r < 32; r += 8)
        LT[(long long)p * Dd * Dd + (long long)(j0 + y + r) * Dd + i0 + x] = t[x][y + r];
}

__global__ void solve_k(const float* __restrict__ LT, const float* __restrict__ q,
                        const float* __restrict__ mean, const float* __restrict__ logdet,
                        float* __restrict__ logp) {
    int p = blockIdx.x;
    int wid = threadIdx.x >> 5, lane = threadIdx.x & 31;
    int b = blockIdx.y * 8 + wid;
    __shared__ float rs[8][Dd];
    float* r = rs[wid];
    for (int i = lane; i < Dd; i += 32) r[i] = q[b * Dd + i] - mean[p * Dd + i];
    const float* lt = LT + (long long)p * Dd * Dd;
    float quad = 0.f;
    for (int j = 0; j < Dd; j++) {
        __syncwarp();
        float y = r[j] / lt[(long long)j * Dd + j];
        if (lane == 0) quad += y * y;
        for (int i = j + 1 + lane; i < Dd; i += 32) r[i] -= lt[(long long)j * Dd + i] * y;
    }
    if (lane == 0)
        logp[b * Pn + p] = -0.5f * ((float)Dd * LOG2PI_F + logdet[p] + quad);
}

__global__ void topk_k(const float* __restrict__ logp, int* __restrict__ topk) {
    int b = threadIdx.x;
    if (b >= Bv) return;
    float v[Pn];
#pragma unroll
    for (int p = 0; p < Pn; p++) v[p] = logp[b * Pn + p];
#pragma unroll
    for (int s = 0; s < Sn; s++) {
        float best = -3e38f;
        int bi = 0;
#pragma unroll
        for (int p = 0; p < Pn; p++) {
            if (v[p] > best) { best = v[p]; bi = p; }
        }
        topk[b * Sn + s] = bi;
        v[bi] = -3e38f;
    }
}

// ---------------------------------------------------------------------------
// Host side
// ---------------------------------------------------------------------------
static void* getsym(const void* symbol) {
    void* p = nullptr;
    cudaGetSymbolAddress(&p, symbol);
    return p;
}

static void gemm(bool transB, const float* A, const float* Bm, const float* bias,
                 const float* resid, float* C, int M, int N, int K,
                 int lda, int ldb, int ldc, int batch, int inner,
                 long long sAo, long long sAi, long long sBo, long long sBi,
                 long long sCo, long long sCi, float alpha, int act, int lowerOnly,
                 int rndOut) {
    dim3 grid((N + 63) / 64, (M + 63) / 64, batch);
    if (transB)
        gemmT_k<1><<<grid, 128>>>(A, Bm, bias, resid, C, M, N, K, lda, ldb, ldc, inner,
                                  sAo, sAi, sBo, sBi, sCo, sCi, alpha, act, lowerOnly, rndOut);
    else
        gemmT_k<0><<<grid, 128>>>(A, Bm, bias, resid, C, M, N, K, lda, ldb, ldc, inner,
                                  sAo, sAi, sBo, sBi, sCo, sCi, alpha, act, lowerOnly, rndOut);
}

static void gemmB(bool transB, const float* A, const float* Bm, const float* bias,
                  const float* resid, float* C, int M, int N, int K,
                  int lda, int ldb, int ldc, int act, int rndOut) {
    dim3 grid(N / 128, (M + 127) / 128);
    size_t smem = 2 * GB_STAGE * sizeof(float);
    if (transB)
        gemmB_k<1><<<grid, 256, smem>>>(A, Bm, bias, resid, C, M, N, K, lda, ldb, ldc,
                                        1.f, act, rndOut);
    else
        gemmB_k<0><<<grid, 256, smem>>>(A, Bm, bias, resid, C, M, N, K, lda, ldb, ldc,
                                        1.f, act, rndOut);
}

struct Weights {
    const float *qkv_b, *proj_b, *fc1_b, *fc2_b;
    const float *ln1_g, *ln1_b, *ln2_g, *ln2_b;
    const float *wc;   // pre-converted weights base
};

static void run_blocks(float* x, int N, const Weights& w,
                       float* h, float* qkv, float* att, float* o, float* mlp) {
    int M = Bv * N;
    int rows = Bv * NHh * N;
    const float* wqkv = w.wc + WC_QKV;
    const float* wproj = w.wc + WC_PROJ;
    const float* wfc1 = w.wc + WC_FC1;
    const float* wfc2 = w.wc + WC_FC2;
    for (int l = 0; l < NLAY; l++) {
        ln_k<<<M, 256>>>(x, w.ln1_g + l * Dd, w.ln1_b + l * Dd, h, M);
        // QKV (rounded out)
        gemmB(false, h, wqkv + (long long)l * Dd * 3 * Dd, w.qkv_b + l * 3 * Dd,
              nullptr, qkv, M, 3 * Dd, Dd, Dd, 3 * Dd, 3 * Dd, 0, 1);
        // att = Q K^T / 8 : batched over (b,h)
        gemm(true, qkv, qkv + Dd, nullptr, nullptr, att,
             N, N, DHh, 3 * Dd, 3 * Dd, N, Bv * NHh, NHh,
             (long long)N * 3 * Dd, DHh, (long long)N * 3 * Dd, DHh,
             (long long)NHh * N * N, (long long)N * N, 0.125f, 0, 0, 0);
        softmax_k<<<(rows + 3) / 4, 128>>>(att, N, rows);
        // o = att V (rounded out)
        gemm(false, att, qkv + 2 * Dd, nullptr, nullptr, o,
             N, DHh, N, N, 3 * Dd, Dd, Bv * NHh, NHh,
             (long long)NHh * N * N, (long long)N * N, (long long)N * 3 * Dd, DHh,
             (long long)N * Dd, DHh, 1.f, 0, 0, 1);
        // x = x + o @ proj_w + proj_b
        gemmB(false, o, wproj + (long long)l * Dd * Dd, w.proj_b + l * Dd,
              x, x, M, Dd, Dd, Dd, Dd, Dd, 0, 0);
        ln_k<<<M, 256>>>(x, w.ln2_g + l * Dd, w.ln2_b + l * Dd, h, M);
        // mlp = gelu(h @ fc1 + b1) (rounded out)
        gemmB(false, h, wfc1 + (long long)l * Dd * DFFd, w.fc1_b + l * DFFd,
              nullptr, mlp, M, DFFd, Dd, Dd, DFFd, DFFd, 1, 1);
        // x = x + mlp @ fc2 + b2
        gemmB(false, mlp, wfc2 + (long long)l * DFFd * Dd, w.fc2_b + l * Dd,
              x, x, M, Dd, DFFd, DFFd, Dd, Dd, 0, 0);
    }
}

extern "C" void kernel_launch(void* const* d_in, const int* in_sizes, int n_in,
                              void* d_out, int out_size) {
    (void)in_sizes; (void)n_in; (void)out_size;
    const float* inputs   = (const float*)d_in[0];
    const float* patch_w  = (const float*)d_in[1];
    const float* patch_b  = (const float*)d_in[2];
    const float* cls_tok  = (const float*)d_in[3];
    const float* pos_emb  = (const float*)d_in[4];
    const float* ln1_g    = (const float*)d_in[5];
    const float* ln1_b    = (const float*)d_in[6];
    const float* qkv_w    = (const float*)d_in[7];
    const float* qkv_b    = (const float*)d_in[8];
    const float* proj_w   = (const float*)d_in[9];
    const float* proj_b   = (const float*)d_in[10];
    const float* ln2_g    = (const float*)d_in[11];
    const float* ln2_b    = (const float*)d_in[12];
    const float* fc1_w    = (const float*)d_in[13];
    const float* fc1_b    = (const float*)d_in[14];
    const float* fc2_w    = (const float*)d_in[15];
    const float* fc2_b    = (const float*)d_in[16];
    const float* norm_g   = (const float*)d_in[17];
    const float* norm_b   = (const float*)d_in[18];
    const float* head_w   = (const float*)d_in[19];
    const float* head_b   = (const float*)d_in[20];
    const float* prompt   = (const float*)d_in[21];
    const float* mean     = (const float*)d_in[22];
    const float* variance = (const float*)d_in[23];
    float* out = (float*)d_out;

    float* col  = (float*)getsym(g_col);
    float* img  = (float*)getsym(g_img);
    float* x0   = (float*)getsym(g_x0);
    float* x    = (float*)getsym(g_x);
    float* h    = (float*)getsym(g_h);
    float* qkv  = (float*)getsym(g_qkv);
    float* att  = (float*)getsym(g_att);
    float* o    = (float*)getsym(g_o);
    float* mlp  = (float*)getsym(g_mlp);
    float* qv   = (float*)getsym(g_q);
    float* L    = (float*)getsym(g_L);
    float* LT   = (float*)getsym(g_LT);
    float* logd = (float*)getsym(g_logdet);
    float* logp = (float*)getsym(g_logp);
    int*   topk = (int*)getsym(g_topk);
    float* pool = (float*)getsym(g_pool);
    float* wc   = (float*)getsym(g_wc);

    // dynamic smem opt-in for the big GEMM (72 KB)
    cudaFuncSetAttribute(gemmB_k<0>, cudaFuncAttributeMaxDynamicSharedMemorySize,
                         (int)(2 * GB_STAGE * sizeof(float)));
    cudaFuncSetAttribute(gemmB_k<1>, cudaFuncAttributeMaxDynamicSharedMemorySize,
                         (int)(2 * GB_STAGE * sizeof(float)));

    // ---- weight pre-conversion to tf32 ----
    {
        long long n;
        n = 12LL * 768 * 2304;
        cvt_k<<<(unsigned)((n + 255) / 256), 256>>>(qkv_w, wc + WC_QKV, n);
        n = 12LL * 768 * 768;
        cvt_k<<<(unsigned)((n + 255) / 256), 256>>>(proj_w, wc + WC_PROJ, n);
        n = 12LL * 768 * 3072;
        cvt_k<<<(unsigned)((n + 255) / 256), 256>>>(fc1_w, wc + WC_FC1, n);
        n = 12LL * 3072 * 768;
        cvt_k<<<(unsigned)((n + 255) / 256), 256>>>(fc2_w, wc + WC_FC2, n);
        n = 768LL * 768;
        cvt_k<<<(unsigned)((n + 255) / 256), 256>>>(patch_w, wc + WC_PATCH, n);
    }

    Weights w;
    w.qkv_b = qkv_b; w.proj_b = proj_b; w.fc1_b = fc1_b; w.fc2_b = fc2_b;
    w.ln1_g = ln1_g; w.ln1_b = ln1_b; w.ln2_g = ln2_g; w.ln2_b = ln2_b;
    w.wc = wc;

    // ---- patch embed ----
    {
        long long tot = (long long)Bv * NP * Dd;
        im2col_k<<<(unsigned)((tot + 255) / 256), 256>>>(inputs, col);
        gemmB(true, col, wc + WC_PATCH, patch_b, nullptr, img,
              Bv * NP, Dd, Dd, Dd, Dd, Dd, 0, 0);
        long long tot0 = (long long)Bv * N1 * Dd;
        build_x0_k<<<(unsigned)((tot0 + 255) / 256), 256>>>(img, cls_tok, pos_emb, x0, x);
    }

    // ---- Cholesky of cov = |variance| + I  (blocked NB=64) ----
    {
        long long tot = (long long)Pn * Dd * Dd;
        chol_prep_k<<<(unsigned)((tot + 255) / 256), 256>>>(variance, L, logd);
        for (int kb = 0; kb < Dd / 64; kb++) {
            potrf_k<<<Pn, 256>>>(L, logd, kb);
            int T = Dd - (kb + 1) * 64;
            if (T > 0) {
                trsm_k<<<dim3(Pn, (T + 7) / 8), 256>>>(L, kb);
                long long off = (long long)(kb + 1) * 64;
                const float* pan = L + off * Dd + kb * 64;
                float* trail = L + off * Dd + off;
                gemm(true, pan, pan, nullptr, trail, trail,
                     T, T, 64, Dd, Dd, Dd, Pn, 1,
                     (long long)Dd * Dd, 0, (long long)Dd * Dd, 0,
                     (long long)Dd * Dd, 0, -1.f, 0, 1, 0);
            }
        }
        transpose_k<<<dim3(Dd / 32, Dd / 32, Pn), dim3(32, 8)>>>(L, LT);
    }

    // ---- pass 1 (query) ----
    run_blocks(x, N1, w, h, qkv, att, o, mlp);
    ln_k<<<Bv * N1, 256>>>(x, norm_g, norm_b, h, Bv * N1);
    extract_q_k<<<(Bv * Dd + 255) / 256, 256>>>(h, qv);

    // ---- MVN logprob + top-k ----
    solve_k<<<dim3(Pn, Bv / 8), 256>>>(LT, qv, mean, logd, logp);
    topk_k<<<1, 16>>>(logp, topk);

    // ---- pass 2 (prompted) ----
    {
        long long tot = (long long)Bv * N2 * Dd;
        build_x2_k<<<(unsigned)((tot + 255) / 256), 256>>>(x0, prompt, pos_emb, img, topk, x);
    }
    run_blocks(x, N2, w, h, qkv, att, o, mlp);
    ln_k<<<Bv * N2, 256>>>(x, norm_g, norm_b, h, Bv * N2);
    pool_k<<<(Bv * Dd + 255) / 256, 256>>>(h, pool);

    // ---- head ----
    gemm(false, pool, head_w, head_b, nullptr, out,
         Bv, NCn, Dd, Dd, NCn, NCn, 1, 1, 0, 0, 0, 0, 0, 0, 1.f, 0, 0, 0);
}

// round 6
// speedup vs baseline: 4.4014x; 1.2382x over previous
#include <cuda_runtime.h>
#include <cuda_fp16.h>
#include <math.h>

// ---------------------------------------------------------------------------
// Problem constants
// ---------------------------------------------------------------------------
#define Bv   16
#define Dd   768
#define NLAY 12
#define NHh  12
#define DHh  64
#define DFFd 3072
#define Pn   10
#define Sn   5
#define LPn  5
#define NCn  100
#define NP   196
#define N1   197
#define N2   222          // 1 + S*LP + 196
#define LOG2PI_F 1.8378770664093454f

// ---------------------------------------------------------------------------
// Device scratch (static __device__ arrays; no runtime allocation)
// ---------------------------------------------------------------------------
__device__ __align__(16) __half g_colh[(size_t)Bv * NP * Dd];
__device__ __align__(16) float  g_img [(size_t)Bv * NP * Dd];
__device__ __align__(16) float  g_x0  [(size_t)Bv * N1 * Dd];
__device__ __align__(16) float  g_x   [(size_t)Bv * N2 * Dd];
__device__ __align__(16) __half g_hh  [(size_t)Bv * N2 * Dd];
__device__ __align__(16) __half g_qkvh[(size_t)Bv * N2 * 3 * Dd];
__device__ __align__(16) float  g_att [(size_t)Bv * NHh * N2 * N2];
__device__ __align__(16) __half g_attp[(size_t)Bv * NHh * N2 * N2];
__device__ __align__(16) __half g_oh  [(size_t)Bv * N2 * Dd];
__device__ __align__(16) __half g_mlph[(size_t)Bv * N2 * DFFd];
__device__ __align__(16) float  g_q   [(size_t)Bv * Dd];
__device__ __align__(16) float  g_L   [(size_t)Pn * Dd * Dd];
__device__ __align__(16) float  g_LT  [(size_t)Pn * Dd * Dd];
__device__ float g_logdet[Pn];
__device__ float g_logp[Bv * Pn];
__device__ int   g_topk[Bv * Sn];
__device__ __align__(16) float g_pool[Bv * Dd];

// pre-converted fp16 weights, TRANSPOSED to [N][K]
#define WC_QKV   0LL
#define WC_PROJ  (WC_QKV  + 12LL * 768 * 2304)
#define WC_FC1   (WC_PROJ + 12LL * 768 * 768)
#define WC_FC2   (WC_FC1  + 12LL * 768 * 3072)
#define WC_PATCH (WC_FC2  + 12LL * 3072 * 768)
#define WC_TOTAL (WC_PATCH + 768LL * 768)
__device__ __align__(16) __half g_wch[WC_TOTAL];

// ---------------------------------------------------------------------------
// Helpers
// ---------------------------------------------------------------------------
__device__ __forceinline__ float warp_sum(float v) {
#pragma unroll
    for (int o = 16; o > 0; o >>= 1) v += __shfl_xor_sync(0xffffffffu, v, o);
    return v;
}
__device__ __forceinline__ float warp_max(float v) {
#pragma unroll
    for (int o = 16; o > 0; o >>= 1) v = fmaxf(v, __shfl_xor_sync(0xffffffffu, v, o));
    return v;
}
__device__ __forceinline__ float gelu_f(float x) {
    float x3 = x * x * x;
    return 0.5f * x * (1.f + tanhf(0.7978845608028654f * (x + 0.044715f * x3)));
}
__device__ __forceinline__ float to_tf32(float x) {
    float r;
    asm("cvt.rna.tf32.f32 %0, %1;" : "=f"(r) : "f"(x));
    return r;
}
__device__ __forceinline__ void mma8(float c[4], const unsigned a[4], const unsigned b[2]) {
    asm volatile(
        "mma.sync.aligned.m16n8k8.row.col.f32.tf32.tf32.f32 "
        "{%0,%1,%2,%3}, {%4,%5,%6,%7}, {%8,%9}, {%0,%1,%2,%3};\n"
        : "+f"(c[0]), "+f"(c[1]), "+f"(c[2]), "+f"(c[3])
        : "r"(a[0]), "r"(a[1]), "r"(a[2]), "r"(a[3]), "r"(b[0]), "r"(b[1]));
}
__device__ __forceinline__ void mma16(float c[4], const unsigned a[4], const unsigned b[2]) {
    asm volatile(
        "mma.sync.aligned.m16n8k16.row.col.f32.f16.f16.f32 "
        "{%0,%1,%2,%3}, {%4,%5,%6,%7}, {%8,%9}, {%0,%1,%2,%3};\n"
        : "+f"(c[0]), "+f"(c[1]), "+f"(c[2]), "+f"(c[3])
        : "r"(a[0]), "r"(a[1]), "r"(a[2]), "r"(a[3]), "r"(b[0]), "r"(b[1]));
}
__device__ __forceinline__ void cpa16(void* dst_smem, const void* src, int srcsize) {
    unsigned d = (unsigned)__cvta_generic_to_shared(dst_smem);
    asm volatile("cp.async.ca.shared.global [%0], [%1], 16, %2;\n"
                 :: "r"(d), "l"(src), "r"(srcsize));
}

// weight transpose+convert: src fp32 [K][N] -> dst half [N][K] (per-layer z)
__global__ void tcvtH_k(const float* __restrict__ src, __half* __restrict__ dst,
                        int K, int N) {
    __shared__ float t[32][33];
    long long zo = (long long)blockIdx.z * K * N;
    int k0 = blockIdx.y * 32, n0 = blockIdx.x * 32;
    int x = threadIdx.x, y = threadIdx.y;   // 32 x 8
#pragma unroll
    for (int r = 0; r < 32; r += 8)
        t[y + r][x] = src[zo + (long long)(k0 + y + r) * N + n0 + x];
    __syncthreads();
#pragma unroll
    for (int r = 0; r < 32; r += 8)
        dst[zo + (long long)(n0 + y + r) * K + k0 + x] = __float2half_rn(t[x][y + r]);
}

__global__ void cvtH_k(const float* __restrict__ s, __half* __restrict__ d, long long n) {
    long long i = (long long)blockIdx.x * 256 + threadIdx.x;
    if (i < n) d[i] = __float2half_rn(s[i]);
}

// ---------------------------------------------------------------------------
// Big dense fp16 GEMM: C = act(A[M,K] @ Bt[N,K]^T + bias) + resid
//   128x128 CTA tile, BK=32 (2 x k16 mma steps), 256 threads, 8 warps 64x32,
//   cp.async 2-stage double buffer. A half [M,K] (lda), Bt half [N,K] packed.
//   Requires N % 128 == 0, K % 32 == 0; M may have a tail.
//   Smem rows stride 40 halves -> conflict-free half2 fragment loads.
// ---------------------------------------------------------------------------
#define GH_STAGE_B 20480   // bytes per stage: (128*40 + 128*40) halves * 2

template <int OUTH>
__global__ void __launch_bounds__(256)
gemmH_k(const __half* __restrict__ A, const __half* __restrict__ Bt,
        const float* __restrict__ bias, const float* __restrict__ resid,
        void* __restrict__ Cv, int M, int N, int K, int lda, int ldc, int act) {
    extern __shared__ char smem[];
    int tid = threadIdx.x;
    int m0 = blockIdx.y * 128, n0 = blockIdx.x * 128;
    int warp = tid >> 5, lane = tid & 31;
    int gid = lane >> 2, ctg = lane & 3;
    int wm = (warp & 1) * 64, wn = (warp >> 1) * 32;

    float acc[4][4][4];
#pragma unroll
    for (int mi = 0; mi < 4; mi++)
#pragma unroll
        for (int ni = 0; ni < 4; ni++)
#pragma unroll
            for (int e = 0; e < 4; e++) acc[mi][ni][e] = 0.f;

    auto loadStage = [&](int kt, int st) {
        __half* As = (__half*)(smem + st * GH_STAGE_B);
        __half* Bs = As + 5120;
        int k0 = kt * 32;
#pragma unroll
        for (int i = 0; i < 2; i++) {
            int ch = tid + i * 256;
            int r = ch >> 2, c = ch & 3;
            int gm = m0 + r;
            cpa16(As + r * 40 + c * 8, A + (long long)gm * lda + k0 + c * 8,
                  (gm < M) ? 16 : 0);
            cpa16(Bs + r * 40 + c * 8, Bt + (long long)(n0 + r) * K + k0 + c * 8, 16);
        }
    };

    int KT = K >> 5;
    loadStage(0, 0);
    asm volatile("cp.async.commit_group;\n");
    for (int kt = 0; kt < KT; kt++) {
        if (kt + 1 < KT) loadStage(kt + 1, (kt + 1) & 1);
        asm volatile("cp.async.commit_group;\n");
        asm volatile("cp.async.wait_group 1;\n");
        __syncthreads();
        const __half* As = (const __half*)(smem + (kt & 1) * GH_STAGE_B);
        const __half* Bs = As + 5120;
#pragma unroll
        for (int ks = 0; ks < 2; ks++) {
            int kb = ks * 16 + ctg * 2;
            unsigned a[4][4], b[4][2];
#pragma unroll
            for (int mi = 0; mi < 4; mi++) {
                int mb = wm + mi * 16 + gid;
                a[mi][0] = *(const unsigned*)&As[mb * 40 + kb];
                a[mi][1] = *(const unsigned*)&As[(mb + 8) * 40 + kb];
                a[mi][2] = *(const unsigned*)&As[mb * 40 + kb + 8];
                a[mi][3] = *(const unsigned*)&As[(mb + 8) * 40 + kb + 8];
            }
#pragma unroll
            for (int ni = 0; ni < 4; ni++) {
                int nb = wn + ni * 8 + gid;
                b[ni][0] = *(const unsigned*)&Bs[nb * 40 + kb];
                b[ni][1] = *(const unsigned*)&Bs[nb * 40 + kb + 8];
            }
#pragma unroll
            for (int mi = 0; mi < 4; mi++)
#pragma unroll
                for (int ni = 0; ni < 4; ni++)
                    mma16(acc[mi][ni], a[mi], b[ni]);
        }
        __syncthreads();
    }

#pragma unroll
    for (int mi = 0; mi < 4; mi++) {
#pragma unroll
        for (int ni = 0; ni < 4; ni++) {
            int cc = n0 + wn + ni * 8 + ctg * 2;
#pragma unroll
            for (int e2 = 0; e2 < 2; e2++) {
                int r = m0 + wm + mi * 16 + gid + e2 * 8;
                if (r >= M) continue;
                float v0 = acc[mi][ni][e2 * 2 + 0];
                float v1 = acc[mi][ni][e2 * 2 + 1];
                if (bias) { v0 += bias[cc]; v1 += bias[cc + 1]; }
                if (act == 1) { v0 = gelu_f(v0); v1 = gelu_f(v1); }
                if (resid) {
                    v0 += resid[(long long)r * ldc + cc];
                    v1 += resid[(long long)r * ldc + cc + 1];
                }
                if (OUTH) {
                    __half2* C = (__half2*)((__half*)Cv + (long long)r * ldc + cc);
                    *C = __floats2half2_rn(v0, v1);
                } else {
                    float* C = (float*)Cv + (long long)r * ldc + cc;
                    C[0] = v0; C[1] = v1;
                }
            }
        }
    }
}

// ---------------------------------------------------------------------------
// Small/batched fp16 GEMM (64x64 tile, 128 threads) — attention.
//   TRANSB=1: B [n][k]; TRANSB=0: B [k][n] (transposed on smem fill).
// ---------------------------------------------------------------------------
template <int TRANSB, int OUTH>
__global__ void gemmTH_k(const __half* __restrict__ A, const __half* __restrict__ Bm,
                         void* __restrict__ Cv,
                         int M, int N, int K, int lda, int ldb, int ldc,
                         int inner,
                         long long sAo, long long sAi, long long sBo, long long sBi,
                         long long sCo, long long sCi, float alpha) {
    int z = blockIdx.z;
    int zo = z / inner, zi = z % inner;
    A  += zo * sAo + zi * sAi;
    Bm += zo * sBo + zi * sBi;
    long long co = zo * sCo + zi * sCi;

    __shared__ __half As[64 * 40];
    __shared__ __half Bs[64 * 40];

    int tid = threadIdx.x;
    int m0 = blockIdx.y * 64, n0 = blockIdx.x * 64;
    int warp = tid >> 5, lane = tid & 31;
    int gid = lane >> 2, ctg = lane & 3;
    int wm = (warp >> 1) * 32, wn = (warp & 1) * 32;

    float acc[2][4][4];
#pragma unroll
    for (int mi = 0; mi < 2; mi++)
#pragma unroll
        for (int ni = 0; ni < 4; ni++)
#pragma unroll
            for (int e = 0; e < 4; e++) acc[mi][ni][e] = 0.f;

    const __half HZ = __float2half_rn(0.f);
    for (int k0 = 0; k0 < K; k0 += 32) {
#pragma unroll
        for (int i = 0; i < 16; i++) {
            int l = tid + i * 128;
            int mm = l >> 5, kk = l & 31;
            int gm = m0 + mm, gk = k0 + kk;
            As[mm * 40 + kk] = (gm < M && gk < K) ? A[(long long)gm * lda + gk] : HZ;
        }
#pragma unroll
        for (int i = 0; i < 16; i++) {
            int l = tid + i * 128;
            int nn = l >> 5, kk = l & 31;
            int gn = n0 + nn, gk = k0 + kk;
            if (TRANSB)
                Bs[nn * 40 + kk] = (gn < N && gk < K) ? Bm[(long long)gn * ldb + gk] : HZ;
            else
                Bs[nn * 40 + kk] = (gn < N && gk < K) ? Bm[(long long)gk * ldb + gn] : HZ;
        }
        __syncthreads();
#pragma unroll
        for (int ks = 0; ks < 2; ks++) {
            int kb = ks * 16 + ctg * 2;
            unsigned a[2][4], b[4][2];
#pragma unroll
            for (int mi = 0; mi < 2; mi++) {
                int mb = wm + mi * 16 + gid;
                a[mi][0] = *(const unsigned*)&As[mb * 40 + kb];
                a[mi][1] = *(const unsigned*)&As[(mb + 8) * 40 + kb];
                a[mi][2] = *(const unsigned*)&As[mb * 40 + kb + 8];
                a[mi][3] = *(const unsigned*)&As[(mb + 8) * 40 + kb + 8];
            }
#pragma unroll
            for (int ni = 0; ni < 4; ni++) {
                int nb = wn + ni * 8 + gid;
                b[ni][0] = *(const unsigned*)&Bs[nb * 40 + kb];
                b[ni][1] = *(const unsigned*)&Bs[nb * 40 + kb + 8];
            }
#pragma unroll
            for (int mi = 0; mi < 2; mi++)
#pragma unroll
                for (int ni = 0; ni < 4; ni++)
                    mma16(acc[mi][ni], a[mi], b[ni]);
        }
        __syncthreads();
    }

#pragma unroll
    for (int mi = 0; mi < 2; mi++) {
#pragma unroll
        for (int ni = 0; ni < 4; ni++) {
            int cc = n0 + wn + ni * 8 + ctg * 2;
#pragma unroll
            for (int e = 0; e < 4; e++) {
                int r = m0 + wm + mi * 16 + gid + ((e >> 1) << 3);
                int c1 = cc + (e & 1);
                if (r < M && c1 < N) {
                    float v = alpha * acc[mi][ni][e];
                    if (OUTH)
                        ((__half*)Cv)[co + (long long)r * ldc + c1] = __float2half_rn(v);
                    else
                        ((float*)Cv)[co + (long long)r * ldc + c1] = v;
                }
            }
        }
    }
}

// ---------------------------------------------------------------------------
// tf32 mma GEMM (fp32 I/O) — SYRK trailing update + head
// ---------------------------------------------------------------------------
template <int TRANSB>
__global__ void gemmT_k(const float* __restrict__ A, const float* __restrict__ Bm,
                        const float* __restrict__ bias, const float* __restrict__ resid,
                        float* __restrict__ C,
                        int M, int N, int K, int lda, int ldb, int ldc,
                        int inner,
                        long long sAo, long long sAi, long long sBo, long long sBi,
                        long long sCo, long long sCi,
                        float alpha, int act, int lowerOnly) {
    if (lowerOnly && blockIdx.x > blockIdx.y) return;

    int z = blockIdx.z;
    int zo = z / inner, zi = z % inner;
    A  += zo * sAo + zi * sAi;
    Bm += zo * sBo + zi * sBi;
    long long co = zo * sCo + zi * sCi;
    C += co;
    if (resid) resid += co;

    __shared__ float As[64 * 36];
    __shared__ float Bs[2304];

    int tid = threadIdx.x;
    int m0 = blockIdx.y * 64, n0 = blockIdx.x * 64;
    int warp = tid >> 5, lane = tid & 31;
    int gid = lane >> 2, ctg = lane & 3;
    int wm = (warp >> 1) * 32, wn = (warp & 1) * 32;

    float acc[2][4][4];
#pragma unroll
    for (int mi = 0; mi < 2; mi++)
#pragma unroll
        for (int ni = 0; ni < 4; ni++)
#pragma unroll
            for (int e = 0; e < 4; e++) acc[mi][ni][e] = 0.f;

    for (int k0 = 0; k0 < K; k0 += 32) {
#pragma unroll
        for (int i = 0; i < 16; i++) {
            int l = tid + i * 128;
            int mm = l >> 5, kk = l & 31;
            int gm = m0 + mm, gk = k0 + kk;
            As[mm * 36 + kk] = (gm < M && gk < K) ? to_tf32(A[(long long)gm * lda + gk]) : 0.f;
        }
        if (TRANSB) {
#pragma unroll
            for (int i = 0; i < 16; i++) {
                int l = tid + i * 128;
                int nn = l >> 5, kk = l & 31;
                int gn = n0 + nn, gk = k0 + kk;
                Bs[nn * 36 + kk] = (gn < N && gk < K) ? to_tf32(Bm[(long long)gn * ldb + gk]) : 0.f;
            }
        } else {
#pragma unroll
            for (int i = 0; i < 16; i++) {
                int l = tid + i * 128;
                int kk = l >> 6, nn = l & 63;
                int gk = k0 + kk, gn = n0 + nn;
                Bs[kk * 72 + nn] = (gk < K && gn < N) ? to_tf32(Bm[(long long)gk * ldb + gn]) : 0.f;
            }
        }
        __syncthreads();
#pragma unroll
        for (int ks = 0; ks < 4; ks++) {
            int kr0 = ks * 8 + ctg, kr1 = kr0 + 4;
            unsigned a[2][4], b[4][2];
#pragma unroll
            for (int mi = 0; mi < 2; mi++) {
                int mb = wm + mi * 16 + gid;
                a[mi][0] = __float_as_uint(As[mb * 36 + kr0]);
                a[mi][1] = __float_as_uint(As[(mb + 8) * 36 + kr0]);
                a[mi][2] = __float_as_uint(As[mb * 36 + kr1]);
                a[mi][3] = __float_as_uint(As[(mb + 8) * 36 + kr1]);
            }
#pragma unroll
            for (int ni = 0; ni < 4; ni++) {
                int nb = wn + ni * 8 + gid;
                if (TRANSB) {
                    b[ni][0] = __float_as_uint(Bs[nb * 36 + kr0]);
                    b[ni][1] = __float_as_uint(Bs[nb * 36 + kr1]);
                } else {
                    b[ni][0] = __float_as_uint(Bs[kr0 * 72 + nb]);
                    b[ni][1] = __float_as_uint(Bs[kr1 * 72 + nb]);
                }
            }
#pragma unroll
            for (int mi = 0; mi < 2; mi++)
#pragma unroll
                for (int ni = 0; ni < 4; ni++)
                    mma8(acc[mi][ni], a[mi], b[ni]);
        }
        __syncthreads();
    }

#pragma unroll
    for (int mi = 0; mi < 2; mi++) {
#pragma unroll
        for (int ni = 0; ni < 4; ni++) {
            int col = n0 + wn + ni * 8 + ctg * 2;
#pragma unroll
            for (int e = 0; e < 4; e++) {
                int r = m0 + wm + mi * 16 + gid + ((e >> 1) << 3);
                int cc = col + (e & 1);
                if (r < M && cc < N) {
                    float v = alpha * acc[mi][ni][e];
                    if (bias) v += bias[cc];
                    if (act == 1) v = gelu_f(v);
                    if (resid) v += resid[(long long)r * ldc + cc];
                    C[(long long)r * ldc + cc] = v;
                }
            }
        }
    }
}

// ---------------------------------------------------------------------------
// LayerNorm (256-thread block per row) — fp32 in, fp16 out
// ---------------------------------------------------------------------------
__global__ void ln_k(const float* __restrict__ x, const float* __restrict__ g,
                     const float* __restrict__ b, __half* __restrict__ out, int rows) {
    int row = blockIdx.x;
    if (row >= rows) return;
    const float* xr = x + (size_t)row * Dd;
    __half* yr = out + (size_t)row * Dd;
    int tid = threadIdx.x;
    float v0 = xr[tid], v1 = xr[tid + 256], v2 = xr[tid + 512];
    __shared__ float red[8];
    __shared__ float stat[2];
    float s = warp_sum(v0 + v1 + v2);
    if ((tid & 31) == 0) red[tid >> 5] = s;
    __syncthreads();
    if (tid == 0) {
        float t = 0.f;
#pragma unroll
        for (int i = 0; i < 8; i++) t += red[i];
        stat[0] = t * (1.f / Dd);
    }
    __syncthreads();
    float m = stat[0];
    float d0 = v0 - m, d1 = v1 - m, d2 = v2 - m;
    s = warp_sum(d0 * d0 + d1 * d1 + d2 * d2);
    if ((tid & 31) == 0) red[tid >> 5] = s;
    __syncthreads();
    if (tid == 0) {
        float t = 0.f;
#pragma unroll
        for (int i = 0; i < 8; i++) t += red[i];
        stat[1] = rsqrtf(t * (1.f / Dd) + 1e-6f);
    }
    __syncthreads();
    float inv = stat[1];
    yr[tid]       = __float2half_rn(d0 * inv * g[tid]       + b[tid]);
    yr[tid + 256] = __float2half_rn(d1 * inv * g[tid + 256] + b[tid + 256]);
    yr[tid + 512] = __float2half_rn(d2 * inv * g[tid + 512] + b[tid + 512]);
}

// ---------------------------------------------------------------------------
// Softmax: fp32 logits in, fp16 probs out (warp per row)
// ---------------------------------------------------------------------------
__global__ void softmax_k(const float* __restrict__ att, __half* __restrict__ attp,
                          int n, int rows) {
    int row = blockIdx.x * (blockDim.x >> 5) + (threadIdx.x >> 5);
    if (row >= rows) return;
    int lane = threadIdx.x & 31;
    const float* r = att + (long long)row * n;
    __half* o = attp + (long long)row * n;
    float m = -3e38f;
    for (int i = lane; i < n; i += 32) m = fmaxf(m, r[i]);
    m = warp_max(m);
    float s = 0.f;
    for (int i = lane; i < n; i += 32) s += expf(r[i] - m);
    s = warp_sum(s);
    float inv = 1.f / s;
    for (int i = lane; i < n; i += 32)
        o[i] = __float2half_rn(expf(r[i] - m) * inv);
}

// ---------------------------------------------------------------------------
// Patch embed im2col (fp16 out) + token assembly
// ---------------------------------------------------------------------------
__global__ void im2col_k(const float* __restrict__ in, __half* __restrict__ col) {
    long long idx = (long long)blockIdx.x * 256 + threadIdx.x;
    if (idx >= (long long)Bv * NP * Dd) return;
    int k = (int)(idx % Dd);
    long long bp = idx / Dd;
    int b = (int)(bp / NP), p = (int)(bp % NP);
    int c = k >> 8, rr = k & 255, i = rr >> 4, j = rr & 15;
    int py = p / 14, px = p % 14;
    col[idx] = __float2half_rn(in[((long long)(b * 3 + c) * 224 + py * 16 + i) * 224 + px * 16 + j]);
}

__global__ void build_x0_k(const float* __restrict__ img, const float* __restrict__ cls,
                           const float* __restrict__ pos, float* __restrict__ x0,
                           float* __restrict__ x) {
    long long idx = (long long)blockIdx.x * 256 + threadIdx.x;
    if (idx >= (long long)Bv * N1 * Dd) return;
    int d = (int)(idx % Dd);
    long long bn = idx / Dd;
    int n = (int)(bn % N1), b = (int)(bn / N1);
    float t = (n == 0) ? cls[d] : img[((long long)b * NP + (n - 1)) * Dd + d];
    float v = t + pos[n * Dd + d];
    x0[idx] = v;
    x[idx] = v;
}

__global__ void extract_q_k(const __half* __restrict__ h, float* __restrict__ q) {
    int idx = blockIdx.x * 256 + threadIdx.x;
    if (idx >= Bv * Dd) return;
    int b = idx / Dd, d = idx % Dd;
    q[idx] = __half2float(h[(long long)b * N1 * Dd + d]);
}

__global__ void build_x2_k(const float* __restrict__ x0, const float* __restrict__ prompt,
                           const float* __restrict__ pos, const float* __restrict__ img,
                           const int* __restrict__ topk, float* __restrict__ x) {
    long long idx = (long long)blockIdx.x * 256 + threadIdx.x;
    if (idx >= (long long)Bv * N2 * Dd) return;
    int d = (int)(idx % Dd);
    long long bn = idx / Dd;
    int n = (int)(bn % N2), b = (int)(bn / N2);
    float v;
    if (n == 0) {
        v = x0[(long long)b * N1 * Dd + d];
    } else if (n < 1 + Sn * LPn) {
        int t = n - 1;
        int s = t / LPn, l = t % LPn;
        int pi = topk[b * Sn + s];
        v = prompt[((long long)pi * LPn + l) * Dd + d] + pos[d];
    } else {
        v = img[((long long)b * NP + (n - (1 + Sn * LPn))) * Dd + d];
    }
    x[idx] = v;
}

__global__ void pool_k(const __half* __restrict__ h, float* __restrict__ pool) {
    int idx = blockIdx.x * 256 + threadIdx.x;
    if (idx >= Bv * Dd) return;
    int b = idx / Dd, d = idx % Dd;
    float s = 0.f;
#pragma unroll
    for (int t = 1; t <= Sn * LPn; t++)
        s += __half2float(h[((long long)b * N2 + t) * Dd + d]);
    pool[idx] = s * (1.f / (Sn * LPn));
}

// ---------------------------------------------------------------------------
// Cholesky (blocked NB=64)
// ---------------------------------------------------------------------------
__global__ void chol_prep_k(const float* __restrict__ var, float* __restrict__ L,
                            float* __restrict__ logdet) {
    long long idx = (long long)blockIdx.x * 256 + threadIdx.x;
    if (idx >= (long long)Pn * Dd * Dd) return;
    int j = (int)(idx % Dd);
    long long pi = idx / Dd;
    int i = (int)(pi % Dd);
    int p = (int)(pi / Dd);
    L[idx] = fabsf(var[idx]) + (i == j ? 1.f : 0.f);
    if (i == 0 && j == 0) logdet[p] = 0.f;
}

__global__ void potrf_k(float* __restrict__ L, float* __restrict__ logdet, int kb) {
    int p = blockIdx.x;
    float* A = L + (long long)p * Dd * Dd + (long long)kb * 64 * Dd + kb * 64;
    __shared__ float s[64][65];
    int tid = threadIdx.x;
    for (int l = tid; l < 4096; l += 256) s[l >> 6][l & 63] = A[(l >> 6) * Dd + (l & 63)];
    __syncthreads();
    for (int k = 0; k < 64; k++) {
        if (tid == 0) s[k][k] = sqrtf(s[k][k]);
        __syncthreads();
        for (int i = k + 1 + tid; i < 64; i += 256) s[i][k] /= s[k][k];
        __syncthreads();
        for (int l = tid; l < 4096; l += 256) {
            int i = l >> 6, j = l & 63;
            if (i > k && j > k && j <= i) s[i][j] -= s[i][k] * s[j][k];
        }
        __syncthreads();
    }
    for (int l = tid; l < 4096; l += 256) A[(l >> 6) * Dd + (l & 63)] = s[l >> 6][l & 63];
    if (tid < 64) atomicAdd(&logdet[p], 2.f * logf(s[tid][tid]));
}

__global__ void trsm_k(float* __restrict__ L, int kb) {
    int p = blockIdx.x;
    int off = (kb + 1) * 64;
    __shared__ float s[64][65];
    int tid = threadIdx.x;
    float* Ldiag = L + (long long)p * Dd * Dd + (long long)kb * 64 * Dd + kb * 64;
    for (int l = tid; l < 4096; l += 256) s[l >> 6][l & 63] = Ldiag[(l >> 6) * Dd + (l & 63)];
    __syncthreads();
    int wid = tid >> 5, lane = tid & 31;
    int row = off + blockIdx.y * 8 + wid;
    if (row >= Dd) return;
    float* a = L + (long long)p * Dd * Dd + (long long)row * Dd + kb * 64;
    float a0 = a[lane], a1 = a[lane + 32];
#pragma unroll
    for (int j = 0; j < 64; j++) {
        float aj = (j < 32) ? __shfl_sync(0xffffffffu, a0, j)
                            : __shfl_sync(0xffffffffu, a1, j - 32);
        float y = aj / s[j][j];
        if (lane == (j & 31)) {
            if (j < 32) a0 = y; else a1 = y;
        }
        if (lane > j) a0 -= s[lane][j] * y;
        if (lane + 32 > j) a1 -= s[lane + 32][j] * y;
    }
    a[lane] = a0;
    a[lane + 32] = a1;
}

__global__ void transpose_k(const float* __restrict__ L, float* __restrict__ LT) {
    __shared__ float t[32][33];
    int p = blockIdx.z;
    int i0 = blockIdx.y * 32, j0 = blockIdx.x * 32;
    int x = threadIdx.x, y = threadIdx.y;    // 32 x 8
#pragma unroll
    for (int r = 0; r < 32; r += 8)
        t[y + r][x] = L[(long long)p * Dd * Dd + (long long)(i0 + y + r) * Dd + j0 + x];
    __syncthreads();
#pragma unroll
    for (int r = 0; r < 32; r += 8)
        LT[(long long)p * Dd * Dd + (long long)(j0 + y + r) * Dd + i0 + x] = t[x][y + r];
}

__global__ void solve_k(const float* __restrict__ LT, const float* __restrict__ q,
                        const float* __restrict__ mean, const float* __restrict__ logdet,
                        float* __restrict__ logp) {
    int p = blockIdx.x;
    int wid = threadIdx.x >> 5, lane = threadIdx.x & 31;
    int b = blockIdx.y * 8 + wid;
    __shared__ float rs[8][Dd];
    float* r = rs[wid];
    for (int i = lane; i < Dd; i += 32) r[i] = q[b * Dd + i] - mean[p * Dd + i];
    const float* lt = LT + (long long)p * Dd * Dd;
    float quad = 0.f;
    for (int j = 0; j < Dd; j++) {
        __syncwarp();
        float y = r[j] / lt[(long long)j * Dd + j];
        if (lane == 0) quad += y * y;
        for (int i = j + 1 + lane; i < Dd; i += 32) r[i] -= lt[(long long)j * Dd + i] * y;
    }
    if (lane == 0)
        logp[b * Pn + p] = -0.5f * ((float)Dd * LOG2PI_F + logdet[p] + quad);
}

__global__ void topk_k(const float* __restrict__ logp, int* __restrict__ topk) {
    int b = threadIdx.x;
    if (b >= Bv) return;
    float v[Pn];
#pragma unroll
    for (int p = 0; p < Pn; p++) v[p] = logp[b * Pn + p];
#pragma unroll
    for (int s = 0; s < Sn; s++) {
        float best = -3e38f;
        int bi = 0;
#pragma unroll
        for (int p = 0; p < Pn; p++) {
            if (v[p] > best) { best = v[p]; bi = p; }
        }
        topk[b * Sn + s] = bi;
        v[bi] = -3e38f;
    }
}

// ---------------------------------------------------------------------------
// Host side
// ---------------------------------------------------------------------------
static void* getsym(const void* symbol) {
    void* p = nullptr;
    cudaGetSymbolAddress(&p, symbol);
    return p;
}

static void gemmH(const __half* A, const __half* Bt, const float* bias,
                  const float* resid, void* C, int M, int N, int K,
                  int lda, int ldc, int act, int outh) {
    dim3 grid(N / 128, (M + 127) / 128);
    size_t smem = 2 * GH_STAGE_B;
    if (outh)
        gemmH_k<1><<<grid, 256, smem>>>(A, Bt, bias, resid, C, M, N, K, lda, ldc, act);
    else
        gemmH_k<0><<<grid, 256, smem>>>(A, Bt, bias, resid, C, M, N, K, lda, ldc, act);
}

static void gemmT(bool transB, const float* A, const float* Bm, const float* bias,
                  const float* resid, float* C, int M, int N, int K,
                  int lda, int ldb, int ldc, int batch, int inner,
                  long long sAo, long long sAi, long long sBo, long long sBi,
                  long long sCo, long long sCi, float alpha, int act, int lowerOnly) {
    dim3 grid((N + 63) / 64, (M + 63) / 64, batch);
    if (transB)
        gemmT_k<1><<<grid, 128>>>(A, Bm, bias, resid, C, M, N, K, lda, ldb, ldc, inner,
                                  sAo, sAi, sBo, sBi, sCo, sCi, alpha, act, lowerOnly);
    else
        gemmT_k<0><<<grid, 128>>>(A, Bm, bias, resid, C, M, N, K, lda, ldb, ldc, inner,
                                  sAo, sAi, sBo, sBi, sCo, sCi, alpha, act, lowerOnly);
}

struct Weights {
    const float *qkv_b, *proj_b, *fc1_b, *fc2_b;
    const float *ln1_g, *ln1_b, *ln2_g, *ln2_b;
    const __half *wc;
};

static void run_blocks(float* x, int N, const Weights& w,
                       __half* h, __half* qkv, float* att, __half* attp,
                       __half* o, __half* mlp) {
    int M = Bv * N;
    int rows = Bv * NHh * N;
    const __half* wqkv = w.wc + WC_QKV;
    const __half* wproj = w.wc + WC_PROJ;
    const __half* wfc1 = w.wc + WC_FC1;
    const __half* wfc2 = w.wc + WC_FC2;
    for (int l = 0; l < NLAY; l++) {
        ln_k<<<M, 256>>>(x, w.ln1_g + l * Dd, w.ln1_b + l * Dd, h, M);
        // QKV -> half
        gemmH(h, wqkv + (long long)l * Dd * 3 * Dd, w.qkv_b + l * 3 * Dd,
              nullptr, qkv, M, 3 * Dd, Dd, Dd, 3 * Dd, 0, 1);
        // att = Q K^T / 8 (fp32 logits), batched over (b,h)
        {
            dim3 grid((N + 63) / 64, (N + 63) / 64, Bv * NHh);
            gemmTH_k<1, 0><<<grid, 128>>>(qkv, qkv + Dd, att,
                N, N, DHh, 3 * Dd, 3 * Dd, N, NHh,
                (long long)N * 3 * Dd, DHh, (long long)N * 3 * Dd, DHh,
                (long long)NHh * N * N, (long long)N * N, 0.125f);
        }
        softmax_k<<<(rows + 3) / 4, 128>>>(att, attp, N, rows);
        // o = attp @ V  -> half
        {
            dim3 grid(1, (N + 63) / 64, Bv * NHh);
            gemmTH_k<0, 1><<<grid, 128>>>(attp, qkv + 2 * Dd, o,
                N, DHh, N, N, 3 * Dd, Dd, NHh,
                (long long)NHh * N * N, (long long)N * N,
                (long long)N * 3 * Dd, DHh,
                (long long)N * Dd, DHh, 1.f);
        }
        // x = x + o @ proj_w + proj_b
        gemmH(o, wproj + (long long)l * Dd * Dd, w.proj_b + l * Dd,
              x, x, M, Dd, Dd, Dd, Dd, 0, 0);
        ln_k<<<M, 256>>>(x, w.ln2_g + l * Dd, w.ln2_b + l * Dd, h, M);
        // mlp = gelu(h @ fc1 + b1) -> half
        gemmH(h, wfc1 + (long long)l * Dd * DFFd, w.fc1_b + l * DFFd,
              nullptr, mlp, M, DFFd, Dd, Dd, DFFd, 1, 1);
        // x = x + mlp @ fc2 + b2
        gemmH(mlp, wfc2 + (long long)l * DFFd * Dd, w.fc2_b + l * Dd,
              x, x, M, Dd, DFFd, DFFd, Dd, 0, 0);
    }
}

extern "C" void kernel_launch(void* const* d_in, const int* in_sizes, int n_in,
                              void* d_out, int out_size) {
    (void)in_sizes; (void)n_in; (void)out_size;
    const float* inputs   = (const float*)d_in[0];
    const float* patch_w  = (const float*)d_in[1];
    const float* patch_b  = (const float*)d_in[2];
    const float* cls_tok  = (const float*)d_in[3];
    const float* pos_emb  = (const float*)d_in[4];
    const float* ln1_g    = (const float*)d_in[5];
    const float* ln1_b    = (const float*)d_in[6];
    const float* qkv_w    = (const float*)d_in[7];
    const float* qkv_b    = (const float*)d_in[8];
    const float* proj_w   = (const float*)d_in[9];
    const float* proj_b   = (const float*)d_in[10];
    const float* ln2_g    = (const float*)d_in[11];
    const float* ln2_b    = (const float*)d_in[12];
    const float* fc1_w    = (const float*)d_in[13];
    const float* fc1_b    = (const float*)d_in[14];
    const float* fc2_w    = (const float*)d_in[15];
    const float* fc2_b    = (const float*)d_in[16];
    const float* norm_g   = (const float*)d_in[17];
    const float* norm_b   = (const float*)d_in[18];
    const float* head_w   = (const float*)d_in[19];
    const float* head_b   = (const float*)d_in[20];
    const float* prompt   = (const float*)d_in[21];
    const float* mean     = (const float*)d_in[22];
    const float* variance = (const float*)d_in[23];
    float* out = (float*)d_out;

    __half* col  = (__half*)getsym(g_colh);
    float*  img  = (float*)getsym(g_img);
    float*  x0   = (float*)getsym(g_x0);
    float*  x    = (float*)getsym(g_x);
    __half* h    = (__half*)getsym(g_hh);
    __half* qkv  = (__half*)getsym(g_qkvh);
    float*  att  = (float*)getsym(g_att);
    __half* attp = (__half*)getsym(g_attp);
    __half* o    = (__half*)getsym(g_oh);
    __half* mlp  = (__half*)getsym(g_mlph);
    float*  qv   = (float*)getsym(g_q);
    float*  L    = (float*)getsym(g_L);
    float*  LT   = (float*)getsym(g_LT);
    float*  logd = (float*)getsym(g_logdet);
    float*  logp = (float*)getsym(g_logp);
    int*    topk = (int*)getsym(g_topk);
    float*  pool = (float*)getsym(g_pool);
    __half* wc   = (__half*)getsym(g_wch);

    cudaFuncSetAttribute(gemmH_k<0>, cudaFuncAttributeMaxDynamicSharedMemorySize,
                         (int)(2 * GH_STAGE_B));
    cudaFuncSetAttribute(gemmH_k<1>, cudaFuncAttributeMaxDynamicSharedMemorySize,
                         (int)(2 * GH_STAGE_B));

    // ---- weight pre-conversion: transpose [K][N] -> half [N][K] ----
    {
        dim3 blk(32, 8);
        tcvtH_k<<<dim3(2304 / 32, 768 / 32, 12), blk>>>(qkv_w, wc + WC_QKV, 768, 2304);
        tcvtH_k<<<dim3(768 / 32, 768 / 32, 12), blk>>>(proj_w, wc + WC_PROJ, 768, 768);
        tcvtH_k<<<dim3(3072 / 32, 768 / 32, 12), blk>>>(fc1_w, wc + WC_FC1, 768, 3072);
        tcvtH_k<<<dim3(768 / 32, 3072 / 32, 12), blk>>>(fc2_w, wc + WC_FC2, 3072, 768);
        long long n = 768LL * 768;   // patch_w already [N][K]
        cvtH_k<<<(unsigned)((n + 255) / 256), 256>>>(patch_w, wc + WC_PATCH, n);
    }

    Weights w;
    w.qkv_b = qkv_b; w.proj_b = proj_b; w.fc1_b = fc1_b; w.fc2_b = fc2_b;
    w.ln1_g = ln1_g; w.ln1_b = ln1_b; w.ln2_g = ln2_g; w.ln2_b = ln2_b;
    w.wc = wc;

    // ---- patch embed ----
    {
        long long tot = (long long)Bv * NP * Dd;
        im2col_k<<<(unsigned)((tot + 255) / 256), 256>>>(inputs, col);
        gemmH(col, wc + WC_PATCH, patch_b, nullptr, img,
              Bv * NP, Dd, Dd, Dd, Dd, 0, 0);
        long long tot0 = (long long)Bv * N1 * Dd;
        build_x0_k<<<(unsigned)((tot0 + 255) / 256), 256>>>(img, cls_tok, pos_emb, x0, x);
    }

    // ---- Cholesky of cov = |variance| + I  (blocked NB=64) ----
    {
        long long tot = (long long)Pn * Dd * Dd;
        chol_prep_k<<<(unsigned)((tot + 255) / 256), 256>>>(variance, L, logd);
        for (int kb = 0; kb < Dd / 64; kb++) {
            potrf_k<<<Pn, 256>>>(L, logd, kb);
            int T = Dd - (kb + 1) * 64;
            if (T > 0) {
                trsm_k<<<dim3(Pn, (T + 7) / 8), 256>>>(L, kb);
                long long off = (long long)(kb + 1) * 64;
                const float* pan = L + off * Dd + kb * 64;
                float* trail = L + off * Dd + off;
                gemmT(true, pan, pan, nullptr, trail, trail,
                      T, T, 64, Dd, Dd, Dd, Pn, 1,
                      (long long)Dd * Dd, 0, (long long)Dd * Dd, 0,
                      (long long)Dd * Dd, 0, -1.f, 0, 1);
            }
        }
        transpose_k<<<dim3(Dd / 32, Dd / 32, Pn), dim3(32, 8)>>>(L, LT);
    }

    // ---- pass 1 (query) ----
    run_blocks(x, N1, w, h, qkv, att, attp, o, mlp);
    ln_k<<<Bv * N1, 256>>>(x, norm_g, norm_b, h, Bv * N1);
    extract_q_k<<<(Bv * Dd + 255) / 256, 256>>>(h, qv);

    // ---- MVN logprob + top-k ----
    solve_k<<<dim3(Pn, Bv / 8), 256>>>(LT, qv, mean, logd, logp);
    topk_k<<<1, 16>>>(logp, topk);

    // ---- pass 2 (prompted) ----
    {
        long long tot = (long long)Bv * N2 * Dd;
        build_x2_k<<<(unsigned)((tot + 255) / 256), 256>>>(x0, prompt, pos_emb, img, topk, x);
    }
    run_blocks(x, N2, w, h, qkv, att, attp, o, mlp);
    ln_k<<<Bv * N2, 256>>>(x, norm_g, norm_b, h, Bv * N2);
    pool_k<<<(Bv * Dd + 255) / 256, 256>>>(h, pool);

    // ---- head ----
    gemmT(false, pool, head_w, head_b, nullptr, out,
          Bv, NCn, Dd, Dd, NCn, NCn, 1, 1, 0, 0, 0, 0, 0, 0, 1.f, 0, 0);
}

// round 7
// speedup vs baseline: 5.1329x; 1.1662x over previous
#include <cuda_runtime.h>
#include <cuda_fp16.h>
#include <math.h>

// ---------------------------------------------------------------------------
// Problem constants
// ---------------------------------------------------------------------------
#define Bv   16
#define Dd   768
#define NLAY 12
#define NHh  12
#define DHh  64
#define DFFd 3072
#define Pn   10
#define Sn   5
#define LPn  5
#define NCn  100
#define NP   196
#define N1   197
#define N2   222          // 1 + S*LP + 196
#define LOG2PI_F 1.8378770664093454f

// ---------------------------------------------------------------------------
// Device scratch (static __device__ arrays; no runtime allocation)
// ---------------------------------------------------------------------------
__device__ __align__(16) __half g_colh[(size_t)Bv * NP * Dd];
__device__ __align__(16) float  g_img [(size_t)Bv * NP * Dd];
__device__ __align__(16) float  g_x0  [(size_t)Bv * N1 * Dd];
__device__ __align__(16) float  g_x   [(size_t)Bv * N2 * Dd];
__device__ __align__(16) __half g_hh  [(size_t)Bv * N2 * Dd];
__device__ __align__(16) __half g_qkvh[(size_t)Bv * N2 * 3 * Dd];
__device__ __align__(16) float  g_att [(size_t)Bv * NHh * N2 * N2];
__device__ __align__(16) __half g_attp[(size_t)Bv * NHh * N2 * N2];
__device__ __align__(16) __half g_vth [(size_t)Bv * NHh * DHh * N2];
__device__ __align__(16) __half g_oh  [(size_t)Bv * N2 * Dd];
__device__ __align__(16) __half g_mlph[(size_t)Bv * N2 * DFFd];
__device__ __align__(16) float  g_q   [(size_t)Bv * Dd];
__device__ __align__(16) float  g_L   [(size_t)Pn * Dd * Dd];
__device__ __align__(16) float  g_LT  [(size_t)Pn * Dd * Dd];
__device__ float g_logdet[Pn];
__device__ float g_logp[Bv * Pn];
__device__ int   g_topk[Bv * Sn];
__device__ __align__(16) float g_pool[Bv * Dd];

// pre-converted fp16 weights, TRANSPOSED to [N][K]
#define WC_QKV   0LL
#define WC_PROJ  (WC_QKV  + 12LL * 768 * 2304)
#define WC_FC1   (WC_PROJ + 12LL * 768 * 768)
#define WC_FC2   (WC_FC1  + 12LL * 768 * 3072)
#define WC_PATCH (WC_FC2  + 12LL * 3072 * 768)
#define WC_TOTAL (WC_PATCH + 768LL * 768)
__device__ __align__(16) __half g_wch[WC_TOTAL];

// ---------------------------------------------------------------------------
// Helpers
// ---------------------------------------------------------------------------
__device__ __forceinline__ float warp_sum(float v) {
#pragma unroll
    for (int o = 16; o > 0; o >>= 1) v += __shfl_xor_sync(0xffffffffu, v, o);
    return v;
}
__device__ __forceinline__ float warp_max(float v) {
#pragma unroll
    for (int o = 16; o > 0; o >>= 1) v = fmaxf(v, __shfl_xor_sync(0xffffffffu, v, o));
    return v;
}
__device__ __forceinline__ float gelu_f(float x) {
    float x3 = x * x * x;
    return 0.5f * x * (1.f + tanhf(0.7978845608028654f * (x + 0.044715f * x3)));
}
__device__ __forceinline__ float to_tf32(float x) {
    float r;
    asm("cvt.rna.tf32.f32 %0, %1;" : "=f"(r) : "f"(x));
    return r;
}
__device__ __forceinline__ void mma8(float c[4], const unsigned a[4], const unsigned b[2]) {
    asm volatile(
        "mma.sync.aligned.m16n8k8.row.col.f32.tf32.tf32.f32 "
        "{%0,%1,%2,%3}, {%4,%5,%6,%7}, {%8,%9}, {%0,%1,%2,%3};\n"
        : "+f"(c[0]), "+f"(c[1]), "+f"(c[2]), "+f"(c[3])
        : "r"(a[0]), "r"(a[1]), "r"(a[2]), "r"(a[3]), "r"(b[0]), "r"(b[1]));
}
__device__ __forceinline__ void mma16(float c[4], const unsigned a[4], const unsigned b[2]) {
    asm volatile(
        "mma.sync.aligned.m16n8k16.row.col.f32.f16.f16.f32 "
        "{%0,%1,%2,%3}, {%4,%5,%6,%7}, {%8,%9}, {%0,%1,%2,%3};\n"
        : "+f"(c[0]), "+f"(c[1]), "+f"(c[2]), "+f"(c[3])
        : "r"(a[0]), "r"(a[1]), "r"(a[2]), "r"(a[3]), "r"(b[0]), "r"(b[1]));
}
__device__ __forceinline__ void cpa16(void* dst_smem, const void* src, int srcsize) {
    unsigned d = (unsigned)__cvta_generic_to_shared(dst_smem);
    asm volatile("cp.async.ca.shared.global [%0], [%1], 16, %2;\n"
                 :: "r"(d), "l"(src), "r"(srcsize));
}

// weight transpose+convert: src fp32 [K][N] -> dst half [N][K] (per-layer z)
__global__ void tcvtH_k(const float* __restrict__ src, __half* __restrict__ dst,
                        int K, int N) {
    __shared__ float t[32][33];
    long long zo = (long long)blockIdx.z * K * N;
    int k0 = blockIdx.y * 32, n0 = blockIdx.x * 32;
    int x = threadIdx.x, y = threadIdx.y;   // 32 x 8
#pragma unroll
    for (int r = 0; r < 32; r += 8)
        t[y + r][x] = src[zo + (long long)(k0 + y + r) * N + n0 + x];
    __syncthreads();
#pragma unroll
    for (int r = 0; r < 32; r += 8)
        dst[zo + (long long)(n0 + y + r) * K + k0 + x] = __float2half_rn(t[x][y + r]);
}

__global__ void cvtH_k(const float* __restrict__ s, __half* __restrict__ d, long long n) {
    long long i = (long long)blockIdx.x * 256 + threadIdx.x;
    if (i < n) d[i] = __float2half_rn(s[i]);
}

// ---------------------------------------------------------------------------
// Big dense fp16 GEMM: C = act(A[M,K] @ Bt[N,K]^T + bias) + resid
//   CTA tile BM x 128, BK=64 (4 x k16 mma steps), 256 threads (8 warps 2x4,
//   warp tile (BM/2)x32), cp.async 2-stage double buffer.
//   Requires N % 128 == 0, K % 64 == 0; M may have a tail.
//   Smem rows stride 72 halves -> conflict-free half2 fragment loads.
// ---------------------------------------------------------------------------
#define GH_STG(BM) (((BM) + 128) * 144)   // bytes per stage

template <int OUTH, int BM>
__global__ void __launch_bounds__(256)
gemmH_k(const __half* __restrict__ A, const __half* __restrict__ Bt,
        const float* __restrict__ bias, const float* __restrict__ resid,
        void* __restrict__ Cv, int M, int N, int K, int lda, int ldc, int act) {
    extern __shared__ char smem[];
    constexpr int MI = BM / 32;
    int tid = threadIdx.x;
    int m0 = blockIdx.y * BM, n0 = blockIdx.x * 128;
    int warp = tid >> 5, lane = tid & 31;
    int gid = lane >> 2, ctg = lane & 3;
    int wm = (warp & 1) * (BM / 2), wn = (warp >> 1) * 32;

    float acc[MI][4][4];
#pragma unroll
    for (int mi = 0; mi < MI; mi++)
#pragma unroll
        for (int ni = 0; ni < 4; ni++)
#pragma unroll
            for (int e = 0; e < 4; e++) acc[mi][ni][e] = 0.f;

    auto loadStage = [&](int kt, int st) {
        __half* As = (__half*)(smem + st * GH_STG(BM));
        __half* Bs = As + BM * 72;
        int k0 = kt * 64;
#pragma unroll
        for (int i = 0; i < BM / 32; i++) {
            int ch = tid + i * 256;
            int r = ch >> 3, c = ch & 7;
            int gm = m0 + r;
            cpa16(As + r * 72 + c * 8, A + (long long)gm * lda + k0 + c * 8,
                  (gm < M) ? 16 : 0);
        }
#pragma unroll
        for (int i = 0; i < 4; i++) {
            int ch = tid + i * 256;
            int r = ch >> 3, c = ch & 7;
            cpa16(Bs + r * 72 + c * 8, Bt + (long long)(n0 + r) * K + k0 + c * 8, 16);
        }
    };

    int KT = K >> 6;
    loadStage(0, 0);
    asm volatile("cp.async.commit_group;\n");
    for (int kt = 0; kt < KT; kt++) {
        if (kt + 1 < KT) loadStage(kt + 1, (kt + 1) & 1);
        asm volatile("cp.async.commit_group;\n");
        asm volatile("cp.async.wait_group 1;\n");
        __syncthreads();
        const __half* As = (const __half*)(smem + (kt & 1) * GH_STG(BM));
        const __half* Bs = As + BM * 72;
#pragma unroll
        for (int ks = 0; ks < 4; ks++) {
            int kb = ks * 16 + ctg * 2;
            unsigned a[MI][4], b[4][2];
#pragma unroll
            for (int mi = 0; mi < MI; mi++) {
                int mb = wm + mi * 16 + gid;
                a[mi][0] = *(const unsigned*)&As[mb * 72 + kb];
                a[mi][1] = *(const unsigned*)&As[(mb + 8) * 72 + kb];
                a[mi][2] = *(const unsigned*)&As[mb * 72 + kb + 8];
                a[mi][3] = *(const unsigned*)&As[(mb + 8) * 72 + kb + 8];
            }
#pragma unroll
            for (int ni = 0; ni < 4; ni++) {
                int nb = wn + ni * 8 + gid;
                b[ni][0] = *(const unsigned*)&Bs[nb * 72 + kb];
                b[ni][1] = *(const unsigned*)&Bs[nb * 72 + kb + 8];
            }
#pragma unroll
            for (int mi = 0; mi < MI; mi++)
#pragma unroll
                for (int ni = 0; ni < 4; ni++)
                    mma16(acc[mi][ni], a[mi], b[ni]);
        }
        __syncthreads();
    }

#pragma unroll
    for (int mi = 0; mi < MI; mi++) {
#pragma unroll
        for (int ni = 0; ni < 4; ni++) {
            int cc = n0 + wn + ni * 8 + ctg * 2;
#pragma unroll
            for (int e2 = 0; e2 < 2; e2++) {
                int r = m0 + wm + mi * 16 + gid + e2 * 8;
                if (r >= M) continue;
                float v0 = acc[mi][ni][e2 * 2 + 0];
                float v1 = acc[mi][ni][e2 * 2 + 1];
                if (bias) { v0 += bias[cc]; v1 += bias[cc + 1]; }
                if (act == 1) { v0 = gelu_f(v0); v1 = gelu_f(v1); }
                if (resid) {
                    v0 += resid[(long long)r * ldc + cc];
                    v1 += resid[(long long)r * ldc + cc + 1];
                }
                if (OUTH) {
                    __half2* C = (__half2*)((__half*)Cv + (long long)r * ldc + cc);
                    *C = __floats2half2_rn(v0, v1);
                } else {
                    float* C = (float*)Cv + (long long)r * ldc + cc;
                    C[0] = v0; C[1] = v1;
                }
            }
        }
    }
}

// ---------------------------------------------------------------------------
// Small/batched fp16 GEMM (64x64 tile, 128 threads) — attention.
//   B is always [n][k] row-major (TRANSB layout); fills fully coalesced.
// ---------------------------------------------------------------------------
template <int OUTH>
__global__ void gemmTH_k(const __half* __restrict__ A, const __half* __restrict__ Bm,
                         void* __restrict__ Cv,
                         int M, int N, int K, int lda, int ldb, int ldc,
                         int inner,
                         long long sAo, long long sAi, long long sBo, long long sBi,
                         long long sCo, long long sCi, float alpha) {
    int z = blockIdx.z;
    int zo = z / inner, zi = z % inner;
    A  += zo * sAo + zi * sAi;
    Bm += zo * sBo + zi * sBi;
    long long co = zo * sCo + zi * sCi;

    __shared__ __half As[64 * 40];
    __shared__ __half Bs[64 * 40];

    int tid = threadIdx.x;
    int m0 = blockIdx.y * 64, n0 = blockIdx.x * 64;
    int warp = tid >> 5, lane = tid & 31;
    int gid = lane >> 2, ctg = lane & 3;
    int wm = (warp >> 1) * 32, wn = (warp & 1) * 32;

    float acc[2][4][4];
#pragma unroll
    for (int mi = 0; mi < 2; mi++)
#pragma unroll
        for (int ni = 0; ni < 4; ni++)
#pragma unroll
            for (int e = 0; e < 4; e++) acc[mi][ni][e] = 0.f;

    const __half HZ = __float2half_rn(0.f);
    for (int k0 = 0; k0 < K; k0 += 32) {
#pragma unroll
        for (int i = 0; i < 16; i++) {
            int l = tid + i * 128;
            int mm = l >> 5, kk = l & 31;
            int gm = m0 + mm, gk = k0 + kk;
            As[mm * 40 + kk] = (gm < M && gk < K) ? A[(long long)gm * lda + gk] : HZ;
        }
#pragma unroll
        for (int i = 0; i < 16; i++) {
            int l = tid + i * 128;
            int nn = l >> 5, kk = l & 31;
            int gn = n0 + nn, gk = k0 + kk;
            Bs[nn * 40 + kk] = (gn < N && gk < K) ? Bm[(long long)gn * ldb + gk] : HZ;
        }
        __syncthreads();
#pragma unroll
        for (int ks = 0; ks < 2; ks++) {
            int kb = ks * 16 + ctg * 2;
            unsigned a[2][4], b[4][2];
#pragma unroll
            for (int mi = 0; mi < 2; mi++) {
                int mb = wm + mi * 16 + gid;
                a[mi][0] = *(const unsigned*)&As[mb * 40 + kb];
                a[mi][1] = *(const unsigned*)&As[(mb + 8) * 40 + kb];
                a[mi][2] = *(const unsigned*)&As[mb * 40 + kb + 8];
                a[mi][3] = *(const unsigned*)&As[(mb + 8) * 40 + kb + 8];
            }
#pragma unroll
            for (int ni = 0; ni < 4; ni++) {
                int nb = wn + ni * 8 + gid;
                b[ni][0] = *(const unsigned*)&Bs[nb * 40 + kb];
                b[ni][1] = *(const unsigned*)&Bs[nb * 40 + kb + 8];
            }
#pragma unroll
            for (int mi = 0; mi < 2; mi++)
#pragma unroll
                for (int ni = 0; ni < 4; ni++)
                    mma16(acc[mi][ni], a[mi], b[ni]);
        }
        __syncthreads();
    }

#pragma unroll
    for (int mi = 0; mi < 2; mi++) {
#pragma unroll
        for (int ni = 0; ni < 4; ni++) {
            int cc = n0 + wn + ni * 8 + ctg * 2;
#pragma unroll
            for (int e = 0; e < 4; e++) {
                int r = m0 + wm + mi * 16 + gid + ((e >> 1) << 3);
                int c1 = cc + (e & 1);
                if (r < M && c1 < N) {
                    float v = alpha * acc[mi][ni][e];
                    if (OUTH)
                        ((__half*)Cv)[co + (long long)r * ldc + c1] = __float2half_rn(v);
                    else
                        ((float*)Cv)[co + (long long)r * ldc + c1] = v;
                }
            }
        }
    }
}

// V transpose: qkv [b, n, 2D + h*64 + d] -> vt [b*H + h][d][n]
__global__ void vt_k(const __half* __restrict__ qkv, __half* __restrict__ vt, int N) {
    __shared__ __half t[32][33];
    int z = blockIdx.z;
    int b = z / NHh, hh = z % NHh;
    int n0 = blockIdx.x * 32, d0 = blockIdx.y * 32;
    int x = threadIdx.x, y = threadIdx.y;   // 32 x 8
#pragma unroll
    for (int r = 0; r < 32; r += 8) {
        int n = n0 + y + r;
        t[y + r][x] = (n < N)
            ? qkv[((long long)(b * N + n)) * 3 * Dd + 2 * Dd + hh * 64 + d0 + x]
            : __float2half_rn(0.f);
    }
    __syncthreads();
#pragma unroll
    for (int r = 0; r < 32; r += 8) {
        int n = n0 + x;
        if (n < N)
            vt[((long long)z * DHh + d0 + y + r) * N + n] = t[x][y + r];
    }
}

// ---------------------------------------------------------------------------
// tf32 mma GEMM (fp32 I/O) — SYRK trailing update + head
// ---------------------------------------------------------------------------
template <int TRANSB>
__global__ void gemmT_k(const float* __restrict__ A, const float* __restrict__ Bm,
                        const float* __restrict__ bias, const float* __restrict__ resid,
                        float* __restrict__ C,
                        int M, int N, int K, int lda, int ldb, int ldc,
                        int inner,
                        long long sAo, long long sAi, long long sBo, long long sBi,
                        long long sCo, long long sCi,
                        float alpha, int act, int lowerOnly) {
    if (lowerOnly && blockIdx.x > blockIdx.y) return;

    int z = blockIdx.z;
    int zo = z / inner, zi = z % inner;
    A  += zo * sAo + zi * sAi;
    Bm += zo * sBo + zi * sBi;
    long long co = zo * sCo + zi * sCi;
    C += co;
    if (resid) resid += co;

    __shared__ float As[64 * 36];
    __shared__ float Bs[2304];

    int tid = threadIdx.x;
    int m0 = blockIdx.y * 64, n0 = blockIdx.x * 64;
    int warp = tid >> 5, lane = tid & 31;
    int gid = lane >> 2, ctg = lane & 3;
    int wm = (warp >> 1) * 32, wn = (warp & 1) * 32;

    float acc[2][4][4];
#pragma unroll
    for (int mi = 0; mi < 2; mi++)
#pragma unroll
        for (int ni = 0; ni < 4; ni++)
#pragma unroll
            for (int e = 0; e < 4; e++) acc[mi][ni][e] = 0.f;

    for (int k0 = 0; k0 < K; k0 += 32) {
#pragma unroll
        for (int i = 0; i < 16; i++) {
            int l = tid + i * 128;
            int mm = l >> 5, kk = l & 31;
            int gm = m0 + mm, gk = k0 + kk;
            As[mm * 36 + kk] = (gm < M && gk < K) ? to_tf32(A[(long long)gm * lda + gk]) : 0.f;
        }
        if (TRANSB) {
#pragma unroll
            for (int i = 0; i < 16; i++) {
                int l = tid + i * 128;
                int nn = l >> 5, kk = l & 31;
                int gn = n0 + nn, gk = k0 + kk;
                Bs[nn * 36 + kk] = (gn < N && gk < K) ? to_tf32(Bm[(long long)gn * ldb + gk]) : 0.f;
            }
        } else {
#pragma unroll
            for (int i = 0; i < 16; i++) {
                int l = tid + i * 128;
                int kk = l >> 6, nn = l & 63;
                int gk = k0 + kk, gn = n0 + nn;
                Bs[kk * 72 + nn] = (gk < K && gn < N) ? to_tf32(Bm[(long long)gk * ldb + gn]) : 0.f;
            }
        }
        __syncthreads();
#pragma unroll
        for (int ks = 0; ks < 4; ks++) {
            int kr0 = ks * 8 + ctg, kr1 = kr0 + 4;
            unsigned a[2][4], b[4][2];
#pragma unroll
            for (int mi = 0; mi < 2; mi++) {
                int mb = wm + mi * 16 + gid;
                a[mi][0] = __float_as_uint(As[mb * 36 + kr0]);
                a[mi][1] = __float_as_uint(As[(mb + 8) * 36 + kr0]);
                a[mi][2] = __float_as_uint(As[mb * 36 + kr1]);
                a[mi][3] = __float_as_uint(As[(mb + 8) * 36 + kr1]);
            }
#pragma unroll
            for (int ni = 0; ni < 4; ni++) {
                int nb = wn + ni * 8 + gid;
                if (TRANSB) {
                    b[ni][0] = __float_as_uint(Bs[nb * 36 + kr0]);
                    b[ni][1] = __float_as_uint(Bs[nb * 36 + kr1]);
                } else {
                    b[ni][0] = __float_as_uint(Bs[kr0 * 72 + nb]);
                    b[ni][1] = __float_as_uint(Bs[kr1 * 72 + nb]);
                }
            }
#pragma unroll
            for (int mi = 0; mi < 2; mi++)
#pragma unroll
                for (int ni = 0; ni < 4; ni++)
                    mma8(acc[mi][ni], a[mi], b[ni]);
        }
        __syncthreads();
    }

#pragma unroll
    for (int mi = 0; mi < 2; mi++) {
#pragma unroll
        for (int ni = 0; ni < 4; ni++) {
            int col = n0 + wn + ni * 8 + ctg * 2;
#pragma unroll
            for (int e = 0; e < 4; e++) {
                int r = m0 + wm + mi * 16 + gid + ((e >> 1) << 3);
                int cc = col + (e & 1);
                if (r < M && cc < N) {
                    float v = alpha * acc[mi][ni][e];
                    if (bias) v += bias[cc];
                    if (act == 1) v = gelu_f(v);
                    if (resid) v += resid[(long long)r * ldc + cc];
                    C[(long long)r * ldc + cc] = v;
                }
            }
        }
    }
}

// ---------------------------------------------------------------------------
// LayerNorm (256-thread block per row) — fp32 in, fp16 out
// ---------------------------------------------------------------------------
__global__ void ln_k(const float* __restrict__ x, const float* __restrict__ g,
                     const float* __restrict__ b, __half* __restrict__ out, int rows) {
    int row = blockIdx.x;
    if (row >= rows) return;
    const float* xr = x + (size_t)row * Dd;
    __half* yr = out + (size_t)row * Dd;
    int tid = threadIdx.x;
    float v0 = xr[tid], v1 = xr[tid + 256], v2 = xr[tid + 512];
    __shared__ float red[8];
    __shared__ float stat[2];
    float s = warp_sum(v0 + v1 + v2);
    if ((tid & 31) == 0) red[tid >> 5] = s;
    __syncthreads();
    if (tid == 0) {
        float t = 0.f;
#pragma unroll
        for (int i = 0; i < 8; i++) t += red[i];
        stat[0] = t * (1.f / Dd);
    }
    __syncthreads();
    float m = stat[0];
    float d0 = v0 - m, d1 = v1 - m, d2 = v2 - m;
    s = warp_sum(d0 * d0 + d1 * d1 + d2 * d2);
    if ((tid & 31) == 0) red[tid >> 5] = s;
    __syncthreads();
    if (tid == 0) {
        float t = 0.f;
#pragma unroll
        for (int i = 0; i < 8; i++) t += red[i];
        stat[1] = rsqrtf(t * (1.f / Dd) + 1e-6f);
    }
    __syncthreads();
    float inv = stat[1];
    yr[tid]       = __float2half_rn(d0 * inv * g[tid]       + b[tid]);
    yr[tid + 256] = __float2half_rn(d1 * inv * g[tid + 256] + b[tid + 256]);
    yr[tid + 512] = __float2half_rn(d2 * inv * g[tid + 512] + b[tid + 512]);
}

// ---------------------------------------------------------------------------
// Softmax: fp32 logits in, fp16 probs out (warp per row, exp cached in regs)
// ---------------------------------------------------------------------------
__global__ void softmax_k(const float* __restrict__ att, __half* __restrict__ attp,
                          int n, int rows) {
    int row = blockIdx.x * (blockDim.x >> 5) + (threadIdx.x >> 5);
    if (row >= rows) return;
    int lane = threadIdx.x & 31;
    const float* r = att + (long long)row * n;
    __half* o = attp + (long long)row * n;
    float m = -3e38f;
    float ebuf[7];
    for (int i = lane; i < n; i += 32) m = fmaxf(m, r[i]);
    m = warp_max(m);
    float s = 0.f;
    int c = 0;
    for (int i = lane; i < n; i += 32) {
        float e = expf(r[i] - m);
        ebuf[c++] = e;
        s += e;
    }
    s = warp_sum(s);
    float inv = 1.f / s;
    c = 0;
    for (int i = lane; i < n; i += 32)
        o[i] = __float2half_rn(ebuf[c++] * inv);
}

// ---------------------------------------------------------------------------
// Patch embed im2col (fp16 out) + token assembly
// ---------------------------------------------------------------------------
__global__ void im2col_k(const float* __restrict__ in, __half* __restrict__ col) {
    long long idx = (long long)blockIdx.x * 256 + threadIdx.x;
    if (idx >= (long long)Bv * NP * Dd) return;
    int k = (int)(idx % Dd);
    long long bp = idx / Dd;
    int b = (int)(bp / NP), p = (int)(bp % NP);
    int c = k >> 8, rr = k & 255, i = rr >> 4, j = rr & 15;
    int py = p / 14, px = p % 14;
    col[idx] = __float2half_rn(in[((long long)(b * 3 + c) * 224 + py * 16 + i) * 224 + px * 16 + j]);
}

__global__ void build_x0_k(const float* __restrict__ img, const float* __restrict__ cls,
                           const float* __restrict__ pos, float* __restrict__ x0,
                           float* __restrict__ x) {
    long long idx = (long long)blockIdx.x * 256 + threadIdx.x;
    if (idx >= (long long)Bv * N1 * Dd) return;
    int d = (int)(idx % Dd);
    long long bn = idx / Dd;
    int n = (int)(bn % N1), b = (int)(bn / N1);
    float t = (n == 0) ? cls[d] : img[((long long)b * NP + (n - 1)) * Dd + d];
    float v = t + pos[n * Dd + d];
    x0[idx] = v;
    x[idx] = v;
}

__global__ void extract_q_k(const __half* __restrict__ h, float* __restrict__ q) {
    int idx = blockIdx.x * 256 + threadIdx.x;
    if (idx >= Bv * Dd) return;
    int b = idx / Dd, d = idx % Dd;
    q[idx] = __half2float(h[(long long)b * N1 * Dd + d]);
}

__global__ void build_x2_k(const float* __restrict__ x0, const float* __restrict__ prompt,
                           const float* __restrict__ pos, const float* __restrict__ img,
                           const int* __restrict__ topk, float* __restrict__ x) {
    long long idx = (long long)blockIdx.x * 256 + threadIdx.x;
    if (idx >= (long long)Bv * N2 * Dd) return;
    int d = (int)(idx % Dd);
    long long bn = idx / Dd;
    int n = (int)(bn % N2), b = (int)(bn / N2);
    float v;
    if (n == 0) {
        v = x0[(long long)b * N1 * Dd + d];
    } else if (n < 1 + Sn * LPn) {
        int t = n - 1;
        int s = t / LPn, l = t % LPn;
        int pi = topk[b * Sn + s];
        v = prompt[((long long)pi * LPn + l) * Dd + d] + pos[d];
    } else {
        v = img[((long long)b * NP + (n - (1 + Sn * LPn))) * Dd + d];
    }
    x[idx] = v;
}

__global__ void pool_k(const __half* __restrict__ h, float* __restrict__ pool) {
    int idx = blockIdx.x * 256 + threadIdx.x;
    if (idx >= Bv * Dd) return;
    int b = idx / Dd, d = idx % Dd;
    float s = 0.f;
#pragma unroll
    for (int t = 1; t <= Sn * LPn; t++)
        s += __half2float(h[((long long)b * N2 + t) * Dd + d]);
    pool[idx] = s * (1.f / (Sn * LPn));
}

// ---------------------------------------------------------------------------
// Cholesky (blocked NB=64)
// ---------------------------------------------------------------------------
__global__ void chol_prep_k(const float* __restrict__ var, float* __restrict__ L,
                            float* __restrict__ logdet) {
    long long idx = (long long)blockIdx.x * 256 + threadIdx.x;
    if (idx >= (long long)Pn * Dd * Dd) return;
    int j = (int)(idx % Dd);
    long long pi = idx / Dd;
    int i = (int)(pi % Dd);
    int p = (int)(pi / Dd);
    L[idx] = fabsf(var[idx]) + (i == j ? 1.f : 0.f);
    if (i == 0 && j == 0) logdet[p] = 0.f;
}

__global__ void potrf_k(float* __restrict__ L, float* __restrict__ logdet, int kb) {
    int p = blockIdx.x;
    float* A = L + (long long)p * Dd * Dd + (long long)kb * 64 * Dd + kb * 64;
    __shared__ float s[64][65];
    int tid = threadIdx.x;
    for (int l = tid; l < 4096; l += 256) s[l >> 6][l & 63] = A[(l >> 6) * Dd + (l & 63)];
    __syncthreads();
    for (int k = 0; k < 64; k++) {
        if (tid == 0) s[k][k] = sqrtf(s[k][k]);
        __syncthreads();
        for (int i = k + 1 + tid; i < 64; i += 256) s[i][k] /= s[k][k];
        __syncthreads();
        for (int l = tid; l < 4096; l += 256) {
            int i = l >> 6, j = l & 63;
            if (i > k && j > k && j <= i) s[i][j] -= s[i][k] * s[j][k];
        }
        __syncthreads();
    }
    for (int l = tid; l < 4096; l += 256) A[(l >> 6) * Dd + (l & 63)] = s[l >> 6][l & 63];
    if (tid < 64) atomicAdd(&logdet[p], 2.f * logf(s[tid][tid]));
}

__global__ void trsm_k(float* __restrict__ L, int kb) {
    int p = blockIdx.x;
    int off = (kb + 1) * 64;
    __shared__ float s[64][65];
    int tid = threadIdx.x;
    float* Ldiag = L + (long long)p * Dd * Dd + (long long)kb * 64 * Dd + kb * 64;
    for (int l = tid; l < 4096; l += 256) s[l >> 6][l & 63] = Ldiag[(l >> 6) * Dd + (l & 63)];
    __syncthreads();
    int wid = tid >> 5, lane = tid & 31;
    int row = off + blockIdx.y * 8 + wid;
    if (row >= Dd) return;
    float* a = L + (long long)p * Dd * Dd + (long long)row * Dd + kb * 64;
    float a0 = a[lane], a1 = a[lane + 32];
#pragma unroll
    for (int j = 0; j < 64; j++) {
        float aj = (j < 32) ? __shfl_sync(0xffffffffu, a0, j)
                            : __shfl_sync(0xffffffffu, a1, j - 32);
        float y = aj / s[j][j];
        if (lane == (j & 31)) {
            if (j < 32) a0 = y; else a1 = y;
        }
        if (lane > j) a0 -= s[lane][j] * y;
        if (lane + 32 > j) a1 -= s[lane + 32][j] * y;
    }
    a[lane] = a0;
    a[lane + 32] = a1;
}

__global__ void transpose_k(const float* __restrict__ L, float* __restrict__ LT) {
    __shared__ float t[32][33];
    int p = blockIdx.z;
    int i0 = blockIdx.y * 32, j0 = blockIdx.x * 32;
    int x = threadIdx.x, y = threadIdx.y;    // 32 x 8
#pragma unroll
    for (int r = 0; r < 32; r += 8)
        t[y + r][x] = L[(long long)p * Dd * Dd + (long long)(i0 + y + r) * Dd + j0 + x];
    __syncthreads();
#pragma unroll
    for (int r = 0; r < 32; r += 8)
        LT[(long long)p * Dd * Dd + (long long)(j0 + y + r) * Dd + i0 + x] = t[x][y + r];
}

__global__ void solve_k(const float* __restrict__ LT, const float* __restrict__ q,
                        const float* __restrict__ mean, const float* __restrict__ logdet,
                        float* __restrict__ logp) {
    int p = blockIdx.x;
    int wid = threadIdx.x >> 5, lane = threadIdx.x & 31;
    int b = blockIdx.y * 8 + wid;
    __shared__ float rs[8][Dd];
    float* r = rs[wid];
    for (int i = lane; i < Dd; i += 32) r[i] = q[b * Dd + i] - mean[p * Dd + i];
    const float* lt = LT + (long long)p * Dd * Dd;
    float quad = 0.f;
    for (int j = 0; j < Dd; j++) {
        __syncwarp();
        float y = r[j] / lt[(long long)j * Dd + j];
        if (lane == 0) quad += y * y;
        for (int i = j + 1 + lane; i < Dd; i += 32) r[i] -= lt[(long long)j * Dd + i] * y;
    }
    if (lane == 0)
        logp[b * Pn + p] = -0.5f * ((float)Dd * LOG2PI_F + logdet[p] + quad);
}

__global__ void topk_k(const float* __restrict__ logp, int* __restrict__ topk) {
    int b = threadIdx.x;
    if (b >= Bv) return;
    float v[Pn];
#pragma unroll
    for (int p = 0; p < Pn; p++) v[p] = logp[b * Pn + p];
#pragma unroll
    for (int s = 0; s < Sn; s++) {
        float best = -3e38f;
        int bi = 0;
#pragma unroll
        for (int p = 0; p < Pn; p++) {
            if (v[p] > best) { best = v[p]; bi = p; }
        }
        topk[b * Sn + s] = bi;
        v[bi] = -3e38f;
    }
}

// ---------------------------------------------------------------------------
// Host side
// ---------------------------------------------------------------------------
static void* getsym(const void* symbol) {
    void* p = nullptr;
    cudaGetSymbolAddress(&p, symbol);
    return p;
}

static void gemmH(const __half* A, const __half* Bt, const float* bias,
                  const float* resid, void* C, int M, int N, int K,
                  int lda, int ldc, int act, int outh, int bm) {
    dim3 grid(N / 128, (M + bm - 1) / bm);
    if (bm == 128) {
        size_t sm = 2 * GH_STG(128);
        if (outh) gemmH_k<1, 128><<<grid, 256, sm>>>(A, Bt, bias, resid, C, M, N, K, lda, ldc, act);
        else      gemmH_k<0, 128><<<grid, 256, sm>>>(A, Bt, bias, resid, C, M, N, K, lda, ldc, act);
    } else {
        size_t sm = 2 * GH_STG(64);
        if (outh) gemmH_k<1, 64><<<grid, 256, sm>>>(A, Bt, bias, resid, C, M, N, K, lda, ldc, act);
        else      gemmH_k<0, 64><<<grid, 256, sm>>>(A, Bt, bias, resid, C, M, N, K, lda, ldc, act);
    }
}

static void gemmT(bool transB, const float* A, const float* Bm, const float* bias,
                  const float* resid, float* C, int M, int N, int K,
                  int lda, int ldb, int ldc, int batch, int inner,
                  long long sAo, long long sAi, long long sBo, long long sBi,
                  long long sCo, long long sCi, float alpha, int act, int lowerOnly) {
    dim3 grid((N + 63) / 64, (M + 63) / 64, batch);
    if (transB)
        gemmT_k<1><<<grid, 128>>>(A, Bm, bias, resid, C, M, N, K, lda, ldb, ldc, inner,
                                  sAo, sAi, sBo, sBi, sCo, sCi, alpha, act, lowerOnly);
    else
        gemmT_k<0><<<grid, 128>>>(A, Bm, bias, resid, C, M, N, K, lda, ldb, ldc, inner,
                                  sAo, sAi, sBo, sBi, sCo, sCi, alpha, act, lowerOnly);
}

struct Weights {
    const float *qkv_b, *proj_b, *fc1_b, *fc2_b;
    const float *ln1_g, *ln1_b, *ln2_g, *ln2_b;
    const __half *wc;
};

static void run_blocks(float* x, int N, const Weights& w,
                       __half* h, __half* qkv, float* att, __half* attp,
                       __half* vt, __half* o, __half* mlp) {
    int M = Bv * N;
    int rows = Bv * NHh * N;
    const __half* wqkv = w.wc + WC_QKV;
    const __half* wproj = w.wc + WC_PROJ;
    const __half* wfc1 = w.wc + WC_FC1;
    const __half* wfc2 = w.wc + WC_FC2;
    for (int l = 0; l < NLAY; l++) {
        ln_k<<<M, 256>>>(x, w.ln1_g + l * Dd, w.ln1_b + l * Dd, h, M);
        // QKV -> half
        gemmH(h, wqkv + (long long)l * Dd * 3 * Dd, w.qkv_b + l * 3 * Dd,
              nullptr, qkv, M, 3 * Dd, Dd, Dd, 3 * Dd, 0, 1, 128);
        // V transpose for coalesced att@V
        vt_k<<<dim3((N + 31) / 32, 2, Bv * NHh), dim3(32, 8)>>>(qkv, vt, N);
        // att = Q K^T / 8 (fp32 logits), batched over (b,h)
        {
            dim3 grid((N + 63) / 64, (N + 63) / 64, Bv * NHh);
            gemmTH_k<0><<<grid, 128>>>(qkv, qkv + Dd, att,
                N, N, DHh, 3 * Dd, 3 * Dd, N, NHh,
                (long long)N * 3 * Dd, DHh, (long long)N * 3 * Dd, DHh,
                (long long)NHh * N * N, (long long)N * N, 0.125f);
        }
        softmax_k<<<(rows + 3) / 4, 128>>>(att, attp, N, rows);
        // o = attp @ V  (B = vt [d][k], coalesced) -> half
        {
            dim3 grid(1, (N + 63) / 64, Bv * NHh);
            gemmTH_k<1><<<grid, 128>>>(attp, vt, o,
                N, DHh, N, N, N, Dd, NHh,
                (long long)NHh * N * N, (long long)N * N,
                (long long)NHh * DHh * N, (long long)DHh * N,
                (long long)N * Dd, 64, 1.f);
        }
        // x = x + o @ proj_w + proj_b
        gemmH(o, wproj + (long long)l * Dd * Dd, w.proj_b + l * Dd,
              x, x, M, Dd, Dd, Dd, Dd, 0, 0, 64);
        ln_k<<<M, 256>>>(x, w.ln2_g + l * Dd, w.ln2_b + l * Dd, h, M);
        // mlp = gelu(h @ fc1 + b1) -> half
        gemmH(h, wfc1 + (long long)l * Dd * DFFd, w.fc1_b + l * DFFd,
              nullptr, mlp, M, DFFd, Dd, Dd, DFFd, 1, 1, 128);
        // x = x + mlp @ fc2 + b2
        gemmH(mlp, wfc2 + (long long)l * DFFd * Dd, w.fc2_b + l * Dd,
              x, x, M, Dd, DFFd, DFFd, Dd, 0, 0, 64);
    }
}

extern "C" void kernel_launch(void* const* d_in, const int* in_sizes, int n_in,
                              void* d_out, int out_size) {
    (void)in_sizes; (void)n_in; (void)out_size;
    const float* inputs   = (const float*)d_in[0];
    const float* patch_w  = (const float*)d_in[1];
    const float* patch_b  = (const float*)d_in[2];
    const float* cls_tok  = (const float*)d_in[3];
    const float* pos_emb  = (const float*)d_in[4];
    const float* ln1_g    = (const float*)d_in[5];
    const float* ln1_b    = (const float*)d_in[6];
    const float* qkv_w    = (const float*)d_in[7];
    const float* qkv_b    = (const float*)d_in[8];
    const float* proj_w   = (const float*)d_in[9];
    const float* proj_b   = (const float*)d_in[10];
    const float* ln2_g    = (const float*)d_in[11];
    const float* ln2_b    = (const float*)d_in[12];
    const float* fc1_w    = (const float*)d_in[13];
    const float* fc1_b    = (const float*)d_in[14];
    const float* fc2_w    = (const float*)d_in[15];
    const float* fc2_b    = (const float*)d_in[16];
    const float* norm_g   = (const float*)d_in[17];
    const float* norm_b   = (const float*)d_in[18];
    const float* head_w   = (const float*)d_in[19];
    const float* head_b   = (const float*)d_in[20];
    const float* prompt   = (const float*)d_in[21];
    const float* mean     = (const float*)d_in[22];
    const float* variance = (const float*)d_in[23];
    float* out = (float*)d_out;

    __half* col  = (__half*)getsym(g_colh);
    float*  img  = (float*)getsym(g_img);
    float*  x0   = (float*)getsym(g_x0);
    float*  x    = (float*)getsym(g_x);
    __half* h    = (__half*)getsym(g_hh);
    __half* qkv  = (__half*)getsym(g_qkvh);
    float*  att  = (float*)getsym(g_att);
    __half* attp = (__half*)getsym(g_attp);
    __half* vt   = (__half*)getsym(g_vth);
    __half* o    = (__half*)getsym(g_oh);
    __half* mlp  = (__half*)getsym(g_mlph);
    float*  qv   = (float*)getsym(g_q);
    float*  L    = (float*)getsym(g_L);
    float*  LT   = (float*)getsym(g_LT);
    float*  logd = (float*)getsym(g_logdet);
    float*  logp = (float*)getsym(g_logp);
    int*    topk = (int*)getsym(g_topk);
    float*  pool = (float*)getsym(g_pool);
    __half* wc   = (__half*)getsym(g_wch);

    cudaFuncSetAttribute(gemmH_k<0, 128>, cudaFuncAttributeMaxDynamicSharedMemorySize,
                         (int)(2 * GH_STG(128)));
    cudaFuncSetAttribute(gemmH_k<1, 128>, cudaFuncAttributeMaxDynamicSharedMemorySize,
                         (int)(2 * GH_STG(128)));
    cudaFuncSetAttribute(gemmH_k<0, 64>, cudaFuncAttributeMaxDynamicSharedMemorySize,
                         (int)(2 * GH_STG(64)));
    cudaFuncSetAttribute(gemmH_k<1, 64>, cudaFuncAttributeMaxDynamicSharedMemorySize,
                         (int)(2 * GH_STG(64)));

    // ---- weight pre-conversion: transpose [K][N] -> half [N][K] ----
    {
        dim3 blk(32, 8);
        tcvtH_k<<<dim3(2304 / 32, 768 / 32, 12), blk>>>(qkv_w, wc + WC_QKV, 768, 2304);
        tcvtH_k<<<dim3(768 / 32, 768 / 32, 12), blk>>>(proj_w, wc + WC_PROJ, 768, 768);
        tcvtH_k<<<dim3(3072 / 32, 768 / 32, 12), blk>>>(fc1_w, wc + WC_FC1, 768, 3072);
        tcvtH_k<<<dim3(768 / 32, 3072 / 32, 12), blk>>>(fc2_w, wc + WC_FC2, 3072, 768);
        long long n = 768LL * 768;   // patch_w already [N][K]
        cvtH_k<<<(unsigned)((n + 255) / 256), 256>>>(patch_w, wc + WC_PATCH, n);
    }

    Weights w;
    w.qkv_b = qkv_b; w.proj_b = proj_b; w.fc1_b = fc1_b; w.fc2_b = fc2_b;
    w.ln1_g = ln1_g; w.ln1_b = ln1_b; w.ln2_g = ln2_g; w.ln2_b = ln2_b;
    w.wc = wc;

    // ---- patch embed ----
    {
        long long tot = (long long)Bv * NP * Dd;
        im2col_k<<<(unsigned)((tot + 255) / 256), 256>>>(inputs, col);
        gemmH(col, wc + WC_PATCH, patch_b, nullptr, img,
              Bv * NP, Dd, Dd, Dd, Dd, 0, 0, 64);
        long long tot0 = (long long)Bv * N1 * Dd;
        build_x0_k<<<(unsigned)((tot0 + 255) / 256), 256>>>(img, cls_tok, pos_emb, x0, x);
    }

    // ---- Cholesky of cov = |variance| + I  (blocked NB=64) ----
    {
        long long tot = (long long)Pn * Dd * Dd;
        chol_prep_k<<<(unsigned)((tot + 255) / 256), 256>>>(variance, L, logd);
        for (int kb = 0; kb < Dd / 64; kb++) {
            potrf_k<<<Pn, 256>>>(L, logd, kb);
            int T = Dd - (kb + 1) * 64;
            if (T > 0) {
                trsm_k<<<dim3(Pn, (T + 7) / 8), 256>>>(L, kb);
                long long off = (long long)(kb + 1) * 64;
                const float* pan = L + off * Dd + kb * 64;
                float* trail = L + off * Dd + off;
                gemmT(true, pan, pan, nullptr, trail, trail,
                      T, T, 64, Dd, Dd, Dd, Pn, 1,
                      (long long)Dd * Dd, 0, (long long)Dd * Dd, 0,
                      (long long)Dd * Dd, 0, -1.f, 0, 1);
            }
        }
        transpose_k<<<dim3(Dd / 32, Dd / 32, Pn), dim3(32, 8)>>>(L, LT);
    }

    // ---- pass 1 (query) ----
    run_blocks(x, N1, w, h, qkv, att, attp, vt, o, mlp);
    ln_k<<<Bv * N1, 256>>>(x, norm_g, norm_b, h, Bv * N1);
    extract_q_k<<<(Bv * Dd + 255) / 256, 256>>>(h, qv);

    // ---- MVN logprob + top-k ----
    solve_k<<<dim3(Pn, Bv / 8), 256>>>(LT, qv, mean, logd, logp);
    topk_k<<<1, 16>>>(logp, topk);

    // ---- pass 2 (prompted) ----
    {
        long long tot = (long long)Bv * N2 * Dd;
        build_x2_k<<<(unsigned)((tot + 255) / 256), 256>>>(x0, prompt, pos_emb, img, topk, x);
    }
    run_blocks(x, N2, w, h, qkv, att, attp, vt, o, mlp);
    ln_k<<<Bv * N2, 256>>>(x, norm_g, norm_b, h, Bv * N2);
    pool_k<<<(Bv * Dd + 255) / 256, 256>>>(h, pool);

    // ---- head ----
    gemmT(false, pool, head_w, head_b, nullptr, out,
          Bv, NCn, Dd, Dd, NCn, NCn, 1, 1, 0, 0, 0, 0, 0, 0, 1.f, 0, 0);
}

// round 8
// speedup vs baseline: 5.5429x; 1.0799x over previous
#include <cuda_runtime.h>
#include <cuda_fp16.h>
#include <math.h>

// ---------------------------------------------------------------------------
// Problem constants
// ---------------------------------------------------------------------------
#define Bv   16
#define Dd   768
#define NLAY 12
#define NHh  12
#define DHh  64
#define DFFd 3072
#define Pn   10
#define Sn   5
#define LPn  5
#define NCn  100
#define NP   196
#define N1   197
#define N2   222          // 1 + S*LP + 196
#define LOG2PI_F 1.8378770664093454f

// ---------------------------------------------------------------------------
// Device scratch (static __device__ arrays; no runtime allocation)
// ---------------------------------------------------------------------------
__device__ __align__(16) __half g_colh[(size_t)Bv * NP * Dd];
__device__ __align__(16) float  g_img [(size_t)Bv * NP * Dd];
__device__ __align__(16) float  g_x0  [(size_t)Bv * N1 * Dd];
__device__ __align__(16) float  g_x   [(size_t)Bv * N2 * Dd];
__device__ __align__(16) __half g_hh  [(size_t)Bv * N2 * Dd];
__device__ __align__(16) __half g_qkvh[(size_t)Bv * N2 * 3 * Dd];
__device__ __align__(16) __half g_oh  [(size_t)Bv * N2 * Dd];
__device__ __align__(16) __half g_mlph[(size_t)Bv * N2 * DFFd];
__device__ __align__(16) float  g_q   [(size_t)Bv * Dd];
__device__ __align__(16) float  g_L   [(size_t)Pn * Dd * Dd];
__device__ __align__(16) float  g_LT  [(size_t)Pn * Dd * Dd];
__device__ float g_logdet[Pn];
__device__ float g_logp[Bv * Pn];
__device__ int   g_topk[Bv * Sn];
__device__ __align__(16) float g_pool[Bv * Dd];

// pre-converted fp16 weights, TRANSPOSED to [N][K]
#define WC_QKV   0LL
#define WC_PROJ  (WC_QKV  + 12LL * 768 * 2304)
#define WC_FC1   (WC_PROJ + 12LL * 768 * 768)
#define WC_FC2   (WC_FC1  + 12LL * 768 * 3072)
#define WC_PATCH (WC_FC2  + 12LL * 3072 * 768)
#define WC_TOTAL (WC_PATCH + 768LL * 768)
__device__ __align__(16) __half g_wch[WC_TOTAL];

// ---------------------------------------------------------------------------
// Helpers
// ---------------------------------------------------------------------------
__device__ __forceinline__ float warp_sum(float v) {
#pragma unroll
    for (int o = 16; o > 0; o >>= 1) v += __shfl_xor_sync(0xffffffffu, v, o);
    return v;
}
__device__ __forceinline__ float warp_max(float v) {
#pragma unroll
    for (int o = 16; o > 0; o >>= 1) v = fmaxf(v, __shfl_xor_sync(0xffffffffu, v, o));
    return v;
}
__device__ __forceinline__ float gelu_f(float x) {
    float x3 = x * x * x;
    return 0.5f * x * (1.f + tanhf(0.7978845608028654f * (x + 0.044715f * x3)));
}
__device__ __forceinline__ float to_tf32(float x) {
    float r;
    asm("cvt.rna.tf32.f32 %0, %1;" : "=f"(r) : "f"(x));
    return r;
}
__device__ __forceinline__ void mma8(float c[4], const unsigned a[4], const unsigned b[2]) {
    asm volatile(
        "mma.sync.aligned.m16n8k8.row.col.f32.tf32.tf32.f32 "
        "{%0,%1,%2,%3}, {%4,%5,%6,%7}, {%8,%9}, {%0,%1,%2,%3};\n"
        : "+f"(c[0]), "+f"(c[1]), "+f"(c[2]), "+f"(c[3])
        : "r"(a[0]), "r"(a[1]), "r"(a[2]), "r"(a[3]), "r"(b[0]), "r"(b[1]));
}
__device__ __forceinline__ void mma16(float c[4], const unsigned a[4], const unsigned b[2]) {
    asm volatile(
        "mma.sync.aligned.m16n8k16.row.col.f32.f16.f16.f32 "
        "{%0,%1,%2,%3}, {%4,%5,%6,%7}, {%8,%9}, {%0,%1,%2,%3};\n"
        : "+f"(c[0]), "+f"(c[1]), "+f"(c[2]), "+f"(c[3])
        : "r"(a[0]), "r"(a[1]), "r"(a[2]), "r"(a[3]), "r"(b[0]), "r"(b[1]));
}
__device__ __forceinline__ void cpa16(void* dst_smem, const void* src, int srcsize) {
    unsigned d = (unsigned)__cvta_generic_to_shared(dst_smem);
    asm volatile("cp.async.ca.shared.global [%0], [%1], 16, %2;\n"
                 :: "r"(d), "l"(src), "r"(srcsize));
}

// weight transpose+convert: src fp32 [K][N] -> dst half [N][K] (per-layer z)
__global__ void tcvtH_k(const float* __restrict__ src, __half* __restrict__ dst,
                        int K, int N) {
    __shared__ float t[32][33];
    long long zo = (long long)blockIdx.z * K * N;
    int k0 = blockIdx.y * 32, n0 = blockIdx.x * 32;
    int x = threadIdx.x, y = threadIdx.y;   // 32 x 8
#pragma unroll
    for (int r = 0; r < 32; r += 8)
        t[y + r][x] = src[zo + (long long)(k0 + y + r) * N + n0 + x];
    __syncthreads();
#pragma unroll
    for (int r = 0; r < 32; r += 8)
        dst[zo + (long long)(n0 + y + r) * K + k0 + x] = __float2half_rn(t[x][y + r]);
}

__global__ void cvtH_k(const float* __restrict__ s, __half* __restrict__ d, long long n) {
    long long i = (long long)blockIdx.x * 256 + threadIdx.x;
    if (i < n) d[i] = __float2half_rn(s[i]);
}

// ---------------------------------------------------------------------------
// Big dense fp16 GEMM: C = act(A[M,K] @ Bt[N,K]^T + bias) + resid
//   CTA tile BM x 128, BK=64, 256 threads, cp.async double buffer.
// ---------------------------------------------------------------------------
#define GH_STG(BM) (((BM) + 128) * 144)   // bytes per stage

template <int OUTH, int BM>
__global__ void __launch_bounds__(256)
gemmH_k(const __half* __restrict__ A, const __half* __restrict__ Bt,
        const float* __restrict__ bias, const float* __restrict__ resid,
        void* __restrict__ Cv, int M, int N, int K, int lda, int ldc, int act) {
    extern __shared__ char smem[];
    constexpr int MI = BM / 32;
    int tid = threadIdx.x;
    int m0 = blockIdx.y * BM, n0 = blockIdx.x * 128;
    int warp = tid >> 5, lane = tid & 31;
    int gid = lane >> 2, ctg = lane & 3;
    int wm = (warp & 1) * (BM / 2), wn = (warp >> 1) * 32;

    float acc[MI][4][4];
#pragma unroll
    for (int mi = 0; mi < MI; mi++)
#pragma unroll
        for (int ni = 0; ni < 4; ni++)
#pragma unroll
            for (int e = 0; e < 4; e++) acc[mi][ni][e] = 0.f;

    auto loadStage = [&](int kt, int st) {
        __half* As = (__half*)(smem + st * GH_STG(BM));
        __half* Bs = As + BM * 72;
        int k0 = kt * 64;
#pragma unroll
        for (int i = 0; i < BM / 32; i++) {
            int ch = tid + i * 256;
            int r = ch >> 3, c = ch & 7;
            int gm = m0 + r;
            cpa16(As + r * 72 + c * 8, A + (long long)gm * lda + k0 + c * 8,
                  (gm < M) ? 16 : 0);
        }
#pragma unroll
        for (int i = 0; i < 4; i++) {
            int ch = tid + i * 256;
            int r = ch >> 3, c = ch & 7;
            cpa16(Bs + r * 72 + c * 8, Bt + (long long)(n0 + r) * K + k0 + c * 8, 16);
        }
    };

    int KT = K >> 6;
    loadStage(0, 0);
    asm volatile("cp.async.commit_group;\n");
    for (int kt = 0; kt < KT; kt++) {
        if (kt + 1 < KT) loadStage(kt + 1, (kt + 1) & 1);
        asm volatile("cp.async.commit_group;\n");
        asm volatile("cp.async.wait_group 1;\n");
        __syncthreads();
        const __half* As = (const __half*)(smem + (kt & 1) * GH_STG(BM));
        const __half* Bs = As + BM * 72;
#pragma unroll
        for (int ks = 0; ks < 4; ks++) {
            int kb = ks * 16 + ctg * 2;
            unsigned a[MI][4], b[4][2];
#pragma unroll
            for (int mi = 0; mi < MI; mi++) {
                int mb = wm + mi * 16 + gid;
                a[mi][0] = *(const unsigned*)&As[mb * 72 + kb];
                a[mi][1] = *(const unsigned*)&As[(mb + 8) * 72 + kb];
                a[mi][2] = *(const unsigned*)&As[mb * 72 + kb + 8];
                a[mi][3] = *(const unsigned*)&As[(mb + 8) * 72 + kb + 8];
            }
#pragma unroll
            for (int ni = 0; ni < 4; ni++) {
                int nb = wn + ni * 8 + gid;
                b[ni][0] = *(const unsigned*)&Bs[nb * 72 + kb];
                b[ni][1] = *(const unsigned*)&Bs[nb * 72 + kb + 8];
            }
#pragma unroll
            for (int mi = 0; mi < MI; mi++)
#pragma unroll
                for (int ni = 0; ni < 4; ni++)
                    mma16(acc[mi][ni], a[mi], b[ni]);
        }
        __syncthreads();
    }

#pragma unroll
    for (int mi = 0; mi < MI; mi++) {
#pragma unroll
        for (int ni = 0; ni < 4; ni++) {
            int cc = n0 + wn + ni * 8 + ctg * 2;
#pragma unroll
            for (int e2 = 0; e2 < 2; e2++) {
                int r = m0 + wm + mi * 16 + gid + e2 * 8;
                if (r >= M) continue;
                float v0 = acc[mi][ni][e2 * 2 + 0];
                float v1 = acc[mi][ni][e2 * 2 + 1];
                if (bias) { v0 += bias[cc]; v1 += bias[cc + 1]; }
                if (act == 1) { v0 = gelu_f(v0); v1 = gelu_f(v1); }
                if (resid) {
                    v0 += resid[(long long)r * ldc + cc];
                    v1 += resid[(long long)r * ldc + cc + 1];
                }
                if (OUTH) {
                    __half2* C = (__half2*)((__half*)Cv + (long long)r * ldc + cc);
                    *C = __floats2half2_rn(v0, v1);
                } else {
                    float* C = (float*)Cv + (long long)r * ldc + cc;
                    C[0] = v0; C[1] = v1;
                }
            }
        }
    }
}

// ---------------------------------------------------------------------------
// Fused flash attention: one CTA per (q-tile 64, b*H). 128 threads.
//   qkv [b, n, 3*768] half (Q | K | V per head hh*64).
//   out [b, n, 768] half.
//   Online softmax, O accumulator in regs, P in smem half.
// ---------------------------------------------------------------------------
#define FA_SMEM (4 * 64 * 72 * 2 + 64 * 65 * 4 + 3 * 64 * 4)

__global__ void __launch_bounds__(128)
fa_k(const __half* __restrict__ qkv, __half* __restrict__ out, int N) {
    extern __shared__ char sm[];
    __half* Qs  = (__half*)sm;            // 64 x 72
    __half* Ks  = Qs + 64 * 72;
    __half* Vts = Ks + 64 * 72;           // [d][kv]
    __half* Ps  = Vts + 64 * 72;
    float*  Ss  = (float*)(Ps + 64 * 72); // 64 x 65
    float*  smm = Ss + 64 * 65;
    float*  sml = smm + 64;
    float*  smc = sml + 64;

    int tid = threadIdx.x;
    int z = blockIdx.y;
    int b = z / NHh, hh = z % NHh;
    int q0 = blockIdx.x * 64;
    const __half* base = qkv + (long long)b * N * 2304 + hh * 64;

    int warp = tid >> 5, lane = tid & 31;
    int gid = lane >> 2, ctg = lane & 3;
    int wm = (warp >> 1) * 32, wn = (warp & 1) * 32;

    // load Q tile
#pragma unroll
    for (int i = 0; i < 4; i++) {
        int l = tid + i * 128;
        int r = l >> 3, c8 = l & 7;
        int q = q0 + r;
        int4 v = (q < N) ? *(const int4*)(base + (long long)q * 2304 + c8 * 8)
                         : make_int4(0, 0, 0, 0);
        *(int4*)&Qs[r * 72 + c8 * 8] = v;
    }
    if (tid < 64) { smm[tid] = -3e38f; sml[tid] = 0.f; }

    float O[2][4][4];
#pragma unroll
    for (int mi = 0; mi < 2; mi++)
#pragma unroll
        for (int ni = 0; ni < 4; ni++)
#pragma unroll
            for (int e = 0; e < 4; e++) O[mi][ni][e] = 0.f;

    int NT = (N + 63) >> 6;
    for (int j = 0; j < NT; j++) {
        int kv0 = j * 64;
        int kvlen = N - kv0; if (kvlen > 64) kvlen = 64;
        __syncthreads();   // protect previous-tile smem consumers
        // load K tile [kv][d]
#pragma unroll
        for (int i = 0; i < 4; i++) {
            int l = tid + i * 128;
            int r = l >> 3, c8 = l & 7;
            int n = kv0 + r;
            int4 v = (n < N) ? *(const int4*)(base + (long long)n * 2304 + 768 + c8 * 8)
                             : make_int4(0, 0, 0, 0);
            *(int4*)&Ks[r * 72 + c8 * 8] = v;
        }
        // load V tile transposed -> Vts[d][kv]
#pragma unroll
        for (int i = 0; i < 4; i++) {
            int l = tid + i * 128;
            int r = l >> 3, c8 = l & 7;
            int n = kv0 + r;
            __half tmp[8];
            *(int4*)tmp = (n < N) ? *(const int4*)(base + (long long)n * 2304 + 1536 + c8 * 8)
                                  : make_int4(0, 0, 0, 0);
#pragma unroll
            for (int t = 0; t < 8; t++) Vts[(c8 * 8 + t) * 72 + r] = tmp[t];
        }
        __syncthreads();
        // S = Q K^T
        float acc[2][4][4];
#pragma unroll
        for (int mi = 0; mi < 2; mi++)
#pragma unroll
            for (int ni = 0; ni < 4; ni++)
#pragma unroll
                for (int e = 0; e < 4; e++) acc[mi][ni][e] = 0.f;
#pragma unroll
        for (int ks = 0; ks < 4; ks++) {
            int kb = ks * 16 + ctg * 2;
            unsigned a[2][4], bb[4][2];
#pragma unroll
            for (int mi = 0; mi < 2; mi++) {
                int mb = wm + mi * 16 + gid;
                a[mi][0] = *(const unsigned*)&Qs[mb * 72 + kb];
                a[mi][1] = *(const unsigned*)&Qs[(mb + 8) * 72 + kb];
                a[mi][2] = *(const unsigned*)&Qs[mb * 72 + kb + 8];
                a[mi][3] = *(const unsigned*)&Qs[(mb + 8) * 72 + kb + 8];
            }
#pragma unroll
            for (int ni = 0; ni < 4; ni++) {
                int nb = wn + ni * 8 + gid;
                bb[ni][0] = *(const unsigned*)&Ks[nb * 72 + kb];
                bb[ni][1] = *(const unsigned*)&Ks[nb * 72 + kb + 8];
            }
#pragma unroll
            for (int mi = 0; mi < 2; mi++)
#pragma unroll
                for (int ni = 0; ni < 4; ni++)
                    mma16(acc[mi][ni], a[mi], bb[ni]);
        }
        // write scaled S to smem
#pragma unroll
        for (int mi = 0; mi < 2; mi++)
#pragma unroll
            for (int ni = 0; ni < 4; ni++)
#pragma unroll
                for (int e = 0; e < 4; e++) {
                    int r = wm + mi * 16 + gid + ((e >> 1) << 3);
                    int c = wn + ni * 8 + ctg * 2 + (e & 1);
                    Ss[r * 65 + c] = acc[mi][ni][e] * 0.125f;
                }
        __syncthreads();
        // online softmax (2 threads per row)
        {
            int row = tid >> 1, hv = tid & 1;
            int c0 = hv * 32;
            float mold = smm[row];
            float tmax = -3e38f;
            for (int c = c0; c < c0 + 32; c++)
                if (c < kvlen) tmax = fmaxf(tmax, Ss[row * 65 + c]);
            tmax = fmaxf(tmax, __shfl_xor_sync(0xffffffffu, tmax, 1));
            float newm = fmaxf(mold, tmax);
            float lsum = 0.f;
            for (int c = c0; c < c0 + 32; c++) {
                float p = (c < kvlen) ? __expf(Ss[row * 65 + c] - newm) : 0.f;
                lsum += p;
                Ps[row * 72 + c] = __float2half_rn(p);
            }
            lsum += __shfl_xor_sync(0xffffffffu, lsum, 1);
            if (hv == 0) {
                float cf = __expf(mold - newm);
                smc[row] = cf;
                sml[row] = sml[row] * cf + lsum;
                smm[row] = newm;
            }
        }
        __syncthreads();
        // O = O * c + P @ V
#pragma unroll
        for (int mi = 0; mi < 2; mi++)
#pragma unroll
            for (int e2 = 0; e2 < 2; e2++) {
                float cf = smc[wm + mi * 16 + gid + e2 * 8];
#pragma unroll
                for (int ni = 0; ni < 4; ni++) {
                    O[mi][ni][e2 * 2] *= cf;
                    O[mi][ni][e2 * 2 + 1] *= cf;
                }
            }
#pragma unroll
        for (int ks = 0; ks < 4; ks++) {
            int kb = ks * 16 + ctg * 2;
            unsigned a[2][4], bb[4][2];
#pragma unroll
            for (int mi = 0; mi < 2; mi++) {
                int mb = wm + mi * 16 + gid;
                a[mi][0] = *(const unsigned*)&Ps[mb * 72 + kb];
                a[mi][1] = *(const unsigned*)&Ps[(mb + 8) * 72 + kb];
                a[mi][2] = *(const unsigned*)&Ps[mb * 72 + kb + 8];
                a[mi][3] = *(const unsigned*)&Ps[(mb + 8) * 72 + kb + 8];
            }
#pragma unroll
            for (int ni = 0; ni < 4; ni++) {
                int nb = wn + ni * 8 + gid;
                bb[ni][0] = *(const unsigned*)&Vts[nb * 72 + kb];
                bb[ni][1] = *(const unsigned*)&Vts[nb * 72 + kb + 8];
            }
#pragma unroll
            for (int mi = 0; mi < 2; mi++)
#pragma unroll
                for (int ni = 0; ni < 4; ni++)
                    mma16(O[mi][ni], a[mi], bb[ni]);
        }
    }
    // epilogue: normalize and store
#pragma unroll
    for (int mi = 0; mi < 2; mi++)
#pragma unroll
        for (int e2 = 0; e2 < 2; e2++) {
            int r = wm + mi * 16 + gid + e2 * 8;
            int q = q0 + r;
            if (q >= N) continue;
            float invl = 1.f / sml[r];
#pragma unroll
            for (int ni = 0; ni < 4; ni++) {
                int c = wn + ni * 8 + ctg * 2;
                __half2* dst = (__half2*)(out + ((long long)(b * N + q)) * Dd + hh * 64 + c);
                *dst = __floats2half2_rn(O[mi][ni][e2 * 2] * invl,
                                         O[mi][ni][e2 * 2 + 1] * invl);
            }
        }
}

// ---------------------------------------------------------------------------
// tf32 mma GEMM (fp32 I/O) — SYRK trailing update + head
// ---------------------------------------------------------------------------
template <int TRANSB>
__global__ void gemmT_k(const float* __restrict__ A, const float* __restrict__ Bm,
                        const float* __restrict__ bias, const float* __restrict__ resid,
                        float* __restrict__ C,
                        int M, int N, int K, int lda, int ldb, int ldc,
                        int inner,
                        long long sAo, long long sAi, long long sBo, long long sBi,
                        long long sCo, long long sCi,
                        float alpha, int act, int lowerOnly) {
    if (lowerOnly && blockIdx.x > blockIdx.y) return;

    int z = blockIdx.z;
    int zo = z / inner, zi = z % inner;
    A  += zo * sAo + zi * sAi;
    Bm += zo * sBo + zi * sBi;
    long long co = zo * sCo + zi * sCi;
    C += co;
    if (resid) resid += co;

    __shared__ float As[64 * 36];
    __shared__ float Bs[2304];

    int tid = threadIdx.x;
    int m0 = blockIdx.y * 64, n0 = blockIdx.x * 64;
    int warp = tid >> 5, lane = tid & 31;
    int gid = lane >> 2, ctg = lane & 3;
    int wm = (warp >> 1) * 32, wn = (warp & 1) * 32;

    float acc[2][4][4];
#pragma unroll
    for (int mi = 0; mi < 2; mi++)
#pragma unroll
        for (int ni = 0; ni < 4; ni++)
#pragma unroll
            for (int e = 0; e < 4; e++) acc[mi][ni][e] = 0.f;

    for (int k0 = 0; k0 < K; k0 += 32) {
#pragma unroll
        for (int i = 0; i < 16; i++) {
            int l = tid + i * 128;
            int mm = l >> 5, kk = l & 31;
            int gm = m0 + mm, gk = k0 + kk;
            As[mm * 36 + kk] = (gm < M && gk < K) ? to_tf32(A[(long long)gm * lda + gk]) : 0.f;
        }
        if (TRANSB) {
#pragma unroll
            for (int i = 0; i < 16; i++) {
                int l = tid + i * 128;
                int nn = l >> 5, kk = l & 31;
                int gn = n0 + nn, gk = k0 + kk;
                Bs[nn * 36 + kk] = (gn < N && gk < K) ? to_tf32(Bm[(long long)gn * ldb + gk]) : 0.f;
            }
        } else {
#pragma unroll
            for (int i = 0; i < 16; i++) {
                int l = tid + i * 128;
                int kk = l >> 6, nn = l & 63;
                int gk = k0 + kk, gn = n0 + nn;
                Bs[kk * 72 + nn] = (gk < K && gn < N) ? to_tf32(Bm[(long long)gk * ldb + gn]) : 0.f;
            }
        }
        __syncthreads();
#pragma unroll
        for (int ks = 0; ks < 4; ks++) {
            int kr0 = ks * 8 + ctg, kr1 = kr0 + 4;
            unsigned a[2][4], b[4][2];
#pragma unroll
            for (int mi = 0; mi < 2; mi++) {
                int mb = wm + mi * 16 + gid;
                a[mi][0] = __float_as_uint(As[mb * 36 + kr0]);
                a[mi][1] = __float_as_uint(As[(mb + 8) * 36 + kr0]);
                a[mi][2] = __float_as_uint(As[mb * 36 + kr1]);
                a[mi][3] = __float_as_uint(As[(mb + 8) * 36 + kr1]);
            }
#pragma unroll
            for (int ni = 0; ni < 4; ni++) {
                int nb = wn + ni * 8 + gid;
                if (TRANSB) {
                    b[ni][0] = __float_as_uint(Bs[nb * 36 + kr0]);
                    b[ni][1] = __float_as_uint(Bs[nb * 36 + kr1]);
                } else {
                    b[ni][0] = __float_as_uint(Bs[kr0 * 72 + nb]);
                    b[ni][1] = __float_as_uint(Bs[kr1 * 72 + nb]);
                }
            }
#pragma unroll
            for (int mi = 0; mi < 2; mi++)
#pragma unroll
                for (int ni = 0; ni < 4; ni++)
                    mma8(acc[mi][ni], a[mi], b[ni]);
        }
        __syncthreads();
    }

#pragma unroll
    for (int mi = 0; mi < 2; mi++) {
#pragma unroll
        for (int ni = 0; ni < 4; ni++) {
            int col = n0 + wn + ni * 8 + ctg * 2;
#pragma unroll
            for (int e = 0; e < 4; e++) {
                int r = m0 + wm + mi * 16 + gid + ((e >> 1) << 3);
                int cc = col + (e & 1);
                if (r < M && cc < N) {
                    float v = alpha * acc[mi][ni][e];
                    if (bias) v += bias[cc];
                    if (act == 1) v = gelu_f(v);
                    if (resid) v += resid[(long long)r * ldc + cc];
                    C[(long long)r * ldc + cc] = v;
                }
            }
        }
    }
}

// ---------------------------------------------------------------------------
// LayerNorm (256-thread block per row) — fp32 in, fp16 out
// ---------------------------------------------------------------------------
__global__ void ln_k(const float* __restrict__ x, const float* __restrict__ g,
                     const float* __restrict__ b, __half* __restrict__ out, int rows) {
    int row = blockIdx.x;
    if (row >= rows) return;
    const float* xr = x + (size_t)row * Dd;
    __half* yr = out + (size_t)row * Dd;
    int tid = threadIdx.x;
    float v0 = xr[tid], v1 = xr[tid + 256], v2 = xr[tid + 512];
    __shared__ float red[8];
    __shared__ float stat[2];
    float s = warp_sum(v0 + v1 + v2);
    if ((tid & 31) == 0) red[tid >> 5] = s;
    __syncthreads();
    if (tid == 0) {
        float t = 0.f;
#pragma unroll
        for (int i = 0; i < 8; i++) t += red[i];
        stat[0] = t * (1.f / Dd);
    }
    __syncthreads();
    float m = stat[0];
    float d0 = v0 - m, d1 = v1 - m, d2 = v2 - m;
    s = warp_sum(d0 * d0 + d1 * d1 + d2 * d2);
    if ((tid & 31) == 0) red[tid >> 5] = s;
    __syncthreads();
    if (tid == 0) {
        float t = 0.f;
#pragma unroll
        for (int i = 0; i < 8; i++) t += red[i];
        stat[1] = rsqrtf(t * (1.f / Dd) + 1e-6f);
    }
    __syncthreads();
    float inv = stat[1];
    yr[tid]       = __float2half_rn(d0 * inv * g[tid]       + b[tid]);
    yr[tid + 256] = __float2half_rn(d1 * inv * g[tid + 256] + b[tid + 256]);
    yr[tid + 512] = __float2half_rn(d2 * inv * g[tid + 512] + b[tid + 512]);
}

// ---------------------------------------------------------------------------
// Patch embed im2col (fp16 out) + token assembly
// ---------------------------------------------------------------------------
__global__ void im2col_k(const float* __restrict__ in, __half* __restrict__ col) {
    long long idx = (long long)blockIdx.x * 256 + threadIdx.x;
    if (idx >= (long long)Bv * NP * Dd) return;
    int k = (int)(idx % Dd);
    long long bp = idx / Dd;
    int b = (int)(bp / NP), p = (int)(bp % NP);
    int c = k >> 8, rr = k & 255, i = rr >> 4, j = rr & 15;
    int py = p / 14, px = p % 14;
    col[idx] = __float2half_rn(in[((long long)(b * 3 + c) * 224 + py * 16 + i) * 224 + px * 16 + j]);
}

__global__ void build_x0_k(const float* __restrict__ img, const float* __restrict__ cls,
                           const float* __restrict__ pos, float* __restrict__ x0,
                           float* __restrict__ x) {
    long long idx = (long long)blockIdx.x * 256 + threadIdx.x;
    if (idx >= (long long)Bv * N1 * Dd) return;
    int d = (int)(idx % Dd);
    long long bn = idx / Dd;
    int n = (int)(bn % N1), b = (int)(bn / N1);
    float t = (n == 0) ? cls[d] : img[((long long)b * NP + (n - 1)) * Dd + d];
    float v = t + pos[n * Dd + d];
    x0[idx] = v;
    x[idx] = v;
}

__global__ void extract_q_k(const __half* __restrict__ h, float* __restrict__ q) {
    int idx = blockIdx.x * 256 + threadIdx.x;
    if (idx >= Bv * Dd) return;
    int b = idx / Dd, d = idx % Dd;
    q[idx] = __half2float(h[(long long)b * N1 * Dd + d]);
}

__global__ void build_x2_k(const float* __restrict__ x0, const float* __restrict__ prompt,
                           const float* __restrict__ pos, const float* __restrict__ img,
                           const int* __restrict__ topk, float* __restrict__ x) {
    long long idx = (long long)blockIdx.x * 256 + threadIdx.x;
    if (idx >= (long long)Bv * N2 * Dd) return;
    int d = (int)(idx % Dd);
    long long bn = idx / Dd;
    int n = (int)(bn % N2), b = (int)(bn / N2);
    float v;
    if (n == 0) {
        v = x0[(long long)b * N1 * Dd + d];
    } else if (n < 1 + Sn * LPn) {
        int t = n - 1;
        int s = t / LPn, l = t % LPn;
        int pi = topk[b * Sn + s];
        v = prompt[((long long)pi * LPn + l) * Dd + d] + pos[d];
    } else {
        v = img[((long long)b * NP + (n - (1 + Sn * LPn))) * Dd + d];
    }
    x[idx] = v;
}

__global__ void pool_k(const __half* __restrict__ h, float* __restrict__ pool) {
    int idx = blockIdx.x * 256 + threadIdx.x;
    if (idx >= Bv * Dd) return;
    int b = idx / Dd, d = idx % Dd;
    float s = 0.f;
#pragma unroll
    for (int t = 1; t <= Sn * LPn; t++)
        s += __half2float(h[((long long)b * N2 + t) * Dd + d]);
    pool[idx] = s * (1.f / (Sn * LPn));
}

// ---------------------------------------------------------------------------
// Cholesky (blocked NB=64)
// ---------------------------------------------------------------------------
__global__ void chol_prep_k(const float* __restrict__ var, float* __restrict__ L,
                            float* __restrict__ logdet) {
    long long idx = (long long)blockIdx.x * 256 + threadIdx.x;
    if (idx >= (long long)Pn * Dd * Dd) return;
    int j = (int)(idx % Dd);
    long long pi = idx / Dd;
    int i = (int)(pi % Dd);
    int p = (int)(pi / Dd);
    L[idx] = fabsf(var[idx]) + (i == j ? 1.f : 0.f);
    if (i == 0 && j == 0) logdet[p] = 0.f;
}

__global__ void potrf_k(float* __restrict__ L, float* __restrict__ logdet, int kb) {
    int p = blockIdx.x;
    float* A = L + (long long)p * Dd * Dd + (long long)kb * 64 * Dd + kb * 64;
    __shared__ float s[64][65];
    int tid = threadIdx.x;
    for (int l = tid; l < 4096; l += 256) s[l >> 6][l & 63] = A[(l >> 6) * Dd + (l & 63)];
    __syncthreads();
    for (int k = 0; k < 64; k++) {
        if (tid == 0) s[k][k] = sqrtf(s[k][k]);
        __syncthreads();
        for (int i = k + 1 + tid; i < 64; i += 256) s[i][k] /= s[k][k];
        __syncthreads();
        for (int l = tid; l < 4096; l += 256) {
            int i = l >> 6, j = l & 63;
            if (i > k && j > k && j <= i) s[i][j] -= s[i][k] * s[j][k];
        }
        __syncthreads();
    }
    for (int l = tid; l < 4096; l += 256) A[(l >> 6) * Dd + (l & 63)] = s[l >> 6][l & 63];
    if (tid < 64) atomicAdd(&logdet[p], 2.f * logf(s[tid][tid]));
}

__global__ void trsm_k(float* __restrict__ L, int kb) {
    int p = blockIdx.x;
    int off = (kb + 1) * 64;
    __shared__ float s[64][65];
    int tid = threadIdx.x;
    float* Ldiag = L + (long long)p * Dd * Dd + (long long)kb * 64 * Dd + kb * 64;
    for (int l = tid; l < 4096; l += 256) s[l >> 6][l & 63] = Ldiag[(l >> 6) * Dd + (l & 63)];
    __syncthreads();
    int wid = tid >> 5, lane = tid & 31;
    int row = off + blockIdx.y * 8 + wid;
    if (row >= Dd) return;
    float* a = L + (long long)p * Dd * Dd + (long long)row * Dd + kb * 64;
    float a0 = a[lane], a1 = a[lane + 32];
#pragma unroll
    for (int j = 0; j < 64; j++) {
        float aj = (j < 32) ? __shfl_sync(0xffffffffu, a0, j)
                            : __shfl_sync(0xffffffffu, a1, j - 32);
        float y = aj / s[j][j];
        if (lane == (j & 31)) {
            if (j < 32) a0 = y; else a1 = y;
        }
        if (lane > j) a0 -= s[lane][j] * y;
        if (lane + 32 > j) a1 -= s[lane + 32][j] * y;
    }
    a[lane] = a0;
    a[lane + 32] = a1;
}

__global__ void transpose_k(const float* __restrict__ L, float* __restrict__ LT) {
    __shared__ float t[32][33];
    int p = blockIdx.z;
    int i0 = blockIdx.y * 32, j0 = blockIdx.x * 32;
    int x = threadIdx.x, y = threadIdx.y;    // 32 x 8
#pragma unroll
    for (int r = 0; r < 32; r += 8)
        t[y + r][x] = L[(long long)p * Dd * Dd + (long long)(i0 + y + r) * Dd + j0 + x];
    __syncthreads();
#pragma unroll
    for (int r = 0; r < 32; r += 8)
        LT[(long long)p * Dd * Dd + (long long)(j0 + y + r) * Dd + i0 + x] = t[x][y + r];
}

__global__ void solve_k(const float* __restrict__ LT, const float* __restrict__ q,
                        const float* __restrict__ mean, const float* __restrict__ logdet,
                        float* __restrict__ logp) {
    int p = blockIdx.x;
    int wid = threadIdx.x >> 5, lane = threadIdx.x & 31;
    int b = blockIdx.y * 8 + wid;
    __shared__ float rs[8][Dd];
    float* r = rs[wid];
    for (int i = lane; i < Dd; i += 32) r[i] = q[b * Dd + i] - mean[p * Dd + i];
    const float* lt = LT + (long long)p * Dd * Dd;
    float quad = 0.f;
    for (int j = 0; j < Dd; j++) {
        __syncwarp();
        float y = r[j] / lt[(long long)j * Dd + j];
        if (lane == 0) quad += y * y;
        for (int i = j + 1 + lane; i < Dd; i += 32) r[i] -= lt[(long long)j * Dd + i] * y;
    }
    if (lane == 0)
        logp[b * Pn + p] = -0.5f * ((float)Dd * LOG2PI_F + logdet[p] + quad);
}

__global__ void topk_k(const float* __restrict__ logp, int* __restrict__ topk) {
    int b = threadIdx.x;
    if (b >= Bv) return;
    float v[Pn];
#pragma unroll
    for (int p = 0; p < Pn; p++) v[p] = logp[b * Pn + p];
#pragma unroll
    for (int s = 0; s < Sn; s++) {
        float best = -3e38f;
        int bi = 0;
#pragma unroll
        for (int p = 0; p < Pn; p++) {
            if (v[p] > best) { best = v[p]; bi = p; }
        }
        topk[b * Sn + s] = bi;
        v[bi] = -3e38f;
    }
}

// ---------------------------------------------------------------------------
// Host side
// ---------------------------------------------------------------------------
static void* getsym(const void* symbol) {
    void* p = nullptr;
    cudaGetSymbolAddress(&p, symbol);
    return p;
}

static void gemmH(const __half* A, const __half* Bt, const float* bias,
                  const float* resid, void* C, int M, int N, int K,
                  int lda, int ldc, int act, int outh, int bm) {
    dim3 grid(N / 128, (M + bm - 1) / bm);
    if (bm == 128) {
        size_t sm = 2 * GH_STG(128);
        if (outh) gemmH_k<1, 128><<<grid, 256, sm>>>(A, Bt, bias, resid, C, M, N, K, lda, ldc, act);
        else      gemmH_k<0, 128><<<grid, 256, sm>>>(A, Bt, bias, resid, C, M, N, K, lda, ldc, act);
    } else {
        size_t sm = 2 * GH_STG(64);
        if (outh) gemmH_k<1, 64><<<grid, 256, sm>>>(A, Bt, bias, resid, C, M, N, K, lda, ldc, act);
        else      gemmH_k<0, 64><<<grid, 256, sm>>>(A, Bt, bias, resid, C, M, N, K, lda, ldc, act);
    }
}

static void gemmT(bool transB, const float* A, const float* Bm, const float* bias,
                  const float* resid, float* C, int M, int N, int K,
                  int lda, int ldb, int ldc, int batch, int inner,
                  long long sAo, long long sAi, long long sBo, long long sBi,
                  long long sCo, long long sCi, float alpha, int act, int lowerOnly) {
    dim3 grid((N + 63) / 64, (M + 63) / 64, batch);
    if (transB)
        gemmT_k<1><<<grid, 128>>>(A, Bm, bias, resid, C, M, N, K, lda, ldb, ldc, inner,
                                  sAo, sAi, sBo, sBi, sCo, sCi, alpha, act, lowerOnly);
    else
        gemmT_k<0><<<grid, 128>>>(A, Bm, bias, resid, C, M, N, K, lda, ldb, ldc, inner,
                                  sAo, sAi, sBo, sBi, sCo, sCi, alpha, act, lowerOnly);
}

struct Weights {
    const float *qkv_b, *proj_b, *fc1_b, *fc2_b;
    const float *ln1_g, *ln1_b, *ln2_g, *ln2_b;
    const __half *wc;
};

static void run_blocks(float* x, int N, const Weights& w,
                       __half* h, __half* qkv, __half* o, __half* mlp) {
    int M = Bv * N;
    int qt = (N + 63) / 64;
    const __half* wqkv = w.wc + WC_QKV;
    const __half* wproj = w.wc + WC_PROJ;
    const __half* wfc1 = w.wc + WC_FC1;
    const __half* wfc2 = w.wc + WC_FC2;
    for (int l = 0; l < NLAY; l++) {
        ln_k<<<M, 256>>>(x, w.ln1_g + l * Dd, w.ln1_b + l * Dd, h, M);
        gemmH(h, wqkv + (long long)l * Dd * 3 * Dd, w.qkv_b + l * 3 * Dd,
              nullptr, qkv, M, 3 * Dd, Dd, Dd, 3 * Dd, 0, 1, 128);
        fa_k<<<dim3(qt, Bv * NHh), 128, FA_SMEM>>>(qkv, o, N);
        gemmH(o, wproj + (long long)l * Dd * Dd, w.proj_b + l * Dd,
              x, x, M, Dd, Dd, Dd, Dd, 0, 0, 64);
        ln_k<<<M, 256>>>(x, w.ln2_g + l * Dd, w.ln2_b + l * Dd, h, M);
        gemmH(h, wfc1 + (long long)l * Dd * DFFd, w.fc1_b + l * DFFd,
              nullptr, mlp, M, DFFd, Dd, Dd, DFFd, 1, 1, 128);
        gemmH(mlp, wfc2 + (long long)l * DFFd * Dd, w.fc2_b + l * Dd,
              x, x, M, Dd, DFFd, DFFd, Dd, 0, 0, 64);
    }
}

extern "C" void kernel_launch(void* const* d_in, const int* in_sizes, int n_in,
                              void* d_out, int out_size) {
    (void)in_sizes; (void)n_in; (void)out_size;
    const float* inputs   = (const float*)d_in[0];
    const float* patch_w  = (const float*)d_in[1];
    const float* patch_b  = (const float*)d_in[2];
    const float* cls_tok  = (const float*)d_in[3];
    const float* pos_emb  = (const float*)d_in[4];
    const float* ln1_g    = (const float*)d_in[5];
    const float* ln1_b    = (const float*)d_in[6];
    const float* qkv_w    = (const float*)d_in[7];
    const float* qkv_b    = (const float*)d_in[8];
    const float* proj_w   = (const float*)d_in[9];
    const float* proj_b   = (const float*)d_in[10];
    const float* ln2_g    = (const float*)d_in[11];
    const float* ln2_b    = (const float*)d_in[12];
    const float* fc1_w    = (const float*)d_in[13];
    const float* fc1_b    = (const float*)d_in[14];
    const float* fc2_w    = (const float*)d_in[15];
    const float* fc2_b    = (const float*)d_in[16];
    const float* norm_g   = (const float*)d_in[17];
    const float* norm_b   = (const float*)d_in[18];
    const float* head_w   = (const float*)d_in[19];
    const float* head_b   = (const float*)d_in[20];
    const float* prompt   = (const float*)d_in[21];
    const float* mean     = (const float*)d_in[22];
    const float* variance = (const float*)d_in[23];
    float* out = (float*)d_out;

    __half* col  = (__half*)getsym(g_colh);
    float*  img  = (float*)getsym(g_img);
    float*  x0   = (float*)getsym(g_x0);
    float*  x    = (float*)getsym(g_x);
    __half* h    = (__half*)getsym(g_hh);
    __half* qkv  = (__half*)getsym(g_qkvh);
    __half* o    = (__half*)getsym(g_oh);
    __half* mlp  = (__half*)getsym(g_mlph);
    float*  qv   = (float*)getsym(g_q);
    float*  L    = (float*)getsym(g_L);
    float*  LT   = (float*)getsym(g_LT);
    float*  logd = (float*)getsym(g_logdet);
    float*  logp = (float*)getsym(g_logp);
    int*    topk = (int*)getsym(g_topk);
    float*  pool = (float*)getsym(g_pool);
    __half* wc   = (__half*)getsym(g_wch);

    cudaFuncSetAttribute(gemmH_k<0, 128>, cudaFuncAttributeMaxDynamicSharedMemorySize,
                         (int)(2 * GH_STG(128)));
    cudaFuncSetAttribute(gemmH_k<1, 128>, cudaFuncAttributeMaxDynamicSharedMemorySize,
                         (int)(2 * GH_STG(128)));
    cudaFuncSetAttribute(gemmH_k<0, 64>, cudaFuncAttributeMaxDynamicSharedMemorySize,
                         (int)(2 * GH_STG(64)));
    cudaFuncSetAttribute(gemmH_k<1, 64>, cudaFuncAttributeMaxDynamicSharedMemorySize,
                         (int)(2 * GH_STG(64)));
    cudaFuncSetAttribute(fa_k, cudaFuncAttributeMaxDynamicSharedMemorySize, FA_SMEM);

    // ---- weight pre-conversion: transpose [K][N] -> half [N][K] ----
    {
        dim3 blk(32, 8);
        tcvtH_k<<<dim3(2304 / 32, 768 / 32, 12), blk>>>(qkv_w, wc + WC_QKV, 768, 2304);
        tcvtH_k<<<dim3(768 / 32, 768 / 32, 12), blk>>>(proj_w, wc + WC_PROJ, 768, 768);
        tcvtH_k<<<dim3(3072 / 32, 768 / 32, 12), blk>>>(fc1_w, wc + WC_FC1, 768, 3072);
        tcvtH_k<<<dim3(768 / 32, 3072 / 32, 12), blk>>>(fc2_w, wc + WC_FC2, 3072, 768);
        long long n = 768LL * 768;   // patch_w already [N][K]
        cvtH_k<<<(unsigned)((n + 255) / 256), 256>>>(patch_w, wc + WC_PATCH, n);
    }

    Weights w;
    w.qkv_b = qkv_b; w.proj_b = proj_b; w.fc1_b = fc1_b; w.fc2_b = fc2_b;
    w.ln1_g = ln1_g; w.ln1_b = ln1_b; w.ln2_g = ln2_g; w.ln2_b = ln2_b;
    w.wc = wc;

    // ---- patch embed ----
    {
        long long tot = (long long)Bv * NP * Dd;
        im2col_k<<<(unsigned)((tot + 255) / 256), 256>>>(inputs, col);
        gemmH(col, wc + WC_PATCH, patch_b, nullptr, img,
              Bv * NP, Dd, Dd, Dd, Dd, 0, 0, 64);
        long long tot0 = (long long)Bv * N1 * Dd;
        build_x0_k<<<(unsigned)((tot0 + 255) / 256), 256>>>(img, cls_tok, pos_emb, x0, x);
    }

    // ---- Cholesky of cov = |variance| + I  (blocked NB=64) ----
    {
        long long tot = (long long)Pn * Dd * Dd;
        chol_prep_k<<<(unsigned)((tot + 255) / 256), 256>>>(variance, L, logd);
        for (int kb = 0; kb < Dd / 64; kb++) {
            potrf_k<<<Pn, 256>>>(L, logd, kb);
            int T = Dd - (kb + 1) * 64;
            if (T > 0) {
                trsm_k<<<dim3(Pn, (T + 7) / 8), 256>>>(L, kb);
                long long off = (long long)(kb + 1) * 64;
                const float* pan = L + off * Dd + kb * 64;
                float* trail = L + off * Dd + off;
                gemmT(true, pan, pan, nullptr, trail, trail,
                      T, T, 64, Dd, Dd, Dd, Pn, 1,
                      (long long)Dd * Dd, 0, (long long)Dd * Dd, 0,
                      (long long)Dd * Dd, 0, -1.f, 0, 1);
            }
        }
        transpose_k<<<dim3(Dd / 32, Dd / 32, Pn), dim3(32, 8)>>>(L, LT);
    }

    // ---- pass 1 (query) ----
    run_blocks(x, N1, w, h, qkv, o, mlp);
    ln_k<<<Bv * N1, 256>>>(x, norm_g, norm_b, h, Bv * N1);
    extract_q_k<<<(Bv * Dd + 255) / 256, 256>>>(h, qv);

    // ---- MVN logprob + top-k ----
    solve_k<<<dim3(Pn, Bv / 8), 256>>>(LT, qv, mean, logd, logp);
    topk_k<<<1, 16>>>(logp, topk);

    // ---- pass 2 (prompted) ----
    {
        long long tot = (long long)Bv * N2 * Dd;
        build_x2_k<<<(unsigned)((tot + 255) / 256), 256>>>(x0, prompt, pos_emb, img, topk, x);
    }
    run_blocks(x, N2, w, h, qkv, o, mlp);
    ln_k<<<Bv * N2, 256>>>(x, norm_g, norm_b, h, Bv * N2);
    pool_k<<<(Bv * Dd + 255) / 256, 256>>>(h, pool);

    // ---- head ----
    gemmT(false, pool, head_w, head_b, nullptr, out,
          Bv, NCn, Dd, Dd, NCn, NCn, 1, 1, 0, 0, 0, 0, 0, 0, 1.f, 0, 0);
}